// round 11
// baseline (speedup 1.0000x reference)
#include <cuda_runtime.h>
#include <cuda_fp16.h>
#include <math.h>
#include <stdint.h>

#define TOKS 131072          // 2048 windows * 64 tokens

// fp16 scratch
__device__ __half g_hR[(size_t)TOKS * 384];      // WIN, later H (residual, fp16)
__device__ __half g_hA[(size_t)TOKS * 384];      // Y (post-LN1), later O (attn out)
__device__ __half g_hB[(size_t)TOKS * 1152];     // QKV, later Y2 (384) + G (768)
__device__ __half g_wh[1179648];                 // weights converted to half

#define WQKV_OFF 0
#define WO_OFF   442368
#define W1_OFF   589824
#define W2_OFF   884736

#define GEMM_SMEM   65536     // 128x128 kernel (MODE 3)
#define GEMM_SMEM2  98304     // 256x128 kernel (MODEs 0-2): 4 x 24KB

// ===========================================================================
// helpers
// ===========================================================================
__device__ __forceinline__ void cp16(uint32_t dst, const void* src) {
    asm volatile("cp.async.cg.shared.global [%0], [%1], 16;"
        :: "r"(dst), "l"(src));
}
__device__ __forceinline__ void mma16(float* d, uint32_t a0, uint32_t a1,
                                      uint32_t a2, uint32_t a3,
                                      uint32_t b0, uint32_t b1) {
    asm volatile(
        "mma.sync.aligned.m16n8k16.row.col.f32.f16.f16.f32 "
        "{%0,%1,%2,%3}, {%4,%5,%6,%7}, {%8,%9}, {%0,%1,%2,%3};"
        : "+f"(d[0]), "+f"(d[1]), "+f"(d[2]), "+f"(d[3])
        : "r"(a0), "r"(a1), "r"(a2), "r"(a3), "r"(b0), "r"(b1));
}
__device__ __forceinline__ void ldsm4(uint32_t* r, uint32_t addr) {
    asm volatile("ldmatrix.sync.aligned.m8n8.x4.shared.b16 {%0,%1,%2,%3}, [%4];"
        : "=r"(r[0]), "=r"(r[1]), "=r"(r[2]), "=r"(r[3]) : "r"(addr));
}
__device__ __forceinline__ void ldsm4t(uint32_t* r, uint32_t addr) {
    asm volatile("ldmatrix.sync.aligned.m8n8.x4.trans.shared.b16 {%0,%1,%2,%3}, [%4];"
        : "=r"(r[0]), "=r"(r[1]), "=r"(r[2]), "=r"(r[3]) : "r"(addr));
}
__device__ __forceinline__ uint32_t pack2(float a, float b) {
    __half2 h = __floats2half2_rn(a, b);
    return *(uint32_t*)&h;
}
__device__ __forceinline__ float2 unpack2(uint32_t u) {
    return __half22float2(*(__half2*)&u);
}

// ===========================================================================
// Kernel 0: all weights fp32 -> fp16 in one launch
// ===========================================================================
__global__ void __launch_bounds__(256) cvt_all_kernel(
    const float* __restrict__ a, const float* __restrict__ b,
    const float* __restrict__ c, const float* __restrict__ d,
    __half* __restrict__ o)
{
    int i = blockIdx.x * 256 + threadIdx.x;
    if (i < 442368)       o[i] = __float2half(a[i]);
    else if (i < 589824)  o[i] = __float2half(b[i - 442368]);
    else if (i < 884736)  o[i] = __float2half(c[i - 589824]);
    else if (i < 1179648) o[i] = __float2half(d[i - 884736]);
}

// ===========================================================================
// Kernel 1: window gather + LayerNorm1. WIN fp16, Y fp16.
// ===========================================================================
__global__ void __launch_bounds__(256) ln1_gather_kernel(
    const float* __restrict__ x,
    const float* __restrict__ gw, const float* __restrict__ gb,
    __half* __restrict__ Y, __half* __restrict__ WIN)
{
    __shared__ float tile[384][17];
    __shared__ float s_mu[16], s_rs[16];

    int blk  = blockIdx.x;
    int win  = blk >> 2;
    int part = blk & 3;
    int b  = win >> 8;
    int wh = (win >> 4) & 15;
    int ww = win & 15;

    int tid = threadIdx.x;
    int sl  = tid & 15;
    int s   = part * 16 + sl;
    int r   = s >> 3, cw = s & 7;
    long xbase = (long)b * 384 * 16384 + (long)(wh * 8 + r) * 128 + ww * 8 + cw;

    for (int c = tid >> 4; c < 384; c += 16)
        tile[c][sl] = x[xbase + (long)c * 16384];
    __syncthreads();

    int lane = tid & 31, wd = tid >> 5;
    for (int t = wd * 2; t < wd * 2 + 2; t++) {
        float sum = 0.f, sq = 0.f;
        for (int c = lane; c < 384; c += 32) {
            float v = tile[c][t];
            sum += v; sq += v * v;
        }
        #pragma unroll
        for (int o = 16; o; o >>= 1) {
            sum += __shfl_xor_sync(~0u, sum, o);
            sq  += __shfl_xor_sync(~0u, sq,  o);
        }
        if (lane == 0) {
            float m = sum * (1.f / 384.f);
            float var = sq * (1.f / 384.f) - m * m;
            s_mu[t] = m;
            s_rs[t] = rsqrtf(var + 1e-5f);
        }
    }
    __syncthreads();

    long tok0 = (long)win * 64 + part * 16;
    for (int idx = tid; idx < 16 * 384; idx += 256) {
        int c = idx % 384, t = idx / 384;
        float v = tile[c][t];
        long o = (tok0 + t) * 384 + c;
        WIN[o] = __float2half(v);
        Y[o] = __float2half((v - s_mu[t]) * s_rs[t] * gw[c] + gb[c]);
    }
}

// ===========================================================================
// FP16 tensor-core GEMM, BM=256, BN=128, BK=32 (modes 0-2). 256 threads,
// 8 warps in 4(M)x2(N) layout, warp tile 64x64 (32 HMMA : 8 LDSM per k16).
// 4-stage cp.async (24KB/stage), ldmatrix + swizzle, full unroll.
//  MODE 0: + bias, fp16 out             (QKV)
//  MODE 1: + bias, exact gelu, fp16 out (MLP1 -> G)
//  MODE 2: + bias + res(fp16), fp16 out (attn out proj -> H)
// ===========================================================================
template<int MODE, int K>
__global__ void __launch_bounds__(256, 1) mma_gemm256(
    const __half* __restrict__ A, const __half* __restrict__ W,
    const float* __restrict__ bias, const __half* __restrict__ res,
    void* __restrict__ outp, int N)
{
    extern __shared__ uint32_t sm[];

    const int tid  = threadIdx.x;
    const int lane = tid & 31, wid = tid >> 5;
    const int wm = wid >> 1;      // M quadrant (64 rows)
    const int wn = wid & 1;       // N half (64 cols)
    const int gr = lane >> 2;
    const int cg = lane & 3;

    const long m0 = (long)blockIdx.y * 256;
    const int  n0 = blockIdx.x * 128;

    const uint32_t sb = (uint32_t)__cvta_generic_to_shared(sm);
    const __half* Ag = A + m0 * K;
    const __half* Wg = W + (long)n0 * K;

    float acc[4][8][4];
    #pragma unroll
    for (int i = 0; i < 4; i++)
        #pragma unroll
        for (int j = 0; j < 8; j++)
            #pragma unroll
            for (int k = 0; k < 4; k++) acc[i][j][k] = 0.f;

    constexpr int NS = K >> 5;

    // stage load: A 256 rows (4/thr), B 128 rows (2/thr), 16B chunks, swizzled
    auto issue = [&](int s, int p) {
        #pragma unroll
        for (int i = 0; i < 4; i++) {
            int idx = tid + i * 256;
            int row = idx >> 2, c = idx & 3;
            int line = row >> 1;
            uint32_t u = (uint32_t)((((row & 1) << 2) + c) ^ (line & 7));
            cp16(sb + p * 24576u + line * 128u + u * 16u,
                 Ag + (long)row * K + s * 32 + c * 8);
        }
        #pragma unroll
        for (int i = 0; i < 2; i++) {
            int idx = tid + i * 256;
            int row = idx >> 2, c = idx & 3;
            int line = row >> 1;
            uint32_t u = (uint32_t)((((row & 1) << 2) + c) ^ (line & 7));
            cp16(sb + p * 24576u + 16384u + line * 128u + u * 16u,
                 Wg + (long)row * K + s * 32 + c * 8);
        }
        asm volatile("cp.async.commit_group;");
    };

    const int lrow = (lane & 7) + ((lane >> 3) & 1) * 8;
    const int lk   = lane >> 4;

    issue(0, 0);
    issue(1, 1);
    issue(2, 2);
    #pragma unroll
    for (int s = 0; s < NS; s++) {
        const int p = s & 3;
        if (s + 2 < NS)      asm volatile("cp.async.wait_group 2;");
        else if (s + 1 < NS) asm volatile("cp.async.wait_group 1;");
        else                 asm volatile("cp.async.wait_group 0;");
        __syncthreads();
        if (s + 3 < NS) issue(s + 3, (s + 3) & 3);

        const uint32_t abase = sb + p * 24576u;
        const uint32_t bbase = abase + 16384u;

        #pragma unroll
        for (int kc = 0; kc < 2; kc++) {
            int c = kc * 2 + lk;
            uint32_t af[4][4], bq[4][4];
            #pragma unroll
            for (int mt = 0; mt < 4; mt++) {
                int row = wm * 64 + mt * 16 + lrow;
                int line = row >> 1;
                uint32_t u = (uint32_t)((((row & 1) << 2) + c) ^ (line & 7));
                ldsm4(af[mt], abase + line * 128u + u * 16u);
            }
            #pragma unroll
            for (int pr = 0; pr < 4; pr++) {
                int row = wn * 64 + pr * 16 + lrow;
                int line = row >> 1;
                uint32_t u = (uint32_t)((((row & 1) << 2) + c) ^ (line & 7));
                ldsm4(bq[pr], bbase + line * 128u + u * 16u);
            }
            #pragma unroll
            for (int mt = 0; mt < 4; mt++)
                #pragma unroll
                for (int nt = 0; nt < 8; nt++) {
                    int pr = nt >> 1, hi = nt & 1;
                    mma16(acc[mt][nt], af[mt][0], af[mt][1], af[mt][2], af[mt][3],
                          bq[pr][hi], bq[pr][hi + 2]);
                }
        }
    }

    #pragma unroll
    for (int mt = 0; mt < 4; mt++) {
        #pragma unroll
        for (int nt = 0; nt < 8; nt++) {
            int n = n0 + wn * 64 + nt * 8 + cg * 2;
            float2 b2 = *(const float2*)(bias + n);
            #pragma unroll
            for (int h = 0; h < 2; h++) {
                long r = m0 + wm * 64 + mt * 16 + h * 8 + gr;
                float v0 = acc[mt][nt][h * 2 + 0] + b2.x;
                float v1 = acc[mt][nt][h * 2 + 1] + b2.y;
                if (MODE == 1) {
                    v0 = 0.5f * v0 * (1.f + erff(v0 * 0.70710678118654752f));
                    v1 = 0.5f * v1 * (1.f + erff(v1 * 0.70710678118654752f));
                }
                if (MODE == 2) {
                    float2 rr = unpack2(*(const uint32_t*)(res + r * N + n));
                    v0 += rr.x; v1 += rr.y;
                }
                *(uint32_t*)((__half*)outp + r * N + n) = pack2(v0, v1);
            }
        }
    }
}

// ===========================================================================
// FP16 tensor-core GEMM, BM=128, BN=128 (MODE 3 only): + bias + res(fp16),
// fp32 window-reverse scatter to NCHW out. Same as R10.
// ===========================================================================
template<int K>
__global__ void __launch_bounds__(256, 2) mma_gemm_sc(
    const __half* __restrict__ A, const __half* __restrict__ W,
    const float* __restrict__ bias, const __half* __restrict__ res,
    float* __restrict__ out, int N)
{
    extern __shared__ uint32_t sm[];

    const int tid  = threadIdx.x;
    const int lane = tid & 31, wid = tid >> 5;
    const int wm = wid & 1;
    const int wn = wid >> 1;
    const int gr = lane >> 2;
    const int cg = lane & 3;

    const long m0 = (long)blockIdx.y * 128;
    const int  n0 = blockIdx.x * 128;

    const uint32_t sb = (uint32_t)__cvta_generic_to_shared(sm);
    const __half* Ag = A + m0 * K;
    const __half* Wg = W + (long)n0 * K;

    float acc[4][4][4];
    #pragma unroll
    for (int i = 0; i < 4; i++)
        #pragma unroll
        for (int j = 0; j < 4; j++)
            #pragma unroll
            for (int k = 0; k < 4; k++) acc[i][j][k] = 0.f;

    constexpr int NS = K >> 5;

    auto issue = [&](int s, int p) {
        #pragma unroll
        for (int i = 0; i < 2; i++) {
            int idx = tid + i * 256;
            int row = idx >> 2, c = idx & 3;
            int line = row >> 1;
            uint32_t u = (uint32_t)((((row & 1) << 2) + c) ^ (line & 7));
            uint32_t off = p * 16384u + line * 128u + u * 16u;
            cp16(sb + off,          Ag + (long)row * K + s * 32 + c * 8);
            cp16(sb + 8192u + off,  Wg + (long)row * K + s * 32 + c * 8);
        }
        asm volatile("cp.async.commit_group;");
    };

    const int lrow = (lane & 7) + ((lane >> 3) & 1) * 8;
    const int lk   = lane >> 4;

    issue(0, 0);
    issue(1, 1);
    issue(2, 2);
    #pragma unroll
    for (int s = 0; s < NS; s++) {
        const int p = s & 3;
        if (s + 2 < NS)      asm volatile("cp.async.wait_group 2;");
        else if (s + 1 < NS) asm volatile("cp.async.wait_group 1;");
        else                 asm volatile("cp.async.wait_group 0;");
        __syncthreads();
        if (s + 3 < NS) issue(s + 3, (s + 3) & 3);

        const uint32_t abase = sb + p * 16384u;
        const uint32_t bbase = abase + 8192u;

        #pragma unroll
        for (int kc = 0; kc < 2; kc++) {
            int c = kc * 2 + lk;
            uint32_t af[4][4], bq[2][4];
            #pragma unroll
            for (int mt = 0; mt < 4; mt++) {
                int row = wm * 64 + mt * 16 + lrow;
                int line = row >> 1;
                uint32_t u = (uint32_t)((((row & 1) << 2) + c) ^ (line & 7));
                ldsm4(af[mt], abase + line * 128u + u * 16u);
            }
            #pragma unroll
            for (int pr = 0; pr < 2; pr++) {
                int row = wn * 32 + pr * 16 + lrow;
                int line = row >> 1;
                uint32_t u = (uint32_t)((((row & 1) << 2) + c) ^ (line & 7));
                ldsm4(bq[pr], bbase + line * 128u + u * 16u);
            }
            #pragma unroll
            for (int mt = 0; mt < 4; mt++)
                #pragma unroll
                for (int nt = 0; nt < 4; nt++) {
                    int pr = nt >> 1, hi = nt & 1;
                    mma16(acc[mt][nt], af[mt][0], af[mt][1], af[mt][2], af[mt][3],
                          bq[pr][hi], bq[pr][hi + 2]);
                }
        }
    }

    __syncthreads();
    float* T = (float*)sm;    // [128][66] floats
    #pragma unroll
    for (int chunk = 0; chunk < 2; chunk++) {
        if ((wn >> 1) == chunk) {
            #pragma unroll
            for (int mt = 0; mt < 4; mt++) {
                #pragma unroll
                for (int nt = 0; nt < 4; nt++) {
                    int cl = (wn & 1) * 32 + nt * 8 + cg * 2;
                    int n  = n0 + chunk * 64 + cl;
                    float2 b2 = *(const float2*)(bias + n);
                    #pragma unroll
                    for (int h = 0; h < 2; h++) {
                        int rl = wm * 64 + mt * 16 + h * 8 + gr;
                        long r = m0 + rl;
                        float2 rr = unpack2(*(const uint32_t*)(res + r * 384 + n));
                        T[rl * 66 + cl]     = acc[mt][nt][h * 2 + 0] + b2.x + rr.x;
                        T[rl * 66 + cl + 1] = acc[mt][nt][h * 2 + 1] + b2.y + rr.y;
                    }
                }
            }
        }
        __syncthreads();
        int ch = tid & 63;
        for (int g = tid >> 6; g < 16; g += 4) {
            long m = m0 + g * 8;
            int winI = (int)(m >> 6), sI = (int)(m & 63);
            int bI = winI >> 8, whI = (winI >> 4) & 15, wwI = winI & 15;
            int n = n0 + chunk * 64 + ch;
            long base = ((long)(bI * 384 + n)) * 16384
                      + (long)(whI * 8 + (sI >> 3)) * 128 + wwI * 8;
            float v[8];
            #pragma unroll
            for (int i = 0; i < 8; i++) v[i] = T[(g * 8 + i) * 66 + ch];
            *(float4*)(out + base)     = make_float4(v[0], v[1], v[2], v[3]);
            *(float4*)(out + base + 4) = make_float4(v[4], v[5], v[6], v[7]);
        }
        __syncthreads();
    }
}

// ===========================================================================
// Kernel 3: tensor-core attention. One block = 2 heads of one window.
// (unchanged from R10: 4 CTAs/SM, one m16 tile per warp)
// ===========================================================================
__global__ void __launch_bounds__(256, 4) attn_kernel(
    const __half* __restrict__ QKV, __half* __restrict__ O)
{
    __shared__ __half qkv[64 * 296];
    const int STRB = 592;

    const int hp  = blockIdx.x;
    const int h0  = hp * 2;
    const long tok0 = (long)blockIdx.y * 64;
    const int tid = threadIdx.x;
    const int lane = tid & 31, wid = tid >> 5;

    const __half* g = QKV + tok0 * 1152 + h0 * 48;
    #pragma unroll
    for (int i = 0; i < 9; i++) {
        int ch = tid + i * 256;
        int row = ch / 36, seg = ch % 36;
        int part = seg / 12, sub = seg % 12;
        *(uint4*)&qkv[row * 296 + seg * 8] =
            *(const uint4*)(g + (long)row * 1152 + part * 384 + sub * 8);
    }
    __syncthreads();

    const uint32_t sb = (uint32_t)__cvta_generic_to_shared(qkv);
    const int hl = wid >> 2;
    const int m0 = (wid & 3) * 16;
    const int gr = lane >> 2, cg = lane & 3;

    const int qoffB = hl * 96;
    const int koffB = 192 + hl * 96;
    const int voffB = 384 + hl * 96;

    const int lrow = (lane & 7) + ((lane >> 3) & 1) * 8;
    const int lkA  = lane >> 4;
    const int krow = (lane & 7) + ((lane >> 4) & 1) * 8;
    const int kcolb= ((lane >> 3) & 1) * 16;
    const int vrow = (lane & 7) + ((lane >> 3) & 1) * 8;
    const int vsel = lane >> 4;

    float sacc[8][4];
    #pragma unroll
    for (int nt = 0; nt < 8; nt++)
        #pragma unroll
        for (int j = 0; j < 4; j++) sacc[nt][j] = 0.f;

    #pragma unroll
    for (int kc = 0; kc < 3; kc++) {
        uint32_t a[4];
        ldsm4(a, sb + (uint32_t)((m0 + lrow) * STRB + qoffB + kc * 32 + lkA * 16));
        #pragma unroll
        for (int j = 0; j < 4; j++) {
            uint32_t b[4];
            ldsm4(b, sb + (uint32_t)((j * 16 + krow) * STRB + koffB + kc * 32 + kcolb));
            mma16(sacc[2 * j],     a[0], a[1], a[2], a[3], b[0], b[1]);
            mma16(sacc[2 * j + 1], a[0], a[1], a[2], a[3], b[2], b[3]);
        }
    }

    const float scale = 0.14433756729740645f;
    float mx0 = -1e30f, mx1 = -1e30f;
    #pragma unroll
    for (int nt = 0; nt < 8; nt++) {
        mx0 = fmaxf(mx0, fmaxf(sacc[nt][0], sacc[nt][1]));
        mx1 = fmaxf(mx1, fmaxf(sacc[nt][2], sacc[nt][3]));
    }
    mx0 = fmaxf(mx0, __shfl_xor_sync(~0u, mx0, 1));
    mx0 = fmaxf(mx0, __shfl_xor_sync(~0u, mx0, 2));
    mx1 = fmaxf(mx1, __shfl_xor_sync(~0u, mx1, 1));
    mx1 = fmaxf(mx1, __shfl_xor_sync(~0u, mx1, 2));
    mx0 *= scale; mx1 *= scale;

    float e[8][4];
    float sum0 = 0.f, sum1 = 0.f;
    #pragma unroll
    for (int nt = 0; nt < 8; nt++) {
        e[nt][0] = __expf(sacc[nt][0] * scale - mx0);
        e[nt][1] = __expf(sacc[nt][1] * scale - mx0);
        e[nt][2] = __expf(sacc[nt][2] * scale - mx1);
        e[nt][3] = __expf(sacc[nt][3] * scale - mx1);
        sum0 += e[nt][0] + e[nt][1];
        sum1 += e[nt][2] + e[nt][3];
    }
    sum0 += __shfl_xor_sync(~0u, sum0, 1);
    sum0 += __shfl_xor_sync(~0u, sum0, 2);
    sum1 += __shfl_xor_sync(~0u, sum1, 1);
    sum1 += __shfl_xor_sync(~0u, sum1, 2);
    float inv0 = 1.f / sum0, inv1 = 1.f / sum1;

    uint32_t p0[8], p1[8];
    #pragma unroll
    for (int nt = 0; nt < 8; nt++) {
        p0[nt] = pack2(e[nt][0] * inv0, e[nt][1] * inv0);
        p1[nt] = pack2(e[nt][2] * inv1, e[nt][3] * inv1);
    }

    float oacc[6][4];
    #pragma unroll
    for (int nt = 0; nt < 6; nt++)
        #pragma unroll
        for (int j = 0; j < 4; j++) oacc[nt][j] = 0.f;

    #pragma unroll
    for (int kc = 0; kc < 4; kc++) {
        uint32_t a0 = p0[2 * kc],     a1 = p1[2 * kc];
        uint32_t a2 = p0[2 * kc + 1], a3 = p1[2 * kc + 1];
        #pragma unroll
        for (int j = 0; j < 3; j++) {
            uint32_t b[4];
            ldsm4t(b, sb + (uint32_t)((kc * 16 + vrow) * STRB
                                      + voffB + (2 * j + vsel) * 16));
            mma16(oacc[2 * j],     a0, a1, a2, a3, b[0], b[1]);
            mma16(oacc[2 * j + 1], a0, a1, a2, a3, b[2], b[3]);
        }
    }

    #pragma unroll
    for (int nt = 0; nt < 6; nt++) {
        long col = (h0 + hl) * 48 + nt * 8 + cg * 2;
        long r0 = tok0 + m0 + gr;
        *(uint32_t*)(O + r0 * 384 + col)       = pack2(oacc[nt][0], oacc[nt][1]);
        *(uint32_t*)(O + (r0 + 8) * 384 + col) = pack2(oacc[nt][2], oacc[nt][3]);
    }
}

// ===========================================================================
// Kernel 5: LayerNorm2, vectorized. 4 tokens per 384-thread block.
// ===========================================================================
__global__ void __launch_bounds__(384) ln2_kernel(
    const __half* __restrict__ Hh,
    const float* __restrict__ gw, const float* __restrict__ gb,
    __half* __restrict__ Y2)
{
    __shared__ float ssum[12], ssq[12];

    int tid = threadIdx.x;
    int tk = tid / 96;
    int tl = tid % 96;
    long t = (long)blockIdx.x * 4 + tk;

    uint2 u = *(const uint2*)(Hh + t * 384 + tl * 4);
    float2 v01 = unpack2(u.x), v23 = unpack2(u.y);
    float sum = v01.x + v01.y + v23.x + v23.y;
    float sq  = v01.x * v01.x + v01.y * v01.y + v23.x * v23.x + v23.y * v23.y;

    #pragma unroll
    for (int o = 16; o; o >>= 1) {
        sum += __shfl_xor_sync(~0u, sum, o);
        sq  += __shfl_xor_sync(~0u, sq,  o);
    }
    int wrp = tid >> 5;
    if ((tid & 31) == 0) { ssum[wrp] = sum; ssq[wrp] = sq; }
    __syncthreads();
    sum = ssum[tk * 3] + ssum[tk * 3 + 1] + ssum[tk * 3 + 2];
    sq  = ssq[tk * 3]  + ssq[tk * 3 + 1]  + ssq[tk * 3 + 2];

    float m  = sum * (1.f / 384.f);
    float rs = rsqrtf(sq * (1.f / 384.f) - m * m + 1e-5f);

    int c = tl * 4;
    float4 w4 = *(const float4*)(gw + c);
    float4 b4 = *(const float4*)(gb + c);
    uint2 o;
    o.x = pack2((v01.x - m) * rs * w4.x + b4.x, (v01.y - m) * rs * w4.y + b4.y);
    o.y = pack2((v23.x - m) * rs * w4.z + b4.z, (v23.y - m) * rs * w4.w + b4.w);
    *(uint2*)(Y2 + t * 384 + c) = o;
}

// ===========================================================================
extern "C" void kernel_launch(void* const* d_in, const int* in_sizes, int n_in,
                              void* d_out, int out_size)
{
    const float* x     = (const float*)d_in[0];
    const float* n1_w  = (const float*)d_in[1];
    const float* n1_b  = (const float*)d_in[2];
    const float* in_w  = (const float*)d_in[3];
    const float* in_b  = (const float*)d_in[4];
    const float* out_w = (const float*)d_in[5];
    const float* out_b = (const float*)d_in[6];
    const float* n2_w  = (const float*)d_in[7];
    const float* n2_b  = (const float*)d_in[8];
    const float* w1    = (const float*)d_in[9];
    const float* b1    = (const float*)d_in[10];
    const float* w2    = (const float*)d_in[11];
    const float* b2    = (const float*)d_in[12];
    float* out = (float*)d_out;

    __half *WINh, *Yh, *Hb, *Wh;
    cudaGetSymbolAddress((void**)&WINh, g_hR);
    cudaGetSymbolAddress((void**)&Yh,   g_hA);
    cudaGetSymbolAddress((void**)&Hb,   g_hB);
    cudaGetSymbolAddress((void**)&Wh,   g_wh);

    __half* QKVh = Hb;
    __half* Oh   = Yh;
    __half* H    = WINh;
    __half* Y2h  = Hb;
    __half* Gh   = Hb + (size_t)TOKS * 384;

    cudaFuncSetAttribute((const void*)mma_gemm256<0,384>, cudaFuncAttributeMaxDynamicSharedMemorySize, GEMM_SMEM2);
    cudaFuncSetAttribute((const void*)mma_gemm256<1,384>, cudaFuncAttributeMaxDynamicSharedMemorySize, GEMM_SMEM2);
    cudaFuncSetAttribute((const void*)mma_gemm256<2,384>, cudaFuncAttributeMaxDynamicSharedMemorySize, GEMM_SMEM2);
    cudaFuncSetAttribute((const void*)mma_gemm_sc<768>,   cudaFuncAttributeMaxDynamicSharedMemorySize, GEMM_SMEM);

    // 0. convert all weights to fp16
    cvt_all_kernel<<<4608, 256>>>(in_w, out_w, w1, w2, Wh);
    // 1. gather + LN1
    ln1_gather_kernel<<<2048 * 4, 256>>>(x, n1_w, n1_b, Yh, WINh);
    // 2. QKV projection (256x128 tiles)
    mma_gemm256<0,384><<<dim3(1152 / 128, TOKS / 256), 256, GEMM_SMEM2>>>(Yh, Wh + WQKV_OFF, in_b, nullptr, QKVh, 1152);
    // 3. tensor-core attention
    attn_kernel<<<dim3(4, 2048), 256>>>(QKVh, Oh);
    // 4. out projection + residual -> H
    mma_gemm256<2,384><<<dim3(384 / 128, TOKS / 256), 256, GEMM_SMEM2>>>(Oh, Wh + WO_OFF, out_b, WINh, H, 384);
    // 5. LN2
    ln2_kernel<<<TOKS / 4, 384>>>(H, n2_w, n2_b, Y2h);
    // 6. MLP fc1 + gelu
    mma_gemm256<1,384><<<dim3(768 / 128, TOKS / 256), 256, GEMM_SMEM2>>>(Y2h, Wh + W1_OFF, b1, nullptr, Gh, 768);
    // 7. MLP fc2 + residual + window-reverse scatter (128x128 kernel)
    mma_gemm_sc<768><<<dim3(384 / 128, TOKS / 128), 256, GEMM_SMEM>>>(Gh, Wh + W2_OFF, b2, H, out, 384);
}

// round 12
// speedup vs baseline: 1.0853x; 1.0853x over previous
#include <cuda_runtime.h>
#include <cuda_fp16.h>
#include <math.h>
#include <stdint.h>

#define TOKS 131072          // 2048 windows * 64 tokens

// fp16 scratch
__device__ __half g_hR[(size_t)TOKS * 384];      // WIN, later H (residual, fp16)
__device__ __half g_hA[(size_t)TOKS * 384];      // Y (post-LN1), later O (attn out)
__device__ __half g_hB[(size_t)TOKS * 1152];     // QKV, later Y2 (384) + G (768)
__device__ __half g_wh[1179648];                 // weights converted to half

#define WQKV_OFF 0
#define WO_OFF   442368
#define W1_OFF   589824
#define W2_OFF   884736

#define GEMM_SMEM 65536

// ===========================================================================
// helpers
// ===========================================================================
__device__ __forceinline__ void cp16(uint32_t dst, const void* src) {
    asm volatile("cp.async.cg.shared.global [%0], [%1], 16;"
        :: "r"(dst), "l"(src));
}
__device__ __forceinline__ void mma16(float* d, uint32_t a0, uint32_t a1,
                                      uint32_t a2, uint32_t a3,
                                      uint32_t b0, uint32_t b1) {
    asm volatile(
        "mma.sync.aligned.m16n8k16.row.col.f32.f16.f16.f32 "
        "{%0,%1,%2,%3}, {%4,%5,%6,%7}, {%8,%9}, {%0,%1,%2,%3};"
        : "+f"(d[0]), "+f"(d[1]), "+f"(d[2]), "+f"(d[3])
        : "r"(a0), "r"(a1), "r"(a2), "r"(a3), "r"(b0), "r"(b1));
}
__device__ __forceinline__ void ldsm4(uint32_t* r, uint32_t addr) {
    asm volatile("ldmatrix.sync.aligned.m8n8.x4.shared.b16 {%0,%1,%2,%3}, [%4];"
        : "=r"(r[0]), "=r"(r[1]), "=r"(r[2]), "=r"(r[3]) : "r"(addr));
}
__device__ __forceinline__ void ldsm4t(uint32_t* r, uint32_t addr) {
    asm volatile("ldmatrix.sync.aligned.m8n8.x4.trans.shared.b16 {%0,%1,%2,%3}, [%4];"
        : "=r"(r[0]), "=r"(r[1]), "=r"(r[2]), "=r"(r[3]) : "r"(addr));
}
__device__ __forceinline__ uint32_t pack2(float a, float b) {
    __half2 h = __floats2half2_rn(a, b);
    return *(uint32_t*)&h;
}
__device__ __forceinline__ float2 unpack2(uint32_t u) {
    return __half22float2(*(__half2*)&u);
}

// ===========================================================================
// Kernel 0: all weights fp32 -> fp16 in one launch
// ===========================================================================
__global__ void __launch_bounds__(256) cvt_all_kernel(
    const float* __restrict__ a, const float* __restrict__ b,
    const float* __restrict__ c, const float* __restrict__ d,
    __half* __restrict__ o)
{
    int i = blockIdx.x * 256 + threadIdx.x;
    if (i < 442368)       o[i] = __float2half(a[i]);
    else if (i < 589824)  o[i] = __float2half(b[i - 442368]);
    else if (i < 884736)  o[i] = __float2half(c[i - 589824]);
    else if (i < 1179648) o[i] = __float2half(d[i - 884736]);
}

// ===========================================================================
// Kernel 1: window gather + LayerNorm1. WIN fp16, Y fp16.
// ===========================================================================
__global__ void __launch_bounds__(256) ln1_gather_kernel(
    const float* __restrict__ x,
    const float* __restrict__ gw, const float* __restrict__ gb,
    __half* __restrict__ Y, __half* __restrict__ WIN)
{
    __shared__ float tile[384][17];
    __shared__ float s_mu[16], s_rs[16];

    int blk  = blockIdx.x;
    int win  = blk >> 2;
    int part = blk & 3;
    int b  = win >> 8;
    int wh = (win >> 4) & 15;
    int ww = win & 15;

    int tid = threadIdx.x;
    int sl  = tid & 15;
    int s   = part * 16 + sl;
    int r   = s >> 3, cw = s & 7;
    long xbase = (long)b * 384 * 16384 + (long)(wh * 8 + r) * 128 + ww * 8 + cw;

    for (int c = tid >> 4; c < 384; c += 16)
        tile[c][sl] = x[xbase + (long)c * 16384];
    __syncthreads();

    int lane = tid & 31, wd = tid >> 5;
    for (int t = wd * 2; t < wd * 2 + 2; t++) {
        float sum = 0.f, sq = 0.f;
        for (int c = lane; c < 384; c += 32) {
            float v = tile[c][t];
            sum += v; sq += v * v;
        }
        #pragma unroll
        for (int o = 16; o; o >>= 1) {
            sum += __shfl_xor_sync(~0u, sum, o);
            sq  += __shfl_xor_sync(~0u, sq,  o);
        }
        if (lane == 0) {
            float m = sum * (1.f / 384.f);
            float var = sq * (1.f / 384.f) - m * m;
            s_mu[t] = m;
            s_rs[t] = rsqrtf(var + 1e-5f);
        }
    }
    __syncthreads();

    long tok0 = (long)win * 64 + part * 16;
    for (int idx = tid; idx < 16 * 384; idx += 256) {
        int c = idx % 384, t = idx / 384;
        float v = tile[c][t];
        long o = (tok0 + t) * 384 + c;
        WIN[o] = __float2half(v);
        Y[o] = __float2half((v - s_mu[t]) * s_rs[t] * gw[c] + gb[c]);
    }
}

// ===========================================================================
// FP16 tensor-core GEMM (R10 config restored): BM=128, BN=128, BK=32,
// 4-stage cp.async, 256 threads (8 warps, 2 CTAs/SM), ldmatrix + swizzle.
//  MODE 0: + bias, fp16 out             (QKV)
//  MODE 1: + bias, exact gelu, fp16 out (MLP1 -> G)
//  MODE 2: + bias + res(fp16), fp16 out (attn out proj -> H)
//  MODE 3: + bias + res(fp16), fp32 window-reverse scatter to NCHW (MLP2)
// ===========================================================================
template<int MODE, int K>
__global__ void __launch_bounds__(256, 2) mma_gemm(
    const __half* __restrict__ A, const __half* __restrict__ W,
    const float* __restrict__ bias, const __half* __restrict__ res,
    void* __restrict__ outp, int N)
{
    extern __shared__ uint32_t sm[];

    const int tid  = threadIdx.x;
    const int lane = tid & 31, wid = tid >> 5;
    const int wm = wid & 1;
    const int wn = wid >> 1;
    const int gr = lane >> 2;
    const int cg = lane & 3;

    const long m0 = (long)blockIdx.y * 128;
    const int  n0 = blockIdx.x * 128;

    const uint32_t sb = (uint32_t)__cvta_generic_to_shared(sm);
    const __half* Ag = A + m0 * K;
    const __half* Wg = W + (long)n0 * K;

    float acc[4][4][4];
    #pragma unroll
    for (int i = 0; i < 4; i++)
        #pragma unroll
        for (int j = 0; j < 4; j++)
            #pragma unroll
            for (int k = 0; k < 4; k++) acc[i][j][k] = 0.f;

    constexpr int NS = K >> 5;

    auto issue = [&](int s, int p) {
        #pragma unroll
        for (int i = 0; i < 2; i++) {
            int idx = tid + i * 256;
            int row = idx >> 2, c = idx & 3;
            int line = row >> 1;
            uint32_t u = (uint32_t)((((row & 1) << 2) + c) ^ (line & 7));
            uint32_t off = p * 16384u + line * 128u + u * 16u;
            cp16(sb + off,          Ag + (long)row * K + s * 32 + c * 8);
            cp16(sb + 8192u + off,  Wg + (long)row * K + s * 32 + c * 8);
        }
        asm volatile("cp.async.commit_group;");
    };

    const int lrow = (lane & 7) + ((lane >> 3) & 1) * 8;
    const int lk   = lane >> 4;

    issue(0, 0);
    issue(1, 1);
    issue(2, 2);
    #pragma unroll
    for (int s = 0; s < NS; s++) {
        const int p = s & 3;
        if (s + 2 < NS)      asm volatile("cp.async.wait_group 2;");
        else if (s + 1 < NS) asm volatile("cp.async.wait_group 1;");
        else                 asm volatile("cp.async.wait_group 0;");
        __syncthreads();
        if (s + 3 < NS) issue(s + 3, (s + 3) & 3);

        const uint32_t abase = sb + p * 16384u;
        const uint32_t bbase = abase + 8192u;

        #pragma unroll
        for (int kc = 0; kc < 2; kc++) {
            int c = kc * 2 + lk;
            uint32_t af[4][4], bq[2][4];
            #pragma unroll
            for (int mt = 0; mt < 4; mt++) {
                int row = wm * 64 + mt * 16 + lrow;
                int line = row >> 1;
                uint32_t u = (uint32_t)((((row & 1) << 2) + c) ^ (line & 7));
                ldsm4(af[mt], abase + line * 128u + u * 16u);
            }
            #pragma unroll
            for (int pr = 0; pr < 2; pr++) {
                int row = wn * 32 + pr * 16 + lrow;
                int line = row >> 1;
                uint32_t u = (uint32_t)((((row & 1) << 2) + c) ^ (line & 7));
                ldsm4(bq[pr], bbase + line * 128u + u * 16u);
            }
            #pragma unroll
            for (int mt = 0; mt < 4; mt++)
                #pragma unroll
                for (int nt = 0; nt < 4; nt++) {
                    int pr = nt >> 1, hi = nt & 1;
                    mma16(acc[mt][nt], af[mt][0], af[mt][1], af[mt][2], af[mt][3],
                          bq[pr][hi], bq[pr][hi + 2]);
                }
        }
    }

    if (MODE != 3) {
        #pragma unroll
        for (int mt = 0; mt < 4; mt++) {
            #pragma unroll
            for (int nt = 0; nt < 4; nt++) {
                int n = n0 + wn * 32 + nt * 8 + cg * 2;
                float2 b2 = *(const float2*)(bias + n);
                #pragma unroll
                for (int h = 0; h < 2; h++) {
                    long r = m0 + wm * 64 + mt * 16 + h * 8 + gr;
                    float v0 = acc[mt][nt][h * 2 + 0] + b2.x;
                    float v1 = acc[mt][nt][h * 2 + 1] + b2.y;
                    if (MODE == 1) {
                        v0 = 0.5f * v0 * (1.f + erff(v0 * 0.70710678118654752f));
                        v1 = 0.5f * v1 * (1.f + erff(v1 * 0.70710678118654752f));
                    }
                    if (MODE == 2) {
                        float2 rr = unpack2(*(const uint32_t*)(res + r * N + n));
                        v0 += rr.x; v1 += rr.y;
                    }
                    *(uint32_t*)((__half*)outp + r * N + n) = pack2(v0, v1);
                }
            }
        }
    } else {
        float* out = (float*)outp;
        __syncthreads();
        float* T = (float*)sm;    // [128][66] floats
        #pragma unroll
        for (int chunk = 0; chunk < 2; chunk++) {
            if ((wn >> 1) == chunk) {
                #pragma unroll
                for (int mt = 0; mt < 4; mt++) {
                    #pragma unroll
                    for (int nt = 0; nt < 4; nt++) {
                        int cl = (wn & 1) * 32 + nt * 8 + cg * 2;
                        int n  = n0 + chunk * 64 + cl;
                        float2 b2 = *(const float2*)(bias + n);
                        #pragma unroll
                        for (int h = 0; h < 2; h++) {
                            int rl = wm * 64 + mt * 16 + h * 8 + gr;
                            long r = m0 + rl;
                            float2 rr = unpack2(*(const uint32_t*)(res + r * 384 + n));
                            T[rl * 66 + cl]     = acc[mt][nt][h * 2 + 0] + b2.x + rr.x;
                            T[rl * 66 + cl + 1] = acc[mt][nt][h * 2 + 1] + b2.y + rr.y;
                        }
                    }
                }
            }
            __syncthreads();
            int ch = tid & 63;
            for (int g = tid >> 6; g < 16; g += 4) {
                long m = m0 + g * 8;
                int winI = (int)(m >> 6), sI = (int)(m & 63);
                int bI = winI >> 8, whI = (winI >> 4) & 15, wwI = winI & 15;
                int n = n0 + chunk * 64 + ch;
                long base = ((long)(bI * 384 + n)) * 16384
                          + (long)(whI * 8 + (sI >> 3)) * 128 + wwI * 8;
                float v[8];
                #pragma unroll
                for (int i = 0; i < 8; i++) v[i] = T[(g * 8 + i) * 66 + ch];
                *(float4*)(out + base)     = make_float4(v[0], v[1], v[2], v[3]);
                *(float4*)(out + base + 4) = make_float4(v[4], v[5], v[6], v[7]);
            }
            __syncthreads();
        }
    }
}

// ===========================================================================
// Kernel 3: tensor-core attention. One block = 2 heads of one window.
// (R10 structure; staging loop divisions replaced with incremental stepping)
// ===========================================================================
__global__ void __launch_bounds__(256, 4) attn_kernel(
    const __half* __restrict__ QKV, __half* __restrict__ O)
{
    __shared__ __half qkv[64 * 296];
    const int STRB = 592;

    const int hp  = blockIdx.x;
    const int h0  = hp * 2;
    const long tok0 = (long)blockIdx.y * 64;
    const int tid = threadIdx.x;
    const int lane = tid & 31, wid = tid >> 5;

    // stage Q|K|V slices for 2 heads: 2304 16B-chunks, 9 per thread.
    // chunk index steps by 256 = 7*36 + 4 -> incremental (row,seg) update.
    {
        const __half* g = QKV + tok0 * 1152 + h0 * 48;
        int row = tid / 36, seg = tid % 36;    // one division, outside loop
        #pragma unroll
        for (int i = 0; i < 9; i++) {
            int part = (seg >= 24) ? 2 : ((seg >= 12) ? 1 : 0);
            int sub  = seg - part * 12;
            *(uint4*)&qkv[row * 296 + seg * 8] =
                *(const uint4*)(g + (long)row * 1152 + part * 384 + sub * 8);
            seg += 4; row += 7;
            if (seg >= 36) { seg -= 36; row += 1; }
        }
    }
    __syncthreads();

    const uint32_t sb = (uint32_t)__cvta_generic_to_shared(qkv);
    const int hl = wid >> 2;
    const int m0 = (wid & 3) * 16;
    const int gr = lane >> 2, cg = lane & 3;

    const int qoffB = hl * 96;
    const int koffB = 192 + hl * 96;
    const int voffB = 384 + hl * 96;

    const int lrow = (lane & 7) + ((lane >> 3) & 1) * 8;
    const int lkA  = lane >> 4;
    const int krow = (lane & 7) + ((lane >> 4) & 1) * 8;
    const int kcolb= ((lane >> 3) & 1) * 16;
    const int vrow = (lane & 7) + ((lane >> 3) & 1) * 8;
    const int vsel = lane >> 4;

    float sacc[8][4];
    #pragma unroll
    for (int nt = 0; nt < 8; nt++)
        #pragma unroll
        for (int j = 0; j < 4; j++) sacc[nt][j] = 0.f;

    #pragma unroll
    for (int kc = 0; kc < 3; kc++) {
        uint32_t a[4];
        ldsm4(a, sb + (uint32_t)((m0 + lrow) * STRB + qoffB + kc * 32 + lkA * 16));
        #pragma unroll
        for (int j = 0; j < 4; j++) {
            uint32_t b[4];
            ldsm4(b, sb + (uint32_t)((j * 16 + krow) * STRB + koffB + kc * 32 + kcolb));
            mma16(sacc[2 * j],     a[0], a[1], a[2], a[3], b[0], b[1]);
            mma16(sacc[2 * j + 1], a[0], a[1], a[2], a[3], b[2], b[3]);
        }
    }

    const float scale = 0.14433756729740645f;
    float mx0 = -1e30f, mx1 = -1e30f;
    #pragma unroll
    for (int nt = 0; nt < 8; nt++) {
        mx0 = fmaxf(mx0, fmaxf(sacc[nt][0], sacc[nt][1]));
        mx1 = fmaxf(mx1, fmaxf(sacc[nt][2], sacc[nt][3]));
    }
    mx0 = fmaxf(mx0, __shfl_xor_sync(~0u, mx0, 1));
    mx0 = fmaxf(mx0, __shfl_xor_sync(~0u, mx0, 2));
    mx1 = fmaxf(mx1, __shfl_xor_sync(~0u, mx1, 1));
    mx1 = fmaxf(mx1, __shfl_xor_sync(~0u, mx1, 2));
    mx0 *= scale; mx1 *= scale;

    float e[8][4];
    float sum0 = 0.f, sum1 = 0.f;
    #pragma unroll
    for (int nt = 0; nt < 8; nt++) {
        e[nt][0] = __expf(sacc[nt][0] * scale - mx0);
        e[nt][1] = __expf(sacc[nt][1] * scale - mx0);
        e[nt][2] = __expf(sacc[nt][2] * scale - mx1);
        e[nt][3] = __expf(sacc[nt][3] * scale - mx1);
        sum0 += e[nt][0] + e[nt][1];
        sum1 += e[nt][2] + e[nt][3];
    }
    sum0 += __shfl_xor_sync(~0u, sum0, 1);
    sum0 += __shfl_xor_sync(~0u, sum0, 2);
    sum1 += __shfl_xor_sync(~0u, sum1, 1);
    sum1 += __shfl_xor_sync(~0u, sum1, 2);
    float inv0 = 1.f / sum0, inv1 = 1.f / sum1;

    uint32_t p0[8], p1[8];
    #pragma unroll
    for (int nt = 0; nt < 8; nt++) {
        p0[nt] = pack2(e[nt][0] * inv0, e[nt][1] * inv0);
        p1[nt] = pack2(e[nt][2] * inv1, e[nt][3] * inv1);
    }

    float oacc[6][4];
    #pragma unroll
    for (int nt = 0; nt < 6; nt++)
        #pragma unroll
        for (int j = 0; j < 4; j++) oacc[nt][j] = 0.f;

    #pragma unroll
    for (int kc = 0; kc < 4; kc++) {
        uint32_t a0 = p0[2 * kc],     a1 = p1[2 * kc];
        uint32_t a2 = p0[2 * kc + 1], a3 = p1[2 * kc + 1];
        #pragma unroll
        for (int j = 0; j < 3; j++) {
            uint32_t b[4];
            ldsm4t(b, sb + (uint32_t)((kc * 16 + vrow) * STRB
                                      + voffB + (2 * j + vsel) * 16));
            mma16(oacc[2 * j],     a0, a1, a2, a3, b[0], b[1]);
            mma16(oacc[2 * j + 1], a0, a1, a2, a3, b[2], b[3]);
        }
    }

    #pragma unroll
    for (int nt = 0; nt < 6; nt++) {
        long col = (h0 + hl) * 48 + nt * 8 + cg * 2;
        long r0 = tok0 + m0 + gr;
        *(uint32_t*)(O + r0 * 384 + col)       = pack2(oacc[nt][0], oacc[nt][1]);
        *(uint32_t*)(O + (r0 + 8) * 384 + col) = pack2(oacc[nt][2], oacc[nt][3]);
    }
}

// ===========================================================================
// Kernel 5: LayerNorm2, vectorized. 4 tokens per 384-thread block.
// ===========================================================================
__global__ void __launch_bounds__(384) ln2_kernel(
    const __half* __restrict__ Hh,
    const float* __restrict__ gw, const float* __restrict__ gb,
    __half* __restrict__ Y2)
{
    __shared__ float ssum[12], ssq[12];

    int tid = threadIdx.x;
    int tk = tid / 96;
    int tl = tid % 96;
    long t = (long)blockIdx.x * 4 + tk;

    uint2 u = *(const uint2*)(Hh + t * 384 + tl * 4);
    float2 v01 = unpack2(u.x), v23 = unpack2(u.y);
    float sum = v01.x + v01.y + v23.x + v23.y;
    float sq  = v01.x * v01.x + v01.y * v01.y + v23.x * v23.x + v23.y * v23.y;

    #pragma unroll
    for (int o = 16; o; o >>= 1) {
        sum += __shfl_xor_sync(~0u, sum, o);
        sq  += __shfl_xor_sync(~0u, sq,  o);
    }
    int wrp = tid >> 5;
    if ((tid & 31) == 0) { ssum[wrp] = sum; ssq[wrp] = sq; }
    __syncthreads();
    sum = ssum[tk * 3] + ssum[tk * 3 + 1] + ssum[tk * 3 + 2];
    sq  = ssq[tk * 3]  + ssq[tk * 3 + 1]  + ssq[tk * 3 + 2];

    float m  = sum * (1.f / 384.f);
    float rs = rsqrtf(sq * (1.f / 384.f) - m * m + 1e-5f);

    int c = tl * 4;
    float4 w4 = *(const float4*)(gw + c);
    float4 b4 = *(const float4*)(gb + c);
    uint2 o;
    o.x = pack2((v01.x - m) * rs * w4.x + b4.x, (v01.y - m) * rs * w4.y + b4.y);
    o.y = pack2((v23.x - m) * rs * w4.z + b4.z, (v23.y - m) * rs * w4.w + b4.w);
    *(uint2*)(Y2 + t * 384 + c) = o;
}

// ===========================================================================
extern "C" void kernel_launch(void* const* d_in, const int* in_sizes, int n_in,
                              void* d_out, int out_size)
{
    const float* x     = (const float*)d_in[0];
    const float* n1_w  = (const float*)d_in[1];
    const float* n1_b  = (const float*)d_in[2];
    const float* in_w  = (const float*)d_in[3];
    const float* in_b  = (const float*)d_in[4];
    const float* out_w = (const float*)d_in[5];
    const float* out_b = (const float*)d_in[6];
    const float* n2_w  = (const float*)d_in[7];
    const float* n2_b  = (const float*)d_in[8];
    const float* w1    = (const float*)d_in[9];
    const float* b1    = (const float*)d_in[10];
    const float* w2    = (const float*)d_in[11];
    const float* b2    = (const float*)d_in[12];
    float* out = (float*)d_out;

    __half *WINh, *Yh, *Hb, *Wh;
    cudaGetSymbolAddress((void**)&WINh, g_hR);
    cudaGetSymbolAddress((void**)&Yh,   g_hA);
    cudaGetSymbolAddress((void**)&Hb,   g_hB);
    cudaGetSymbolAddress((void**)&Wh,   g_wh);

    __half* QKVh = Hb;
    __half* Oh   = Yh;
    __half* H    = WINh;
    __half* Y2h  = Hb;
    __half* Gh   = Hb + (size_t)TOKS * 384;

    cudaFuncSetAttribute((const void*)mma_gemm<0,384>, cudaFuncAttributeMaxDynamicSharedMemorySize, GEMM_SMEM);
    cudaFuncSetAttribute((const void*)mma_gemm<1,384>, cudaFuncAttributeMaxDynamicSharedMemorySize, GEMM_SMEM);
    cudaFuncSetAttribute((const void*)mma_gemm<2,384>, cudaFuncAttributeMaxDynamicSharedMemorySize, GEMM_SMEM);
    cudaFuncSetAttribute((const void*)mma_gemm<3,768>, cudaFuncAttributeMaxDynamicSharedMemorySize, GEMM_SMEM);

    // 0. convert all weights to fp16
    cvt_all_kernel<<<4608, 256>>>(in_w, out_w, w1, w2, Wh);
    // 1. gather + LN1
    ln1_gather_kernel<<<2048 * 4, 256>>>(x, n1_w, n1_b, Yh, WINh);
    // 2. QKV projection
    mma_gemm<0,384><<<dim3(1152 / 128, TOKS / 128), 256, GEMM_SMEM>>>(Yh, Wh + WQKV_OFF, in_b, nullptr, QKVh, 1152);
    // 3. tensor-core attention: 2 heads per block, 4 CTAs/SM
    attn_kernel<<<dim3(4, 2048), 256>>>(QKVh, Oh);
    // 4. out projection + residual -> H
    mma_gemm<2,384><<<dim3(384 / 128, TOKS / 128), 256, GEMM_SMEM>>>(Oh, Wh + WO_OFF, out_b, WINh, H, 384);
    // 5. LN2
    ln2_kernel<<<TOKS / 4, 384>>>(H, n2_w, n2_b, Y2h);
    // 6. MLP fc1 + gelu
    mma_gemm<1,384><<<dim3(768 / 128, TOKS / 128), 256, GEMM_SMEM>>>(Y2h, Wh + W1_OFF, b1, nullptr, Gh, 768);
    // 7. MLP fc2 + residual + window-reverse scatter
    mma_gemm<3,768><<<dim3(384 / 128, TOKS / 128), 256, GEMM_SMEM>>>(Gh, Wh + W2_OFF, b2, H, out, 384);
}

// round 13
// speedup vs baseline: 1.0947x; 1.0086x over previous
#include <cuda_runtime.h>
#include <cuda_fp16.h>
#include <math.h>
#include <stdint.h>

#define TOKS 131072          // 2048 windows * 64 tokens

// fp16 scratch
__device__ __half g_hR[(size_t)TOKS * 384];      // WIN, later H (residual, fp16)
__device__ __half g_hA[(size_t)TOKS * 384];      // Y (post-LN1), later O (attn out)
__device__ __half g_hB[(size_t)TOKS * 1152];     // QKV, later Y2 (384) + G (768)
__device__ __half g_wh[1179648];                 // weights converted to half

#define WQKV_OFF 0
#define WO_OFF   442368
#define W1_OFF   589824
#define W2_OFF   884736

#define GEMM_SMEM   65536     // 128x128 scatter kernel (MODE 3)
#define GEMM_SMEM64 49152     // 64x128 kernel: 4 stages x 12KB

// ===========================================================================
// helpers
// ===========================================================================
__device__ __forceinline__ void cp16(uint32_t dst, const void* src) {
    asm volatile("cp.async.cg.shared.global [%0], [%1], 16;"
        :: "r"(dst), "l"(src));
}
__device__ __forceinline__ void mma16(float* d, uint32_t a0, uint32_t a1,
                                      uint32_t a2, uint32_t a3,
                                      uint32_t b0, uint32_t b1) {
    asm volatile(
        "mma.sync.aligned.m16n8k16.row.col.f32.f16.f16.f32 "
        "{%0,%1,%2,%3}, {%4,%5,%6,%7}, {%8,%9}, {%0,%1,%2,%3};"
        : "+f"(d[0]), "+f"(d[1]), "+f"(d[2]), "+f"(d[3])
        : "r"(a0), "r"(a1), "r"(a2), "r"(a3), "r"(b0), "r"(b1));
}
__device__ __forceinline__ void ldsm4(uint32_t* r, uint32_t addr) {
    asm volatile("ldmatrix.sync.aligned.m8n8.x4.shared.b16 {%0,%1,%2,%3}, [%4];"
        : "=r"(r[0]), "=r"(r[1]), "=r"(r[2]), "=r"(r[3]) : "r"(addr));
}
__device__ __forceinline__ void ldsm4t(uint32_t* r, uint32_t addr) {
    asm volatile("ldmatrix.sync.aligned.m8n8.x4.trans.shared.b16 {%0,%1,%2,%3}, [%4];"
        : "=r"(r[0]), "=r"(r[1]), "=r"(r[2]), "=r"(r[3]) : "r"(addr));
}
__device__ __forceinline__ uint32_t pack2(float a, float b) {
    __half2 h = __floats2half2_rn(a, b);
    return *(uint32_t*)&h;
}
__device__ __forceinline__ float2 unpack2(uint32_t u) {
    return __half22float2(*(__half2*)&u);
}

// ===========================================================================
// Kernel 0: all weights fp32 -> fp16 in one launch
// ===========================================================================
__global__ void __launch_bounds__(256) cvt_all_kernel(
    const float* __restrict__ a, const float* __restrict__ b,
    const float* __restrict__ c, const float* __restrict__ d,
    __half* __restrict__ o)
{
    int i = blockIdx.x * 256 + threadIdx.x;
    if (i < 442368)       o[i] = __float2half(a[i]);
    else if (i < 589824)  o[i] = __float2half(b[i - 442368]);
    else if (i < 884736)  o[i] = __float2half(c[i - 589824]);
    else if (i < 1179648) o[i] = __float2half(d[i - 884736]);
}

// ===========================================================================
// Kernel 1: window gather + LayerNorm1. WIN fp16, Y fp16.
// ===========================================================================
__global__ void __launch_bounds__(256) ln1_gather_kernel(
    const float* __restrict__ x,
    const float* __restrict__ gw, const float* __restrict__ gb,
    __half* __restrict__ Y, __half* __restrict__ WIN)
{
    __shared__ float tile[384][17];
    __shared__ float s_mu[16], s_rs[16];

    int blk  = blockIdx.x;
    int win  = blk >> 2;
    int part = blk & 3;
    int b  = win >> 8;
    int wh = (win >> 4) & 15;
    int ww = win & 15;

    int tid = threadIdx.x;
    int sl  = tid & 15;
    int s   = part * 16 + sl;
    int r   = s >> 3, cw = s & 7;
    long xbase = (long)b * 384 * 16384 + (long)(wh * 8 + r) * 128 + ww * 8 + cw;

    for (int c = tid >> 4; c < 384; c += 16)
        tile[c][sl] = x[xbase + (long)c * 16384];
    __syncthreads();

    int lane = tid & 31, wd = tid >> 5;
    for (int t = wd * 2; t < wd * 2 + 2; t++) {
        float sum = 0.f, sq = 0.f;
        for (int c = lane; c < 384; c += 32) {
            float v = tile[c][t];
            sum += v; sq += v * v;
        }
        #pragma unroll
        for (int o = 16; o; o >>= 1) {
            sum += __shfl_xor_sync(~0u, sum, o);
            sq  += __shfl_xor_sync(~0u, sq,  o);
        }
        if (lane == 0) {
            float m = sum * (1.f / 384.f);
            float var = sq * (1.f / 384.f) - m * m;
            s_mu[t] = m;
            s_rs[t] = rsqrtf(var + 1e-5f);
        }
    }
    __syncthreads();

    long tok0 = (long)win * 64 + part * 16;
    for (int idx = tid; idx < 16 * 384; idx += 256) {
        int c = idx % 384, t = idx / 384;
        float v = tile[c][t];
        long o = (tok0 + t) * 384 + c;
        WIN[o] = __float2half(v);
        Y[o] = __float2half((v - s_mu[t]) * s_rs[t] * gw[c] + gb[c]);
    }
}

// ===========================================================================
// FP16 tensor-core GEMM, BM=64, BN=128, BK=32 (modes 0-2). 256 threads,
// 8 warps in 2(M)x4(N), warp tile 32x32. 4-stage cp.async (12KB/stage),
// 3 CTAs/SM (24 warps) for latency hiding. ldmatrix + swizzle, full unroll.
//  MODE 0: + bias, fp16 out             (QKV)
//  MODE 1: + bias, exact gelu, fp16 out (MLP1 -> G)
//  MODE 2: + bias + res(fp16), fp16 out (attn out proj -> H)
// ===========================================================================
template<int MODE, int K>
__global__ void __launch_bounds__(256, 3) mma_gemm64(
    const __half* __restrict__ A, const __half* __restrict__ W,
    const float* __restrict__ bias, const __half* __restrict__ res,
    void* __restrict__ outp, int N)
{
    extern __shared__ uint32_t sm[];

    const int tid  = threadIdx.x;
    const int lane = tid & 31, wid = tid >> 5;
    const int wm = wid & 1;       // M half (32 rows)
    const int wn = wid >> 1;      // N quarter (32 cols)
    const int gr = lane >> 2;
    const int cg = lane & 3;

    const long m0 = (long)blockIdx.y * 64;
    const int  n0 = blockIdx.x * 128;

    const uint32_t sb = (uint32_t)__cvta_generic_to_shared(sm);
    const __half* Ag = A + m0 * K;
    const __half* Wg = W + (long)n0 * K;

    float acc[2][4][4];
    #pragma unroll
    for (int i = 0; i < 2; i++)
        #pragma unroll
        for (int j = 0; j < 4; j++)
            #pragma unroll
            for (int k = 0; k < 4; k++) acc[i][j][k] = 0.f;

    constexpr int NS = K >> 5;

    // stage: A 64 rows (1 chunk/thr), B 128 rows (2 chunks/thr), swizzled
    auto issue = [&](int s, int p) {
        {
            int row = tid >> 2, c = tid & 3;
            int line = row >> 1;
            uint32_t u = (uint32_t)((((row & 1) << 2) + c) ^ (line & 7));
            cp16(sb + p * 12288u + line * 128u + u * 16u,
                 Ag + (long)row * K + s * 32 + c * 8);
        }
        #pragma unroll
        for (int i = 0; i < 2; i++) {
            int idx = tid + i * 256;
            int row = idx >> 2, c = idx & 3;
            int line = row >> 1;
            uint32_t u = (uint32_t)((((row & 1) << 2) + c) ^ (line & 7));
            cp16(sb + p * 12288u + 4096u + line * 128u + u * 16u,
                 Wg + (long)row * K + s * 32 + c * 8);
        }
        asm volatile("cp.async.commit_group;");
    };

    const int lrow = (lane & 7) + ((lane >> 3) & 1) * 8;
    const int lk   = lane >> 4;

    issue(0, 0);
    issue(1, 1);
    issue(2, 2);
    #pragma unroll
    for (int s = 0; s < NS; s++) {
        const int p = s & 3;
        if (s + 2 < NS)      asm volatile("cp.async.wait_group 2;");
        else if (s + 1 < NS) asm volatile("cp.async.wait_group 1;");
        else                 asm volatile("cp.async.wait_group 0;");
        __syncthreads();
        if (s + 3 < NS) issue(s + 3, (s + 3) & 3);

        const uint32_t abase = sb + p * 12288u;
        const uint32_t bbase = abase + 4096u;

        #pragma unroll
        for (int kc = 0; kc < 2; kc++) {
            int c = kc * 2 + lk;
            uint32_t af[2][4], bq[2][4];
            #pragma unroll
            for (int mt = 0; mt < 2; mt++) {
                int row = wm * 32 + mt * 16 + lrow;
                int line = row >> 1;
                uint32_t u = (uint32_t)((((row & 1) << 2) + c) ^ (line & 7));
                ldsm4(af[mt], abase + line * 128u + u * 16u);
            }
            #pragma unroll
            for (int pr = 0; pr < 2; pr++) {
                int row = wn * 32 + pr * 16 + lrow;
                int line = row >> 1;
                uint32_t u = (uint32_t)((((row & 1) << 2) + c) ^ (line & 7));
                ldsm4(bq[pr], bbase + line * 128u + u * 16u);
            }
            #pragma unroll
            for (int mt = 0; mt < 2; mt++)
                #pragma unroll
                for (int nt = 0; nt < 4; nt++) {
                    int pr = nt >> 1, hi = nt & 1;
                    mma16(acc[mt][nt], af[mt][0], af[mt][1], af[mt][2], af[mt][3],
                          bq[pr][hi], bq[pr][hi + 2]);
                }
        }
    }

    #pragma unroll
    for (int mt = 0; mt < 2; mt++) {
        #pragma unroll
        for (int nt = 0; nt < 4; nt++) {
            int n = n0 + wn * 32 + nt * 8 + cg * 2;
            float2 b2 = *(const float2*)(bias + n);
            #pragma unroll
            for (int h = 0; h < 2; h++) {
                long r = m0 + wm * 32 + mt * 16 + h * 8 + gr;
                float v0 = acc[mt][nt][h * 2 + 0] + b2.x;
                float v1 = acc[mt][nt][h * 2 + 1] + b2.y;
                if (MODE == 1) {
                    v0 = 0.5f * v0 * (1.f + erff(v0 * 0.70710678118654752f));
                    v1 = 0.5f * v1 * (1.f + erff(v1 * 0.70710678118654752f));
                }
                if (MODE == 2) {
                    float2 rr = unpack2(*(const uint32_t*)(res + r * N + n));
                    v0 += rr.x; v1 += rr.y;
                }
                *(uint32_t*)((__half*)outp + r * N + n) = pack2(v0, v1);
            }
        }
    }
}

// ===========================================================================
// FP16 tensor-core GEMM, BM=128, BN=128 (MODE 3): + bias + res(fp16),
// fp32 window-reverse scatter to NCHW out. (proven R10 kernel)
// ===========================================================================
template<int K>
__global__ void __launch_bounds__(256, 2) mma_gemm_sc(
    const __half* __restrict__ A, const __half* __restrict__ W,
    const float* __restrict__ bias, const __half* __restrict__ res,
    float* __restrict__ out, int N)
{
    extern __shared__ uint32_t sm[];

    const int tid  = threadIdx.x;
    const int lane = tid & 31, wid = tid >> 5;
    const int wm = wid & 1;
    const int wn = wid >> 1;
    const int gr = lane >> 2;
    const int cg = lane & 3;

    const long m0 = (long)blockIdx.y * 128;
    const int  n0 = blockIdx.x * 128;

    const uint32_t sb = (uint32_t)__cvta_generic_to_shared(sm);
    const __half* Ag = A + m0 * K;
    const __half* Wg = W + (long)n0 * K;

    float acc[4][4][4];
    #pragma unroll
    for (int i = 0; i < 4; i++)
        #pragma unroll
        for (int j = 0; j < 4; j++)
            #pragma unroll
            for (int k = 0; k < 4; k++) acc[i][j][k] = 0.f;

    constexpr int NS = K >> 5;

    auto issue = [&](int s, int p) {
        #pragma unroll
        for (int i = 0; i < 2; i++) {
            int idx = tid + i * 256;
            int row = idx >> 2, c = idx & 3;
            int line = row >> 1;
            uint32_t u = (uint32_t)((((row & 1) << 2) + c) ^ (line & 7));
            uint32_t off = p * 16384u + line * 128u + u * 16u;
            cp16(sb + off,          Ag + (long)row * K + s * 32 + c * 8);
            cp16(sb + 8192u + off,  Wg + (long)row * K + s * 32 + c * 8);
        }
        asm volatile("cp.async.commit_group;");
    };

    const int lrow = (lane & 7) + ((lane >> 3) & 1) * 8;
    const int lk   = lane >> 4;

    issue(0, 0);
    issue(1, 1);
    issue(2, 2);
    #pragma unroll
    for (int s = 0; s < NS; s++) {
        const int p = s & 3;
        if (s + 2 < NS)      asm volatile("cp.async.wait_group 2;");
        else if (s + 1 < NS) asm volatile("cp.async.wait_group 1;");
        else                 asm volatile("cp.async.wait_group 0;");
        __syncthreads();
        if (s + 3 < NS) issue(s + 3, (s + 3) & 3);

        const uint32_t abase = sb + p * 16384u;
        const uint32_t bbase = abase + 8192u;

        #pragma unroll
        for (int kc = 0; kc < 2; kc++) {
            int c = kc * 2 + lk;
            uint32_t af[4][4], bq[2][4];
            #pragma unroll
            for (int mt = 0; mt < 4; mt++) {
                int row = wm * 64 + mt * 16 + lrow;
                int line = row >> 1;
                uint32_t u = (uint32_t)((((row & 1) << 2) + c) ^ (line & 7));
                ldsm4(af[mt], abase + line * 128u + u * 16u);
            }
            #pragma unroll
            for (int pr = 0; pr < 2; pr++) {
                int row = wn * 32 + pr * 16 + lrow;
                int line = row >> 1;
                uint32_t u = (uint32_t)((((row & 1) << 2) + c) ^ (line & 7));
                ldsm4(bq[pr], bbase + line * 128u + u * 16u);
            }
            #pragma unroll
            for (int mt = 0; mt < 4; mt++)
                #pragma unroll
                for (int nt = 0; nt < 4; nt++) {
                    int pr = nt >> 1, hi = nt & 1;
                    mma16(acc[mt][nt], af[mt][0], af[mt][1], af[mt][2], af[mt][3],
                          bq[pr][hi], bq[pr][hi + 2]);
                }
        }
    }

    __syncthreads();
    float* T = (float*)sm;    // [128][66] floats
    #pragma unroll
    for (int chunk = 0; chunk < 2; chunk++) {
        if ((wn >> 1) == chunk) {
            #pragma unroll
            for (int mt = 0; mt < 4; mt++) {
                #pragma unroll
                for (int nt = 0; nt < 4; nt++) {
                    int cl = (wn & 1) * 32 + nt * 8 + cg * 2;
                    int n  = n0 + chunk * 64 + cl;
                    float2 b2 = *(const float2*)(bias + n);
                    #pragma unroll
                    for (int h = 0; h < 2; h++) {
                        int rl = wm * 64 + mt * 16 + h * 8 + gr;
                        long r = m0 + rl;
                        float2 rr = unpack2(*(const uint32_t*)(res + r * 384 + n));
                        T[rl * 66 + cl]     = acc[mt][nt][h * 2 + 0] + b2.x + rr.x;
                        T[rl * 66 + cl + 1] = acc[mt][nt][h * 2 + 1] + b2.y + rr.y;
                    }
                }
            }
        }
        __syncthreads();
        int ch = tid & 63;
        for (int g = tid >> 6; g < 16; g += 4) {
            long m = m0 + g * 8;
            int winI = (int)(m >> 6), sI = (int)(m & 63);
            int bI = winI >> 8, whI = (winI >> 4) & 15, wwI = winI & 15;
            int n = n0 + chunk * 64 + ch;
            long base = ((long)(bI * 384 + n)) * 16384
                      + (long)(whI * 8 + (sI >> 3)) * 128 + wwI * 8;
            float v[8];
            #pragma unroll
            for (int i = 0; i < 8; i++) v[i] = T[(g * 8 + i) * 66 + ch];
            *(float4*)(out + base)     = make_float4(v[0], v[1], v[2], v[3]);
            *(float4*)(out + base + 4) = make_float4(v[4], v[5], v[6], v[7]);
        }
        __syncthreads();
    }
}

// ===========================================================================
// Kernel 3: tensor-core attention (unchanged from R12 best).
// ===========================================================================
__global__ void __launch_bounds__(256, 4) attn_kernel(
    const __half* __restrict__ QKV, __half* __restrict__ O)
{
    __shared__ __half qkv[64 * 296];
    const int STRB = 592;

    const int hp  = blockIdx.x;
    const int h0  = hp * 2;
    const long tok0 = (long)blockIdx.y * 64;
    const int tid = threadIdx.x;
    const int lane = tid & 31, wid = tid >> 5;

    {
        const __half* g = QKV + tok0 * 1152 + h0 * 48;
        int row = tid / 36, seg = tid % 36;
        #pragma unroll
        for (int i = 0; i < 9; i++) {
            int part = (seg >= 24) ? 2 : ((seg >= 12) ? 1 : 0);
            int sub  = seg - part * 12;
            *(uint4*)&qkv[row * 296 + seg * 8] =
                *(const uint4*)(g + (long)row * 1152 + part * 384 + sub * 8);
            seg += 4; row += 7;
            if (seg >= 36) { seg -= 36; row += 1; }
        }
    }
    __syncthreads();

    const uint32_t sb = (uint32_t)__cvta_generic_to_shared(qkv);
    const int hl = wid >> 2;
    const int m0 = (wid & 3) * 16;
    const int gr = lane >> 2, cg = lane & 3;

    const int qoffB = hl * 96;
    const int koffB = 192 + hl * 96;
    const int voffB = 384 + hl * 96;

    const int lrow = (lane & 7) + ((lane >> 3) & 1) * 8;
    const int lkA  = lane >> 4;
    const int krow = (lane & 7) + ((lane >> 4) & 1) * 8;
    const int kcolb= ((lane >> 3) & 1) * 16;
    const int vrow = (lane & 7) + ((lane >> 3) & 1) * 8;
    const int vsel = lane >> 4;

    float sacc[8][4];
    #pragma unroll
    for (int nt = 0; nt < 8; nt++)
        #pragma unroll
        for (int j = 0; j < 4; j++) sacc[nt][j] = 0.f;

    #pragma unroll
    for (int kc = 0; kc < 3; kc++) {
        uint32_t a[4];
        ldsm4(a, sb + (uint32_t)((m0 + lrow) * STRB + qoffB + kc * 32 + lkA * 16));
        #pragma unroll
        for (int j = 0; j < 4; j++) {
            uint32_t b[4];
            ldsm4(b, sb + (uint32_t)((j * 16 + krow) * STRB + koffB + kc * 32 + kcolb));
            mma16(sacc[2 * j],     a[0], a[1], a[2], a[3], b[0], b[1]);
            mma16(sacc[2 * j + 1], a[0], a[1], a[2], a[3], b[2], b[3]);
        }
    }

    const float scale = 0.14433756729740645f;
    float mx0 = -1e30f, mx1 = -1e30f;
    #pragma unroll
    for (int nt = 0; nt < 8; nt++) {
        mx0 = fmaxf(mx0, fmaxf(sacc[nt][0], sacc[nt][1]));
        mx1 = fmaxf(mx1, fmaxf(sacc[nt][2], sacc[nt][3]));
    }
    mx0 = fmaxf(mx0, __shfl_xor_sync(~0u, mx0, 1));
    mx0 = fmaxf(mx0, __shfl_xor_sync(~0u, mx0, 2));
    mx1 = fmaxf(mx1, __shfl_xor_sync(~0u, mx1, 1));
    mx1 = fmaxf(mx1, __shfl_xor_sync(~0u, mx1, 2));
    mx0 *= scale; mx1 *= scale;

    float e[8][4];
    float sum0 = 0.f, sum1 = 0.f;
    #pragma unroll
    for (int nt = 0; nt < 8; nt++) {
        e[nt][0] = __expf(sacc[nt][0] * scale - mx0);
        e[nt][1] = __expf(sacc[nt][1] * scale - mx0);
        e[nt][2] = __expf(sacc[nt][2] * scale - mx1);
        e[nt][3] = __expf(sacc[nt][3] * scale - mx1);
        sum0 += e[nt][0] + e[nt][1];
        sum1 += e[nt][2] + e[nt][3];
    }
    sum0 += __shfl_xor_sync(~0u, sum0, 1);
    sum0 += __shfl_xor_sync(~0u, sum0, 2);
    sum1 += __shfl_xor_sync(~0u, sum1, 1);
    sum1 += __shfl_xor_sync(~0u, sum1, 2);
    float inv0 = 1.f / sum0, inv1 = 1.f / sum1;

    uint32_t p0[8], p1[8];
    #pragma unroll
    for (int nt = 0; nt < 8; nt++) {
        p0[nt] = pack2(e[nt][0] * inv0, e[nt][1] * inv0);
        p1[nt] = pack2(e[nt][2] * inv1, e[nt][3] * inv1);
    }

    float oacc[6][4];
    #pragma unroll
    for (int nt = 0; nt < 6; nt++)
        #pragma unroll
        for (int j = 0; j < 4; j++) oacc[nt][j] = 0.f;

    #pragma unroll
    for (int kc = 0; kc < 4; kc++) {
        uint32_t a0 = p0[2 * kc],     a1 = p1[2 * kc];
        uint32_t a2 = p0[2 * kc + 1], a3 = p1[2 * kc + 1];
        #pragma unroll
        for (int j = 0; j < 3; j++) {
            uint32_t b[4];
            ldsm4t(b, sb + (uint32_t)((kc * 16 + vrow) * STRB
                                      + voffB + (2 * j + vsel) * 16));
            mma16(oacc[2 * j],     a0, a1, a2, a3, b[0], b[1]);
            mma16(oacc[2 * j + 1], a0, a1, a2, a3, b[2], b[3]);
        }
    }

    #pragma unroll
    for (int nt = 0; nt < 6; nt++) {
        long col = (h0 + hl) * 48 + nt * 8 + cg * 2;
        long r0 = tok0 + m0 + gr;
        *(uint32_t*)(O + r0 * 384 + col)       = pack2(oacc[nt][0], oacc[nt][1]);
        *(uint32_t*)(O + (r0 + 8) * 384 + col) = pack2(oacc[nt][2], oacc[nt][3]);
    }
}

// ===========================================================================
// Kernel 5: LayerNorm2, vectorized. 4 tokens per 384-thread block.
// ===========================================================================
__global__ void __launch_bounds__(384) ln2_kernel(
    const __half* __restrict__ Hh,
    const float* __restrict__ gw, const float* __restrict__ gb,
    __half* __restrict__ Y2)
{
    __shared__ float ssum[12], ssq[12];

    int tid = threadIdx.x;
    int tk = tid / 96;
    int tl = tid % 96;
    long t = (long)blockIdx.x * 4 + tk;

    uint2 u = *(const uint2*)(Hh + t * 384 + tl * 4);
    float2 v01 = unpack2(u.x), v23 = unpack2(u.y);
    float sum = v01.x + v01.y + v23.x + v23.y;
    float sq  = v01.x * v01.x + v01.y * v01.y + v23.x * v23.x + v23.y * v23.y;

    #pragma unroll
    for (int o = 16; o; o >>= 1) {
        sum += __shfl_xor_sync(~0u, sum, o);
        sq  += __shfl_xor_sync(~0u, sq,  o);
    }
    int wrp = tid >> 5;
    if ((tid & 31) == 0) { ssum[wrp] = sum; ssq[wrp] = sq; }
    __syncthreads();
    sum = ssum[tk * 3] + ssum[tk * 3 + 1] + ssum[tk * 3 + 2];
    sq  = ssq[tk * 3]  + ssq[tk * 3 + 1]  + ssq[tk * 3 + 2];

    float m  = sum * (1.f / 384.f);
    float rs = rsqrtf(sq * (1.f / 384.f) - m * m + 1e-5f);

    int c = tl * 4;
    float4 w4 = *(const float4*)(gw + c);
    float4 b4 = *(const float4*)(gb + c);
    uint2 o;
    o.x = pack2((v01.x - m) * rs * w4.x + b4.x, (v01.y - m) * rs * w4.y + b4.y);
    o.y = pack2((v23.x - m) * rs * w4.z + b4.z, (v23.y - m) * rs * w4.w + b4.w);
    *(uint2*)(Y2 + t * 384 + c) = o;
}

// ===========================================================================
extern "C" void kernel_launch(void* const* d_in, const int* in_sizes, int n_in,
                              void* d_out, int out_size)
{
    const float* x     = (const float*)d_in[0];
    const float* n1_w  = (const float*)d_in[1];
    const float* n1_b  = (const float*)d_in[2];
    const float* in_w  = (const float*)d_in[3];
    const float* in_b  = (const float*)d_in[4];
    const float* out_w = (const float*)d_in[5];
    const float* out_b = (const float*)d_in[6];
    const float* n2_w  = (const float*)d_in[7];
    const float* n2_b  = (const float*)d_in[8];
    const float* w1    = (const float*)d_in[9];
    const float* b1    = (const float*)d_in[10];
    const float* w2    = (const float*)d_in[11];
    const float* b2    = (const float*)d_in[12];
    float* out = (float*)d_out;

    __half *WINh, *Yh, *Hb, *Wh;
    cudaGetSymbolAddress((void**)&WINh, g_hR);
    cudaGetSymbolAddress((void**)&Yh,   g_hA);
    cudaGetSymbolAddress((void**)&Hb,   g_hB);
    cudaGetSymbolAddress((void**)&Wh,   g_wh);

    __half* QKVh = Hb;
    __half* Oh   = Yh;
    __half* H    = WINh;
    __half* Y2h  = Hb;
    __half* Gh   = Hb + (size_t)TOKS * 384;

    cudaFuncSetAttribute((const void*)mma_gemm64<0,384>, cudaFuncAttributeMaxDynamicSharedMemorySize, GEMM_SMEM64);
    cudaFuncSetAttribute((const void*)mma_gemm64<1,384>, cudaFuncAttributeMaxDynamicSharedMemorySize, GEMM_SMEM64);
    cudaFuncSetAttribute((const void*)mma_gemm64<2,384>, cudaFuncAttributeMaxDynamicSharedMemorySize, GEMM_SMEM64);
    cudaFuncSetAttribute((const void*)mma_gemm_sc<768>,  cudaFuncAttributeMaxDynamicSharedMemorySize, GEMM_SMEM);

    // 0. convert all weights to fp16
    cvt_all_kernel<<<4608, 256>>>(in_w, out_w, w1, w2, Wh);
    // 1. gather + LN1
    ln1_gather_kernel<<<2048 * 4, 256>>>(x, n1_w, n1_b, Yh, WINh);
    // 2. QKV projection (64x128 tiles, 3 CTAs/SM)
    mma_gemm64<0,384><<<dim3(1152 / 128, TOKS / 64), 256, GEMM_SMEM64>>>(Yh, Wh + WQKV_OFF, in_b, nullptr, QKVh, 1152);
    // 3. tensor-core attention
    attn_kernel<<<dim3(4, 2048), 256>>>(QKVh, Oh);
    // 4. out projection + residual -> H
    mma_gemm64<2,384><<<dim3(384 / 128, TOKS / 64), 256, GEMM_SMEM64>>>(Oh, Wh + WO_OFF, out_b, WINh, H, 384);
    // 5. LN2
    ln2_kernel<<<TOKS / 4, 384>>>(H, n2_w, n2_b, Y2h);
    // 6. MLP fc1 + gelu
    mma_gemm64<1,384><<<dim3(768 / 128, TOKS / 64), 256, GEMM_SMEM64>>>(Y2h, Wh + W1_OFF, b1, nullptr, Gh, 768);
    // 7. MLP fc2 + residual + window-reverse scatter (128x128 kernel)
    mma_gemm_sc<768><<<dim3(384 / 128, TOKS / 128), 256, GEMM_SMEM>>>(Gh, Wh + W2_OFF, b2, H, out, 384);
}

// round 14
// speedup vs baseline: 1.1064x; 1.0107x over previous
#include <cuda_runtime.h>
#include <cuda_fp16.h>
#include <math.h>
#include <stdint.h>

#define TOKS 131072          // 2048 windows * 64 tokens

// fp16 scratch
__device__ __half g_hR[(size_t)TOKS * 384];      // WIN, later H (residual, fp16)
__device__ __half g_hA[(size_t)TOKS * 384];      // Y (post-LN1), later O (attn out)
__device__ __half g_hB[(size_t)TOKS * 1152];     // QKV, later Y2 (384) + G (768)
__device__ __half g_wh[1179648];                 // weights converted to half

#define WQKV_OFF 0
#define WO_OFF   442368
#define W1_OFF   589824
#define W2_OFF   884736

#define GEMM_SMEM   65536     // 128x128 scatter kernel (MODE 3)
#define GEMM_SMEM64 73728     // 64x128 BK=64 kernel: 3 stages x 24KB

// ===========================================================================
// helpers
// ===========================================================================
__device__ __forceinline__ void cp16(uint32_t dst, const void* src) {
    asm volatile("cp.async.cg.shared.global [%0], [%1], 16;"
        :: "r"(dst), "l"(src));
}
__device__ __forceinline__ void mma16(float* d, uint32_t a0, uint32_t a1,
                                      uint32_t a2, uint32_t a3,
                                      uint32_t b0, uint32_t b1) {
    asm volatile(
        "mma.sync.aligned.m16n8k16.row.col.f32.f16.f16.f32 "
        "{%0,%1,%2,%3}, {%4,%5,%6,%7}, {%8,%9}, {%0,%1,%2,%3};"
        : "+f"(d[0]), "+f"(d[1]), "+f"(d[2]), "+f"(d[3])
        : "r"(a0), "r"(a1), "r"(a2), "r"(a3), "r"(b0), "r"(b1));
}
__device__ __forceinline__ void ldsm4(uint32_t* r, uint32_t addr) {
    asm volatile("ldmatrix.sync.aligned.m8n8.x4.shared.b16 {%0,%1,%2,%3}, [%4];"
        : "=r"(r[0]), "=r"(r[1]), "=r"(r[2]), "=r"(r[3]) : "r"(addr));
}
__device__ __forceinline__ void ldsm4t(uint32_t* r, uint32_t addr) {
    asm volatile("ldmatrix.sync.aligned.m8n8.x4.trans.shared.b16 {%0,%1,%2,%3}, [%4];"
        : "=r"(r[0]), "=r"(r[1]), "=r"(r[2]), "=r"(r[3]) : "r"(addr));
}
__device__ __forceinline__ uint32_t pack2(float a, float b) {
    __half2 h = __floats2half2_rn(a, b);
    return *(uint32_t*)&h;
}
__device__ __forceinline__ float2 unpack2(uint32_t u) {
    return __half22float2(*(__half2*)&u);
}

// ===========================================================================
// Kernel 0: all weights fp32 -> fp16 in one launch
// ===========================================================================
__global__ void __launch_bounds__(256) cvt_all_kernel(
    const float* __restrict__ a, const float* __restrict__ b,
    const float* __restrict__ c, const float* __restrict__ d,
    __half* __restrict__ o)
{
    int i = blockIdx.x * 256 + threadIdx.x;
    if (i < 442368)       o[i] = __float2half(a[i]);
    else if (i < 589824)  o[i] = __float2half(b[i - 442368]);
    else if (i < 884736)  o[i] = __float2half(c[i - 589824]);
    else if (i < 1179648) o[i] = __float2half(d[i - 884736]);
}

// ===========================================================================
// Kernel 1: window gather + LayerNorm1. WIN fp16, Y fp16.
// ===========================================================================
__global__ void __launch_bounds__(256) ln1_gather_kernel(
    const float* __restrict__ x,
    const float* __restrict__ gw, const float* __restrict__ gb,
    __half* __restrict__ Y, __half* __restrict__ WIN)
{
    __shared__ float tile[384][17];
    __shared__ float s_mu[16], s_rs[16];

    int blk  = blockIdx.x;
    int win  = blk >> 2;
    int part = blk & 3;
    int b  = win >> 8;
    int wh = (win >> 4) & 15;
    int ww = win & 15;

    int tid = threadIdx.x;
    int sl  = tid & 15;
    int s   = part * 16 + sl;
    int r   = s >> 3, cw = s & 7;
    long xbase = (long)b * 384 * 16384 + (long)(wh * 8 + r) * 128 + ww * 8 + cw;

    for (int c = tid >> 4; c < 384; c += 16)
        tile[c][sl] = x[xbase + (long)c * 16384];
    __syncthreads();

    int lane = tid & 31, wd = tid >> 5;
    for (int t = wd * 2; t < wd * 2 + 2; t++) {
        float sum = 0.f, sq = 0.f;
        for (int c = lane; c < 384; c += 32) {
            float v = tile[c][t];
            sum += v; sq += v * v;
        }
        #pragma unroll
        for (int o = 16; o; o >>= 1) {
            sum += __shfl_xor_sync(~0u, sum, o);
            sq  += __shfl_xor_sync(~0u, sq,  o);
        }
        if (lane == 0) {
            float m = sum * (1.f / 384.f);
            float var = sq * (1.f / 384.f) - m * m;
            s_mu[t] = m;
            s_rs[t] = rsqrtf(var + 1e-5f);
        }
    }
    __syncthreads();

    long tok0 = (long)win * 64 + part * 16;
    for (int idx = tid; idx < 16 * 384; idx += 256) {
        int c = idx % 384, t = idx / 384;
        float v = tile[c][t];
        long o = (tok0 + t) * 384 + c;
        WIN[o] = __float2half(v);
        Y[o] = __float2half((v - s_mu[t]) * s_rs[t] * gw[c] + gb[c]);
    }
}

// ===========================================================================
// FP16 tensor-core GEMM, BM=64, BN=128, BK=64 (modes 0-2). 256 threads,
// 8 warps 2(M)x4(N), warp tile 32x32, 32 HMMA/warp per stage (halved
// barrier count vs BK=32). 3-stage cp.async (24KB/stage), 3 CTAs/SM.
// smem rows are full 128B SW128 lines: u = chunk ^ (row & 7).
//  MODE 0: + bias, fp16 out             (QKV)
//  MODE 1: + bias, exact gelu, fp16 out (MLP1 -> G)
//  MODE 2: + bias + res(fp16), fp16 out (attn out proj -> H)
// ===========================================================================
template<int MODE, int K>
__global__ void __launch_bounds__(256, 3) mma_gemm64(
    const __half* __restrict__ A, const __half* __restrict__ W,
    const float* __restrict__ bias, const __half* __restrict__ res,
    void* __restrict__ outp, int N)
{
    extern __shared__ uint32_t sm[];

    const int tid  = threadIdx.x;
    const int lane = tid & 31, wid = tid >> 5;
    const int wm = wid & 1;       // M half (32 rows)
    const int wn = wid >> 1;      // N quarter (32 cols)
    const int gr = lane >> 2;
    const int cg = lane & 3;

    const long m0 = (long)blockIdx.y * 64;
    const int  n0 = blockIdx.x * 128;

    const uint32_t sb = (uint32_t)__cvta_generic_to_shared(sm);
    const __half* Ag = A + m0 * K;
    const __half* Wg = W + (long)n0 * K;

    float acc[2][4][4];
    #pragma unroll
    for (int i = 0; i < 2; i++)
        #pragma unroll
        for (int j = 0; j < 4; j++)
            #pragma unroll
            for (int k = 0; k < 4; k++) acc[i][j][k] = 0.f;

    constexpr int NS = K >> 6;    // BK=64 stages

    // stage: A 64 rows x 8 chunks (2/thr), B 128 rows x 8 chunks (4/thr)
    auto issue = [&](int s, int p) {
        #pragma unroll
        for (int i = 0; i < 2; i++) {
            int idx = tid + i * 256;
            int row = idx >> 3, c = idx & 7;
            uint32_t u = (uint32_t)(c ^ (row & 7));
            cp16(sb + p * 24576u + row * 128u + u * 16u,
                 Ag + (long)row * K + s * 64 + c * 8);
        }
        #pragma unroll
        for (int i = 0; i < 4; i++) {
            int idx = tid + i * 256;
            int row = idx >> 3, c = idx & 7;
            uint32_t u = (uint32_t)(c ^ (row & 7));
            cp16(sb + p * 24576u + 8192u + row * 128u + u * 16u,
                 Wg + (long)row * K + s * 64 + c * 8);
        }
        asm volatile("cp.async.commit_group;");
    };

    const int lrow = (lane & 7) + ((lane >> 3) & 1) * 8;
    const int lk   = lane >> 4;

    issue(0, 0);
    issue(1, 1);
    #pragma unroll
    for (int s = 0; s < NS; s++) {
        const int p = s - (s / 3) * 3;          // s % 3, constexpr-folded
        if (s + 1 < NS) asm volatile("cp.async.wait_group 1;");
        else            asm volatile("cp.async.wait_group 0;");
        __syncthreads();
        if (s + 2 < NS) {
            int s2 = s + 2;
            issue(s2, s2 - (s2 / 3) * 3);
        }

        const uint32_t abase = sb + p * 24576u;
        const uint32_t bbase = abase + 8192u;

        #pragma unroll
        for (int kc = 0; kc < 4; kc++) {
            int c = kc * 2 + lk;
            uint32_t af[2][4], bq[2][4];
            #pragma unroll
            for (int mt = 0; mt < 2; mt++) {
                int row = wm * 32 + mt * 16 + lrow;
                uint32_t u = (uint32_t)(c ^ (row & 7));
                ldsm4(af[mt], abase + row * 128u + u * 16u);
            }
            #pragma unroll
            for (int pr = 0; pr < 2; pr++) {
                int row = wn * 32 + pr * 16 + lrow;
                uint32_t u = (uint32_t)(c ^ (row & 7));
                ldsm4(bq[pr], bbase + row * 128u + u * 16u);
            }
            #pragma unroll
            for (int mt = 0; mt < 2; mt++)
                #pragma unroll
                for (int nt = 0; nt < 4; nt++) {
                    int pr = nt >> 1, hi = nt & 1;
                    mma16(acc[mt][nt], af[mt][0], af[mt][1], af[mt][2], af[mt][3],
                          bq[pr][hi], bq[pr][hi + 2]);
                }
        }
    }

    #pragma unroll
    for (int mt = 0; mt < 2; mt++) {
        #pragma unroll
        for (int nt = 0; nt < 4; nt++) {
            int n = n0 + wn * 32 + nt * 8 + cg * 2;
            float2 b2 = *(const float2*)(bias + n);
            #pragma unroll
            for (int h = 0; h < 2; h++) {
                long r = m0 + wm * 32 + mt * 16 + h * 8 + gr;
                float v0 = acc[mt][nt][h * 2 + 0] + b2.x;
                float v1 = acc[mt][nt][h * 2 + 1] + b2.y;
                if (MODE == 1) {
                    v0 = 0.5f * v0 * (1.f + erff(v0 * 0.70710678118654752f));
                    v1 = 0.5f * v1 * (1.f + erff(v1 * 0.70710678118654752f));
                }
                if (MODE == 2) {
                    float2 rr = unpack2(*(const uint32_t*)(res + r * N + n));
                    v0 += rr.x; v1 += rr.y;
                }
                *(uint32_t*)((__half*)outp + r * N + n) = pack2(v0, v1);
            }
        }
    }
}

// ===========================================================================
// FP16 tensor-core GEMM, BM=128, BN=128, BK=32 (MODE 3): + bias + res(fp16),
// fp32 window-reverse scatter to NCHW out. (proven R10 kernel, unchanged)
// ===========================================================================
template<int K>
__global__ void __launch_bounds__(256, 2) mma_gemm_sc(
    const __half* __restrict__ A, const __half* __restrict__ W,
    const float* __restrict__ bias, const __half* __restrict__ res,
    float* __restrict__ out, int N)
{
    extern __shared__ uint32_t sm[];

    const int tid  = threadIdx.x;
    const int lane = tid & 31, wid = tid >> 5;
    const int wm = wid & 1;
    const int wn = wid >> 1;
    const int gr = lane >> 2;
    const int cg = lane & 3;

    const long m0 = (long)blockIdx.y * 128;
    const int  n0 = blockIdx.x * 128;

    const uint32_t sb = (uint32_t)__cvta_generic_to_shared(sm);
    const __half* Ag = A + m0 * K;
    const __half* Wg = W + (long)n0 * K;

    float acc[4][4][4];
    #pragma unroll
    for (int i = 0; i < 4; i++)
        #pragma unroll
        for (int j = 0; j < 4; j++)
            #pragma unroll
            for (int k = 0; k < 4; k++) acc[i][j][k] = 0.f;

    constexpr int NS = K >> 5;

    auto issue = [&](int s, int p) {
        #pragma unroll
        for (int i = 0; i < 2; i++) {
            int idx = tid + i * 256;
            int row = idx >> 2, c = idx & 3;
            int line = row >> 1;
            uint32_t u = (uint32_t)((((row & 1) << 2) + c) ^ (line & 7));
            uint32_t off = p * 16384u + line * 128u + u * 16u;
            cp16(sb + off,          Ag + (long)row * K + s * 32 + c * 8);
            cp16(sb + 8192u + off,  Wg + (long)row * K + s * 32 + c * 8);
        }
        asm volatile("cp.async.commit_group;");
    };

    const int lrow = (lane & 7) + ((lane >> 3) & 1) * 8;
    const int lk   = lane >> 4;

    issue(0, 0);
    issue(1, 1);
    issue(2, 2);
    #pragma unroll
    for (int s = 0; s < NS; s++) {
        const int p = s & 3;
        if (s + 2 < NS)      asm volatile("cp.async.wait_group 2;");
        else if (s + 1 < NS) asm volatile("cp.async.wait_group 1;");
        else                 asm volatile("cp.async.wait_group 0;");
        __syncthreads();
        if (s + 3 < NS) issue(s + 3, (s + 3) & 3);

        const uint32_t abase = sb + p * 16384u;
        const uint32_t bbase = abase + 8192u;

        #pragma unroll
        for (int kc = 0; kc < 2; kc++) {
            int c = kc * 2 + lk;
            uint32_t af[4][4], bq[2][4];
            #pragma unroll
            for (int mt = 0; mt < 4; mt++) {
                int row = wm * 64 + mt * 16 + lrow;
                int line = row >> 1;
                uint32_t u = (uint32_t)((((row & 1) << 2) + c) ^ (line & 7));
                ldsm4(af[mt], abase + line * 128u + u * 16u);
            }
            #pragma unroll
            for (int pr = 0; pr < 2; pr++) {
                int row = wn * 32 + pr * 16 + lrow;
                int line = row >> 1;
                uint32_t u = (uint32_t)((((row & 1) << 2) + c) ^ (line & 7));
                ldsm4(bq[pr], bbase + line * 128u + u * 16u);
            }
            #pragma unroll
            for (int mt = 0; mt < 4; mt++)
                #pragma unroll
                for (int nt = 0; nt < 4; nt++) {
                    int pr = nt >> 1, hi = nt & 1;
                    mma16(acc[mt][nt], af[mt][0], af[mt][1], af[mt][2], af[mt][3],
                          bq[pr][hi], bq[pr][hi + 2]);
                }
        }
    }

    __syncthreads();
    float* T = (float*)sm;    // [128][66] floats
    #pragma unroll
    for (int chunk = 0; chunk < 2; chunk++) {
        if ((wn >> 1) == chunk) {
            #pragma unroll
            for (int mt = 0; mt < 4; mt++) {
                #pragma unroll
                for (int nt = 0; nt < 4; nt++) {
                    int cl = (wn & 1) * 32 + nt * 8 + cg * 2;
                    int n  = n0 + chunk * 64 + cl;
                    float2 b2 = *(const float2*)(bias + n);
                    #pragma unroll
                    for (int h = 0; h < 2; h++) {
                        int rl = wm * 64 + mt * 16 + h * 8 + gr;
                        long r = m0 + rl;
                        float2 rr = unpack2(*(const uint32_t*)(res + r * 384 + n));
                        T[rl * 66 + cl]     = acc[mt][nt][h * 2 + 0] + b2.x + rr.x;
                        T[rl * 66 + cl + 1] = acc[mt][nt][h * 2 + 1] + b2.y + rr.y;
                    }
                }
            }
        }
        __syncthreads();
        int ch = tid & 63;
        for (int g = tid >> 6; g < 16; g += 4) {
            long m = m0 + g * 8;
            int winI = (int)(m >> 6), sI = (int)(m & 63);
            int bI = winI >> 8, whI = (winI >> 4) & 15, wwI = winI & 15;
            int n = n0 + chunk * 64 + ch;
            long base = ((long)(bI * 384 + n)) * 16384
                      + (long)(whI * 8 + (sI >> 3)) * 128 + wwI * 8;
            float v[8];
            #pragma unroll
            for (int i = 0; i < 8; i++) v[i] = T[(g * 8 + i) * 66 + ch];
            *(float4*)(out + base)     = make_float4(v[0], v[1], v[2], v[3]);
            *(float4*)(out + base + 4) = make_float4(v[4], v[5], v[6], v[7]);
        }
        __syncthreads();
    }
}

// ===========================================================================
// Kernel 3: tensor-core attention (unchanged from R13 best).
// ===========================================================================
__global__ void __launch_bounds__(256, 4) attn_kernel(
    const __half* __restrict__ QKV, __half* __restrict__ O)
{
    __shared__ __half qkv[64 * 296];
    const int STRB = 592;

    const int hp  = blockIdx.x;
    const int h0  = hp * 2;
    const long tok0 = (long)blockIdx.y * 64;
    const int tid = threadIdx.x;
    const int lane = tid & 31, wid = tid >> 5;

    {
        const __half* g = QKV + tok0 * 1152 + h0 * 48;
        int row = tid / 36, seg = tid % 36;
        #pragma unroll
        for (int i = 0; i < 9; i++) {
            int part = (seg >= 24) ? 2 : ((seg >= 12) ? 1 : 0);
            int sub  = seg - part * 12;
            *(uint4*)&qkv[row * 296 + seg * 8] =
                *(const uint4*)(g + (long)row * 1152 + part * 384 + sub * 8);
            seg += 4; row += 7;
            if (seg >= 36) { seg -= 36; row += 1; }
        }
    }
    __syncthreads();

    const uint32_t sb = (uint32_t)__cvta_generic_to_shared(qkv);
    const int hl = wid >> 2;
    const int m0 = (wid & 3) * 16;
    const int gr = lane >> 2, cg = lane & 3;

    const int qoffB = hl * 96;
    const int koffB = 192 + hl * 96;
    const int voffB = 384 + hl * 96;

    const int lrow = (lane & 7) + ((lane >> 3) & 1) * 8;
    const int lkA  = lane >> 4;
    const int krow = (lane & 7) + ((lane >> 4) & 1) * 8;
    const int kcolb= ((lane >> 3) & 1) * 16;
    const int vrow = (lane & 7) + ((lane >> 3) & 1) * 8;
    const int vsel = lane >> 4;

    float sacc[8][4];
    #pragma unroll
    for (int nt = 0; nt < 8; nt++)
        #pragma unroll
        for (int j = 0; j < 4; j++) sacc[nt][j] = 0.f;

    #pragma unroll
    for (int kc = 0; kc < 3; kc++) {
        uint32_t a[4];
        ldsm4(a, sb + (uint32_t)((m0 + lrow) * STRB + qoffB + kc * 32 + lkA * 16));
        #pragma unroll
        for (int j = 0; j < 4; j++) {
            uint32_t b[4];
            ldsm4(b, sb + (uint32_t)((j * 16 + krow) * STRB + koffB + kc * 32 + kcolb));
            mma16(sacc[2 * j],     a[0], a[1], a[2], a[3], b[0], b[1]);
            mma16(sacc[2 * j + 1], a[0], a[1], a[2], a[3], b[2], b[3]);
        }
    }

    const float scale = 0.14433756729740645f;
    float mx0 = -1e30f, mx1 = -1e30f;
    #pragma unroll
    for (int nt = 0; nt < 8; nt++) {
        mx0 = fmaxf(mx0, fmaxf(sacc[nt][0], sacc[nt][1]));
        mx1 = fmaxf(mx1, fmaxf(sacc[nt][2], sacc[nt][3]));
    }
    mx0 = fmaxf(mx0, __shfl_xor_sync(~0u, mx0, 1));
    mx0 = fmaxf(mx0, __shfl_xor_sync(~0u, mx0, 2));
    mx1 = fmaxf(mx1, __shfl_xor_sync(~0u, mx1, 1));
    mx1 = fmaxf(mx1, __shfl_xor_sync(~0u, mx1, 2));
    mx0 *= scale; mx1 *= scale;

    float e[8][4];
    float sum0 = 0.f, sum1 = 0.f;
    #pragma unroll
    for (int nt = 0; nt < 8; nt++) {
        e[nt][0] = __expf(sacc[nt][0] * scale - mx0);
        e[nt][1] = __expf(sacc[nt][1] * scale - mx0);
        e[nt][2] = __expf(sacc[nt][2] * scale - mx1);
        e[nt][3] = __expf(sacc[nt][3] * scale - mx1);
        sum0 += e[nt][0] + e[nt][1];
        sum1 += e[nt][2] + e[nt][3];
    }
    sum0 += __shfl_xor_sync(~0u, sum0, 1);
    sum0 += __shfl_xor_sync(~0u, sum0, 2);
    sum1 += __shfl_xor_sync(~0u, sum1, 1);
    sum1 += __shfl_xor_sync(~0u, sum1, 2);
    float inv0 = 1.f / sum0, inv1 = 1.f / sum1;

    uint32_t p0[8], p1[8];
    #pragma unroll
    for (int nt = 0; nt < 8; nt++) {
        p0[nt] = pack2(e[nt][0] * inv0, e[nt][1] * inv0);
        p1[nt] = pack2(e[nt][2] * inv1, e[nt][3] * inv1);
    }

    float oacc[6][4];
    #pragma unroll
    for (int nt = 0; nt < 6; nt++)
        #pragma unroll
        for (int j = 0; j < 4; j++) oacc[nt][j] = 0.f;

    #pragma unroll
    for (int kc = 0; kc < 4; kc++) {
        uint32_t a0 = p0[2 * kc],     a1 = p1[2 * kc];
        uint32_t a2 = p0[2 * kc + 1], a3 = p1[2 * kc + 1];
        #pragma unroll
        for (int j = 0; j < 3; j++) {
            uint32_t b[4];
            ldsm4t(b, sb + (uint32_t)((kc * 16 + vrow) * STRB
                                      + voffB + (2 * j + vsel) * 16));
            mma16(oacc[2 * j],     a0, a1, a2, a3, b[0], b[1]);
            mma16(oacc[2 * j + 1], a0, a1, a2, a3, b[2], b[3]);
        }
    }

    #pragma unroll
    for (int nt = 0; nt < 6; nt++) {
        long col = (h0 + hl) * 48 + nt * 8 + cg * 2;
        long r0 = tok0 + m0 + gr;
        *(uint32_t*)(O + r0 * 384 + col)       = pack2(oacc[nt][0], oacc[nt][1]);
        *(uint32_t*)(O + (r0 + 8) * 384 + col) = pack2(oacc[nt][2], oacc[nt][3]);
    }
}

// ===========================================================================
// Kernel 5: LayerNorm2, vectorized. 4 tokens per 384-thread block.
// ===========================================================================
__global__ void __launch_bounds__(384) ln2_kernel(
    const __half* __restrict__ Hh,
    const float* __restrict__ gw, const float* __restrict__ gb,
    __half* __restrict__ Y2)
{
    __shared__ float ssum[12], ssq[12];

    int tid = threadIdx.x;
    int tk = tid / 96;
    int tl = tid % 96;
    long t = (long)blockIdx.x * 4 + tk;

    uint2 u = *(const uint2*)(Hh + t * 384 + tl * 4);
    float2 v01 = unpack2(u.x), v23 = unpack2(u.y);
    float sum = v01.x + v01.y + v23.x + v23.y;
    float sq  = v01.x * v01.x + v01.y * v01.y + v23.x * v23.x + v23.y * v23.y;

    #pragma unroll
    for (int o = 16; o; o >>= 1) {
        sum += __shfl_xor_sync(~0u, sum, o);
        sq  += __shfl_xor_sync(~0u, sq,  o);
    }
    int wrp = tid >> 5;
    if ((tid & 31) == 0) { ssum[wrp] = sum; ssq[wrp] = sq; }
    __syncthreads();
    sum = ssum[tk * 3] + ssum[tk * 3 + 1] + ssum[tk * 3 + 2];
    sq  = ssq[tk * 3]  + ssq[tk * 3 + 1]  + ssq[tk * 3 + 2];

    float m  = sum * (1.f / 384.f);
    float rs = rsqrtf(sq * (1.f / 384.f) - m * m + 1e-5f);

    int c = tl * 4;
    float4 w4 = *(const float4*)(gw + c);
    float4 b4 = *(const float4*)(gb + c);
    uint2 o;
    o.x = pack2((v01.x - m) * rs * w4.x + b4.x, (v01.y - m) * rs * w4.y + b4.y);
    o.y = pack2((v23.x - m) * rs * w4.z + b4.z, (v23.y - m) * rs * w4.w + b4.w);
    *(uint2*)(Y2 + t * 384 + c) = o;
}

// ===========================================================================
extern "C" void kernel_launch(void* const* d_in, const int* in_sizes, int n_in,
                              void* d_out, int out_size)
{
    const float* x     = (const float*)d_in[0];
    const float* n1_w  = (const float*)d_in[1];
    const float* n1_b  = (const float*)d_in[2];
    const float* in_w  = (const float*)d_in[3];
    const float* in_b  = (const float*)d_in[4];
    const float* out_w = (const float*)d_in[5];
    const float* out_b = (const float*)d_in[6];
    const float* n2_w  = (const float*)d_in[7];
    const float* n2_b  = (const float*)d_in[8];
    const float* w1    = (const float*)d_in[9];
    const float* b1    = (const float*)d_in[10];
    const float* w2    = (const float*)d_in[11];
    const float* b2    = (const float*)d_in[12];
    float* out = (float*)d_out;

    __half *WINh, *Yh, *Hb, *Wh;
    cudaGetSymbolAddress((void**)&WINh, g_hR);
    cudaGetSymbolAddress((void**)&Yh,   g_hA);
    cudaGetSymbolAddress((void**)&Hb,   g_hB);
    cudaGetSymbolAddress((void**)&Wh,   g_wh);

    __half* QKVh = Hb;
    __half* Oh   = Yh;
    __half* H    = WINh;
    __half* Y2h  = Hb;
    __half* Gh   = Hb + (size_t)TOKS * 384;

    cudaFuncSetAttribute((const void*)mma_gemm64<0,384>, cudaFuncAttributeMaxDynamicSharedMemorySize, GEMM_SMEM64);
    cudaFuncSetAttribute((const void*)mma_gemm64<1,384>, cudaFuncAttributeMaxDynamicSharedMemorySize, GEMM_SMEM64);
    cudaFuncSetAttribute((const void*)mma_gemm64<2,384>, cudaFuncAttributeMaxDynamicSharedMemorySize, GEMM_SMEM64);
    cudaFuncSetAttribute((const void*)mma_gemm_sc<768>,  cudaFuncAttributeMaxDynamicSharedMemorySize, GEMM_SMEM);

    // 0. convert all weights to fp16
    cvt_all_kernel<<<4608, 256>>>(in_w, out_w, w1, w2, Wh);
    // 1. gather + LN1
    ln1_gather_kernel<<<2048 * 4, 256>>>(x, n1_w, n1_b, Yh, WINh);
    // 2. QKV projection (64x128 tiles, BK=64, 3 CTAs/SM)
    mma_gemm64<0,384><<<dim3(1152 / 128, TOKS / 64), 256, GEMM_SMEM64>>>(Yh, Wh + WQKV_OFF, in_b, nullptr, QKVh, 1152);
    // 3. tensor-core attention
    attn_kernel<<<dim3(4, 2048), 256>>>(QKVh, Oh);
    // 4. out projection + residual -> H
    mma_gemm64<2,384><<<dim3(384 / 128, TOKS / 64), 256, GEMM_SMEM64>>>(Oh, Wh + WO_OFF, out_b, WINh, H, 384);
    // 5. LN2
    ln2_kernel<<<TOKS / 4, 384>>>(H, n2_w, n2_b, Y2h);
    // 6. MLP fc1 + gelu
    mma_gemm64<1,384><<<dim3(768 / 128, TOKS / 64), 256, GEMM_SMEM64>>>(Y2h, Wh + W1_OFF, b1, nullptr, Gh, 768);
    // 7. MLP fc2 + residual + window-reverse scatter (128x128 BK=32 kernel)
    mma_gemm_sc<768><<<dim3(384 / 128, TOKS / 128), 256, GEMM_SMEM>>>(Gh, Wh + W2_OFF, b2, H, out, 384);
}

// round 15
// speedup vs baseline: 1.1076x; 1.0012x over previous
#include <cuda_runtime.h>
#include <cuda_fp16.h>
#include <math.h>
#include <stdint.h>

#define TOKS 131072          // 2048 windows * 64 tokens

// fp16 scratch
__device__ __half g_hR[(size_t)TOKS * 384];      // WIN, later H (residual, fp16)
__device__ __half g_hA[(size_t)TOKS * 384];      // Y (post-LN1), later O (attn out)
__device__ __half g_hB[(size_t)TOKS * 1152];     // QKV, later Y2 (384) + G (768)
__device__ __half g_wh[1179648];                 // weights converted to half

#define WQKV_OFF 0
#define WO_OFF   442368
#define W1_OFF   589824
#define W2_OFF   884736

#define GEMM_SMEM64 73728     // 64x128 BK=64 kernel: 3 stages x 24KB
#define GEMM_SMEM_SC 98304    // 128x128 BK=64 scatter kernel: 3 stages x 32KB
#define PROJ_SMEM   79872     // proj+LN kernel: 3 stages x 26KB

// ===========================================================================
// helpers
// ===========================================================================
__device__ __forceinline__ void cp16(uint32_t dst, const void* src) {
    asm volatile("cp.async.cg.shared.global [%0], [%1], 16;"
        :: "r"(dst), "l"(src));
}
__device__ __forceinline__ void mma16(float* d, uint32_t a0, uint32_t a1,
                                      uint32_t a2, uint32_t a3,
                                      uint32_t b0, uint32_t b1) {
    asm volatile(
        "mma.sync.aligned.m16n8k16.row.col.f32.f16.f16.f32 "
        "{%0,%1,%2,%3}, {%4,%5,%6,%7}, {%8,%9}, {%0,%1,%2,%3};"
        : "+f"(d[0]), "+f"(d[1]), "+f"(d[2]), "+f"(d[3])
        : "r"(a0), "r"(a1), "r"(a2), "r"(a3), "r"(b0), "r"(b1));
}
__device__ __forceinline__ void ldsm4(uint32_t* r, uint32_t addr) {
    asm volatile("ldmatrix.sync.aligned.m8n8.x4.shared.b16 {%0,%1,%2,%3}, [%4];"
        : "=r"(r[0]), "=r"(r[1]), "=r"(r[2]), "=r"(r[3]) : "r"(addr));
}
__device__ __forceinline__ void ldsm4t(uint32_t* r, uint32_t addr) {
    asm volatile("ldmatrix.sync.aligned.m8n8.x4.trans.shared.b16 {%0,%1,%2,%3}, [%4];"
        : "=r"(r[0]), "=r"(r[1]), "=r"(r[2]), "=r"(r[3]) : "r"(addr));
}
__device__ __forceinline__ uint32_t pack2(float a, float b) {
    __half2 h = __floats2half2_rn(a, b);
    return *(uint32_t*)&h;
}
__device__ __forceinline__ float2 unpack2(uint32_t u) {
    return __half22float2(*(__half2*)&u);
}

// ===========================================================================
// Kernel 0: all weights fp32 -> fp16 in one launch
// ===========================================================================
__global__ void __launch_bounds__(256) cvt_all_kernel(
    const float* __restrict__ a, const float* __restrict__ b,
    const float* __restrict__ c, const float* __restrict__ d,
    __half* __restrict__ o)
{
    int i = blockIdx.x * 256 + threadIdx.x;
    if (i < 442368)       o[i] = __float2half(a[i]);
    else if (i < 589824)  o[i] = __float2half(b[i - 442368]);
    else if (i < 884736)  o[i] = __float2half(c[i - 589824]);
    else if (i < 1179648) o[i] = __float2half(d[i - 884736]);
}

// ===========================================================================
// Kernel 1: window gather + LayerNorm1. WIN fp16, Y fp16.
// ===========================================================================
__global__ void __launch_bounds__(256) ln1_gather_kernel(
    const float* __restrict__ x,
    const float* __restrict__ gw, const float* __restrict__ gb,
    __half* __restrict__ Y, __half* __restrict__ WIN)
{
    __shared__ float tile[384][17];
    __shared__ float s_mu[16], s_rs[16];

    int blk  = blockIdx.x;
    int win  = blk >> 2;
    int part = blk & 3;
    int b  = win >> 8;
    int wh = (win >> 4) & 15;
    int ww = win & 15;

    int tid = threadIdx.x;
    int sl  = tid & 15;
    int s   = part * 16 + sl;
    int r   = s >> 3, cw = s & 7;
    long xbase = (long)b * 384 * 16384 + (long)(wh * 8 + r) * 128 + ww * 8 + cw;

    for (int c = tid >> 4; c < 384; c += 16)
        tile[c][sl] = x[xbase + (long)c * 16384];
    __syncthreads();

    int lane = tid & 31, wd = tid >> 5;
    for (int t = wd * 2; t < wd * 2 + 2; t++) {
        float sum = 0.f, sq = 0.f;
        for (int c = lane; c < 384; c += 32) {
            float v = tile[c][t];
            sum += v; sq += v * v;
        }
        #pragma unroll
        for (int o = 16; o; o >>= 1) {
            sum += __shfl_xor_sync(~0u, sum, o);
            sq  += __shfl_xor_sync(~0u, sq,  o);
        }
        if (lane == 0) {
            float m = sum * (1.f / 384.f);
            float var = sq * (1.f / 384.f) - m * m;
            s_mu[t] = m;
            s_rs[t] = rsqrtf(var + 1e-5f);
        }
    }
    __syncthreads();

    long tok0 = (long)win * 64 + part * 16;
    for (int idx = tid; idx < 16 * 384; idx += 256) {
        int c = idx % 384, t = idx / 384;
        float v = tile[c][t];
        long o = (tok0 + t) * 384 + c;
        WIN[o] = __float2half(v);
        Y[o] = __float2half((v - s_mu[t]) * s_rs[t] * gw[c] + gb[c]);
    }
}

// ===========================================================================
// FP16 tensor-core GEMM, BM=64, BN=128, BK=64 (modes 0-1). 256 threads,
// 3-stage cp.async (24KB/stage), 3 CTAs/SM. (proven R14 kernel)
//  MODE 0: + bias, fp16 out             (QKV)
//  MODE 1: + bias, exact gelu, fp16 out (MLP1 -> G)
// ===========================================================================
template<int MODE, int K>
__global__ void __launch_bounds__(256, 3) mma_gemm64(
    const __half* __restrict__ A, const __half* __restrict__ W,
    const float* __restrict__ bias, const __half* __restrict__ res,
    void* __restrict__ outp, int N)
{
    extern __shared__ uint32_t sm[];

    const int tid  = threadIdx.x;
    const int lane = tid & 31, wid = tid >> 5;
    const int wm = wid & 1;
    const int wn = wid >> 1;
    const int gr = lane >> 2;
    const int cg = lane & 3;

    const long m0 = (long)blockIdx.y * 64;
    const int  n0 = blockIdx.x * 128;

    const uint32_t sb = (uint32_t)__cvta_generic_to_shared(sm);
    const __half* Ag = A + m0 * K;
    const __half* Wg = W + (long)n0 * K;

    float acc[2][4][4];
    #pragma unroll
    for (int i = 0; i < 2; i++)
        #pragma unroll
        for (int j = 0; j < 4; j++)
            #pragma unroll
            for (int k = 0; k < 4; k++) acc[i][j][k] = 0.f;

    constexpr int NS = K >> 6;

    auto issue = [&](int s, int p) {
        #pragma unroll
        for (int i = 0; i < 2; i++) {
            int idx = tid + i * 256;
            int row = idx >> 3, c = idx & 7;
            uint32_t u = (uint32_t)(c ^ (row & 7));
            cp16(sb + p * 24576u + row * 128u + u * 16u,
                 Ag + (long)row * K + s * 64 + c * 8);
        }
        #pragma unroll
        for (int i = 0; i < 4; i++) {
            int idx = tid + i * 256;
            int row = idx >> 3, c = idx & 7;
            uint32_t u = (uint32_t)(c ^ (row & 7));
            cp16(sb + p * 24576u + 8192u + row * 128u + u * 16u,
                 Wg + (long)row * K + s * 64 + c * 8);
        }
        asm volatile("cp.async.commit_group;");
    };

    const int lrow = (lane & 7) + ((lane >> 3) & 1) * 8;
    const int lk   = lane >> 4;

    issue(0, 0);
    issue(1, 1);
    #pragma unroll
    for (int s = 0; s < NS; s++) {
        const int p = s - (s / 3) * 3;
        if (s + 1 < NS) asm volatile("cp.async.wait_group 1;");
        else            asm volatile("cp.async.wait_group 0;");
        __syncthreads();
        if (s + 2 < NS) {
            int s2 = s + 2;
            issue(s2, s2 - (s2 / 3) * 3);
        }

        const uint32_t abase = sb + p * 24576u;
        const uint32_t bbase = abase + 8192u;

        #pragma unroll
        for (int kc = 0; kc < 4; kc++) {
            int c = kc * 2 + lk;
            uint32_t af[2][4], bq[2][4];
            #pragma unroll
            for (int mt = 0; mt < 2; mt++) {
                int row = wm * 32 + mt * 16 + lrow;
                uint32_t u = (uint32_t)(c ^ (row & 7));
                ldsm4(af[mt], abase + row * 128u + u * 16u);
            }
            #pragma unroll
            for (int pr = 0; pr < 2; pr++) {
                int row = wn * 32 + pr * 16 + lrow;
                uint32_t u = (uint32_t)(c ^ (row & 7));
                ldsm4(bq[pr], bbase + row * 128u + u * 16u);
            }
            #pragma unroll
            for (int mt = 0; mt < 2; mt++)
                #pragma unroll
                for (int nt = 0; nt < 4; nt++) {
                    int pr = nt >> 1, hi = nt & 1;
                    mma16(acc[mt][nt], af[mt][0], af[mt][1], af[mt][2], af[mt][3],
                          bq[pr][hi], bq[pr][hi + 2]);
                }
        }
    }

    #pragma unroll
    for (int mt = 0; mt < 2; mt++) {
        #pragma unroll
        for (int nt = 0; nt < 4; nt++) {
            int n = n0 + wn * 32 + nt * 8 + cg * 2;
            float2 b2 = *(const float2*)(bias + n);
            #pragma unroll
            for (int h = 0; h < 2; h++) {
                long r = m0 + wm * 32 + mt * 16 + h * 8 + gr;
                float v0 = acc[mt][nt][h * 2 + 0] + b2.x;
                float v1 = acc[mt][nt][h * 2 + 1] + b2.y;
                if (MODE == 1) {
                    v0 = 0.5f * v0 * (1.f + erff(v0 * 0.70710678118654752f));
                    v1 = 0.5f * v1 * (1.f + erff(v1 * 0.70710678118654752f));
                }
                *(uint32_t*)((__half*)outp + r * N + n) = pack2(v0, v1);
            }
        }
    }
}

// ===========================================================================
// Fused attn-out projection + residual + LayerNorm2.
// BM=32, BN=384 (full row per block), BK=32, 256 threads, 8 warps 2(M)x4(N),
// warp tile 16x96. 3-stage cp.async (26KB/stage), 2 CTAs/SM.
// Epilogue: H = acc + bias + WIN (write fp16), then per-row LN stats via
// shfl + smem cross-warp reduce, write Y2 = LN(H). Eliminates ln2 kernel.
// ===========================================================================
__global__ void __launch_bounds__(256, 2) proj_ln_kernel(
    const __half* __restrict__ A, const __half* __restrict__ W,
    const float* __restrict__ bias, const __half* __restrict__ res,
    const float* __restrict__ gw, const float* __restrict__ gb,
    __half* __restrict__ H, __half* __restrict__ Y2)
{
    extern __shared__ uint32_t sm[];
    const int ST = 26624;     // stage bytes: A 2KB + B 24KB

    const int tid  = threadIdx.x;
    const int lane = tid & 31, wid = tid >> 5;
    const int wm = wid & 1;       // M half (16 rows)
    const int wn = wid >> 1;      // N quarter (96 cols)
    const int gr = lane >> 2;
    const int cg = lane & 3;

    const long m0 = (long)blockIdx.x * 32;
    const uint32_t sb = (uint32_t)__cvta_generic_to_shared(sm);
    const __half* Ag = A + m0 * 384;

    float acc[12][4];
    #pragma unroll
    for (int j = 0; j < 12; j++)
        #pragma unroll
        for (int k = 0; k < 4; k++) acc[j][k] = 0.f;

    const int NS = 12;            // K=384, BK=32

    auto issue = [&](int s, int p) {
        if (tid < 128) {          // A: 32 rows x 4 chunks
            int row = tid >> 2, c = tid & 3;
            int line = row >> 1;
            uint32_t u = (uint32_t)((((row & 1) << 2) + c) ^ (line & 7));
            cp16(sb + p * ST + line * 128u + u * 16u,
                 Ag + (long)row * 384 + s * 32 + c * 8);
        }
        #pragma unroll
        for (int i = 0; i < 6; i++) {   // B: 384 rows x 4 chunks
            int idx = tid + i * 256;
            int row = idx >> 2, c = idx & 3;
            int line = row >> 1;
            uint32_t u = (uint32_t)((((row & 1) << 2) + c) ^ (line & 7));
            cp16(sb + p * ST + 2048u + line * 128u + u * 16u,
                 W + (long)row * 384 + s * 32 + c * 8);
        }
        asm volatile("cp.async.commit_group;");
    };

    const int lrow = (lane & 7) + ((lane >> 3) & 1) * 8;
    const int lk   = lane >> 4;

    issue(0, 0);
    issue(1, 1);
    #pragma unroll
    for (int s = 0; s < NS; s++) {
        const int p = s - (s / 3) * 3;
        if (s + 1 < NS) asm volatile("cp.async.wait_group 1;");
        else            asm volatile("cp.async.wait_group 0;");
        __syncthreads();
        if (s + 2 < NS) {
            int s2 = s + 2;
            issue(s2, s2 - (s2 / 3) * 3);
        }

        const uint32_t abase = sb + p * ST;
        const uint32_t bbase = abase + 2048u;

        #pragma unroll
        for (int kc = 0; kc < 2; kc++) {
            int c = kc * 2 + lk;
            uint32_t af[4], bq[6][4];
            {
                int row = wm * 16 + lrow;
                int line = row >> 1;
                uint32_t u = (uint32_t)((((row & 1) << 2) + c) ^ (line & 7));
                ldsm4(af, abase + line * 128u + u * 16u);
            }
            #pragma unroll
            for (int pr = 0; pr < 6; pr++) {
                int row = wn * 96 + pr * 16 + lrow;
                int line = row >> 1;
                uint32_t u = (uint32_t)((((row & 1) << 2) + c) ^ (line & 7));
                ldsm4(bq[pr], bbase + line * 128u + u * 16u);
            }
            #pragma unroll
            for (int nt = 0; nt < 12; nt++) {
                int pr = nt >> 1, hi = nt & 1;
                mma16(acc[nt], af[0], af[1], af[2], af[3],
                      bq[pr][hi], bq[pr][hi + 2]);
            }
        }
    }

    // ------ epilogue: H + LN2 ------
    __syncthreads();
    float* rsum = (float*)sm;          // [32][4]
    float* rsq  = (float*)sm + 128;    // [32][4]

    const int rl0 = wm * 16 + gr;
    const int rl1 = rl0 + 8;
    const long r0 = m0 + rl0, r1 = m0 + rl1;

    float s0 = 0.f, q0 = 0.f, s1 = 0.f, q1 = 0.f;
    #pragma unroll
    for (int nt = 0; nt < 12; nt++) {
        int n = wn * 96 + nt * 8 + cg * 2;
        float2 b2 = *(const float2*)(bias + n);
        float2 rr0 = unpack2(*(const uint32_t*)(res + r0 * 384 + n));
        float2 rr1 = unpack2(*(const uint32_t*)(res + r1 * 384 + n));
        float v00 = acc[nt][0] + b2.x + rr0.x;
        float v01 = acc[nt][1] + b2.y + rr0.y;
        float v10 = acc[nt][2] + b2.x + rr1.x;
        float v11 = acc[nt][3] + b2.y + rr1.y;
        acc[nt][0] = v00; acc[nt][1] = v01; acc[nt][2] = v10; acc[nt][3] = v11;
        *(uint32_t*)(H + r0 * 384 + n) = pack2(v00, v01);
        *(uint32_t*)(H + r1 * 384 + n) = pack2(v10, v11);
        s0 += v00 + v01; q0 += v00 * v00 + v01 * v01;
        s1 += v10 + v11; q1 += v10 * v10 + v11 * v11;
    }
    s0 += __shfl_xor_sync(~0u, s0, 1); s0 += __shfl_xor_sync(~0u, s0, 2);
    q0 += __shfl_xor_sync(~0u, q0, 1); q0 += __shfl_xor_sync(~0u, q0, 2);
    s1 += __shfl_xor_sync(~0u, s1, 1); s1 += __shfl_xor_sync(~0u, s1, 2);
    q1 += __shfl_xor_sync(~0u, q1, 1); q1 += __shfl_xor_sync(~0u, q1, 2);
    if (cg == 0) {
        rsum[rl0 * 4 + wn] = s0; rsq[rl0 * 4 + wn] = q0;
        rsum[rl1 * 4 + wn] = s1; rsq[rl1 * 4 + wn] = q1;
    }
    __syncthreads();
    float sum0 = rsum[rl0 * 4] + rsum[rl0 * 4 + 1] + rsum[rl0 * 4 + 2] + rsum[rl0 * 4 + 3];
    float sq0  = rsq[rl0 * 4]  + rsq[rl0 * 4 + 1]  + rsq[rl0 * 4 + 2]  + rsq[rl0 * 4 + 3];
    float sum1 = rsum[rl1 * 4] + rsum[rl1 * 4 + 1] + rsum[rl1 * 4 + 2] + rsum[rl1 * 4 + 3];
    float sq1  = rsq[rl1 * 4]  + rsq[rl1 * 4 + 1]  + rsq[rl1 * 4 + 2]  + rsq[rl1 * 4 + 3];
    float mu0 = sum0 * (1.f / 384.f);
    float ir0 = rsqrtf(sq0 * (1.f / 384.f) - mu0 * mu0 + 1e-5f);
    float mu1 = sum1 * (1.f / 384.f);
    float ir1 = rsqrtf(sq1 * (1.f / 384.f) - mu1 * mu1 + 1e-5f);

    #pragma unroll
    for (int nt = 0; nt < 12; nt++) {
        int n = wn * 96 + nt * 8 + cg * 2;
        float2 w2 = *(const float2*)(gw + n);
        float2 g2 = *(const float2*)(gb + n);
        *(uint32_t*)(Y2 + r0 * 384 + n) =
            pack2((acc[nt][0] - mu0) * ir0 * w2.x + g2.x,
                  (acc[nt][1] - mu0) * ir0 * w2.y + g2.y);
        *(uint32_t*)(Y2 + r1 * 384 + n) =
            pack2((acc[nt][2] - mu1) * ir1 * w2.x + g2.x,
                  (acc[nt][3] - mu1) * ir1 * w2.y + g2.y);
    }
}

// ===========================================================================
// FP16 tensor-core GEMM, BM=128, BN=128, BK=64 (MODE 3): + bias + res(fp16),
// fp32 window-reverse scatter to NCHW out. 3-stage cp.async (32KB/stage).
// ===========================================================================
template<int K>
__global__ void __launch_bounds__(256, 2) mma_gemm_sc(
    const __half* __restrict__ A, const __half* __restrict__ W,
    const float* __restrict__ bias, const __half* __restrict__ res,
    float* __restrict__ out, int N)
{
    extern __shared__ uint32_t sm[];

    const int tid  = threadIdx.x;
    const int lane = tid & 31, wid = tid >> 5;
    const int wm = wid & 1;
    const int wn = wid >> 1;
    const int gr = lane >> 2;
    const int cg = lane & 3;

    const long m0 = (long)blockIdx.y * 128;
    const int  n0 = blockIdx.x * 128;

    const uint32_t sb = (uint32_t)__cvta_generic_to_shared(sm);
    const __half* Ag = A + m0 * K;
    const __half* Wg = W + (long)n0 * K;

    float acc[4][4][4];
    #pragma unroll
    for (int i = 0; i < 4; i++)
        #pragma unroll
        for (int j = 0; j < 4; j++)
            #pragma unroll
            for (int k = 0; k < 4; k++) acc[i][j][k] = 0.f;

    constexpr int NS = K >> 6;    // BK=64

    auto issue = [&](int s, int p) {
        #pragma unroll
        for (int i = 0; i < 4; i++) {
            int idx = tid + i * 256;
            int row = idx >> 3, c = idx & 7;
            uint32_t u = (uint32_t)(c ^ (row & 7));
            cp16(sb + p * 32768u + row * 128u + u * 16u,
                 Ag + (long)row * K + s * 64 + c * 8);
            cp16(sb + p * 32768u + 16384u + row * 128u + u * 16u,
                 Wg + (long)row * K + s * 64 + c * 8);
        }
        asm volatile("cp.async.commit_group;");
    };

    const int lrow = (lane & 7) + ((lane >> 3) & 1) * 8;
    const int lk   = lane >> 4;

    issue(0, 0);
    issue(1, 1);
    #pragma unroll
    for (int s = 0; s < NS; s++) {
        const int p = s - (s / 3) * 3;
        if (s + 1 < NS) asm volatile("cp.async.wait_group 1;");
        else            asm volatile("cp.async.wait_group 0;");
        __syncthreads();
        if (s + 2 < NS) {
            int s2 = s + 2;
            issue(s2, s2 - (s2 / 3) * 3);
        }

        const uint32_t abase = sb + p * 32768u;
        const uint32_t bbase = abase + 16384u;

        #pragma unroll
        for (int kc = 0; kc < 4; kc++) {
            int c = kc * 2 + lk;
            uint32_t af[4][4], bq[2][4];
            #pragma unroll
            for (int mt = 0; mt < 4; mt++) {
                int row = wm * 64 + mt * 16 + lrow;
                uint32_t u = (uint32_t)(c ^ (row & 7));
                ldsm4(af[mt], abase + row * 128u + u * 16u);
            }
            #pragma unroll
            for (int pr = 0; pr < 2; pr++) {
                int row = wn * 32 + pr * 16 + lrow;
                uint32_t u = (uint32_t)(c ^ (row & 7));
                ldsm4(bq[pr], bbase + row * 128u + u * 16u);
            }
            #pragma unroll
            for (int mt = 0; mt < 4; mt++)
                #pragma unroll
                for (int nt = 0; nt < 4; nt++) {
                    int pr = nt >> 1, hi = nt & 1;
                    mma16(acc[mt][nt], af[mt][0], af[mt][1], af[mt][2], af[mt][3],
                          bq[pr][hi], bq[pr][hi + 2]);
                }
        }
    }

    __syncthreads();
    float* T = (float*)sm;    // [128][66] floats = 33792B
    #pragma unroll
    for (int chunk = 0; chunk < 2; chunk++) {
        if ((wn >> 1) == chunk) {
            #pragma unroll
            for (int mt = 0; mt < 4; mt++) {
                #pragma unroll
                for (int nt = 0; nt < 4; nt++) {
                    int cl = (wn & 1) * 32 + nt * 8 + cg * 2;
                    int n  = n0 + chunk * 64 + cl;
                    float2 b2 = *(const float2*)(bias + n);
                    #pragma unroll
                    for (int h = 0; h < 2; h++) {
                        int rl = wm * 64 + mt * 16 + h * 8 + gr;
                        long r = m0 + rl;
                        float2 rr = unpack2(*(const uint32_t*)(res + r * 384 + n));
                        T[rl * 66 + cl]     = acc[mt][nt][h * 2 + 0] + b2.x + rr.x;
                        T[rl * 66 + cl + 1] = acc[mt][nt][h * 2 + 1] + b2.y + rr.y;
                    }
                }
            }
        }
        __syncthreads();
        int ch = tid & 63;
        for (int g = tid >> 6; g < 16; g += 4) {
            long m = m0 + g * 8;
            int winI = (int)(m >> 6), sI = (int)(m & 63);
            int bI = winI >> 8, whI = (winI >> 4) & 15, wwI = winI & 15;
            int n = n0 + chunk * 64 + ch;
            long base = ((long)(bI * 384 + n)) * 16384
                      + (long)(whI * 8 + (sI >> 3)) * 128 + wwI * 8;
            float v[8];
            #pragma unroll
            for (int i = 0; i < 8; i++) v[i] = T[(g * 8 + i) * 66 + ch];
            *(float4*)(out + base)     = make_float4(v[0], v[1], v[2], v[3]);
            *(float4*)(out + base + 4) = make_float4(v[4], v[5], v[6], v[7]);
        }
        __syncthreads();
    }
}

// ===========================================================================
// Kernel 3: tensor-core attention (unchanged from R14 best).
// ===========================================================================
__global__ void __launch_bounds__(256, 4) attn_kernel(
    const __half* __restrict__ QKV, __half* __restrict__ O)
{
    __shared__ __half qkv[64 * 296];
    const int STRB = 592;

    const int hp  = blockIdx.x;
    const int h0  = hp * 2;
    const long tok0 = (long)blockIdx.y * 64;
    const int tid = threadIdx.x;
    const int lane = tid & 31, wid = tid >> 5;

    {
        const __half* g = QKV + tok0 * 1152 + h0 * 48;
        int row = tid / 36, seg = tid % 36;
        #pragma unroll
        for (int i = 0; i < 9; i++) {
            int part = (seg >= 24) ? 2 : ((seg >= 12) ? 1 : 0);
            int sub  = seg - part * 12;
            *(uint4*)&qkv[row * 296 + seg * 8] =
                *(const uint4*)(g + (long)row * 1152 + part * 384 + sub * 8);
            seg += 4; row += 7;
            if (seg >= 36) { seg -= 36; row += 1; }
        }
    }
    __syncthreads();

    const uint32_t sb = (uint32_t)__cvta_generic_to_shared(qkv);
    const int hl = wid >> 2;
    const int m0 = (wid & 3) * 16;
    const int gr = lane >> 2, cg = lane & 3;

    const int qoffB = hl * 96;
    const int koffB = 192 + hl * 96;
    const int voffB = 384 + hl * 96;

    const int lrow = (lane & 7) + ((lane >> 3) & 1) * 8;
    const int lkA  = lane >> 4;
    const int krow = (lane & 7) + ((lane >> 4) & 1) * 8;
    const int kcolb= ((lane >> 3) & 1) * 16;
    const int vrow = (lane & 7) + ((lane >> 3) & 1) * 8;
    const int vsel = lane >> 4;

    float sacc[8][4];
    #pragma unroll
    for (int nt = 0; nt < 8; nt++)
        #pragma unroll
        for (int j = 0; j < 4; j++) sacc[nt][j] = 0.f;

    #pragma unroll
    for (int kc = 0; kc < 3; kc++) {
        uint32_t a[4];
        ldsm4(a, sb + (uint32_t)((m0 + lrow) * STRB + qoffB + kc * 32 + lkA * 16));
        #pragma unroll
        for (int j = 0; j < 4; j++) {
            uint32_t b[4];
            ldsm4(b, sb + (uint32_t)((j * 16 + krow) * STRB + koffB + kc * 32 + kcolb));
            mma16(sacc[2 * j],     a[0], a[1], a[2], a[3], b[0], b[1]);
            mma16(sacc[2 * j + 1], a[0], a[1], a[2], a[3], b[2], b[3]);
        }
    }

    const float scale = 0.14433756729740645f;
    float mx0 = -1e30f, mx1 = -1e30f;
    #pragma unroll
    for (int nt = 0; nt < 8; nt++) {
        mx0 = fmaxf(mx0, fmaxf(sacc[nt][0], sacc[nt][1]));
        mx1 = fmaxf(mx1, fmaxf(sacc[nt][2], sacc[nt][3]));
    }
    mx0 = fmaxf(mx0, __shfl_xor_sync(~0u, mx0, 1));
    mx0 = fmaxf(mx0, __shfl_xor_sync(~0u, mx0, 2));
    mx1 = fmaxf(mx1, __shfl_xor_sync(~0u, mx1, 1));
    mx1 = fmaxf(mx1, __shfl_xor_sync(~0u, mx1, 2));
    mx0 *= scale; mx1 *= scale;

    float e[8][4];
    float sum0 = 0.f, sum1 = 0.f;
    #pragma unroll
    for (int nt = 0; nt < 8; nt++) {
        e[nt][0] = __expf(sacc[nt][0] * scale - mx0);
        e[nt][1] = __expf(sacc[nt][1] * scale - mx0);
        e[nt][2] = __expf(sacc[nt][2] * scale - mx1);
        e[nt][3] = __expf(sacc[nt][3] * scale - mx1);
        sum0 += e[nt][0] + e[nt][1];
        sum1 += e[nt][2] + e[nt][3];
    }
    sum0 += __shfl_xor_sync(~0u, sum0, 1);
    sum0 += __shfl_xor_sync(~0u, sum0, 2);
    sum1 += __shfl_xor_sync(~0u, sum1, 1);
    sum1 += __shfl_xor_sync(~0u, sum1, 2);
    float inv0 = 1.f / sum0, inv1 = 1.f / sum1;

    uint32_t p0[8], p1[8];
    #pragma unroll
    for (int nt = 0; nt < 8; nt++) {
        p0[nt] = pack2(e[nt][0] * inv0, e[nt][1] * inv0);
        p1[nt] = pack2(e[nt][2] * inv1, e[nt][3] * inv1);
    }

    float oacc[6][4];
    #pragma unroll
    for (int nt = 0; nt < 6; nt++)
        #pragma unroll
        for (int j = 0; j < 4; j++) oacc[nt][j] = 0.f;

    #pragma unroll
    for (int kc = 0; kc < 4; kc++) {
        uint32_t a0 = p0[2 * kc],     a1 = p1[2 * kc];
        uint32_t a2 = p0[2 * kc + 1], a3 = p1[2 * kc + 1];
        #pragma unroll
        for (int j = 0; j < 3; j++) {
            uint32_t b[4];
            ldsm4t(b, sb + (uint32_t)((kc * 16 + vrow) * STRB
                                      + voffB + (2 * j + vsel) * 16));
            mma16(oacc[2 * j],     a0, a1, a2, a3, b[0], b[1]);
            mma16(oacc[2 * j + 1], a0, a1, a2, a3, b[2], b[3]);
        }
    }

    #pragma unroll
    for (int nt = 0; nt < 6; nt++) {
        long col = (h0 + hl) * 48 + nt * 8 + cg * 2;
        long r0 = tok0 + m0 + gr;
        *(uint32_t*)(O + r0 * 384 + col)       = pack2(oacc[nt][0], oacc[nt][1]);
        *(uint32_t*)(O + (r0 + 8) * 384 + col) = pack2(oacc[nt][2], oacc[nt][3]);
    }
}

// ===========================================================================
extern "C" void kernel_launch(void* const* d_in, const int* in_sizes, int n_in,
                              void* d_out, int out_size)
{
    const float* x     = (const float*)d_in[0];
    const float* n1_w  = (const float*)d_in[1];
    const float* n1_b  = (const float*)d_in[2];
    const float* in_w  = (const float*)d_in[3];
    const float* in_b  = (const float*)d_in[4];
    const float* out_w = (const float*)d_in[5];
    const float* out_b = (const float*)d_in[6];
    const float* n2_w  = (const float*)d_in[7];
    const float* n2_b  = (const float*)d_in[8];
    const float* w1    = (const float*)d_in[9];
    const float* b1    = (const float*)d_in[10];
    const float* w2    = (const float*)d_in[11];
    const float* b2    = (const float*)d_in[12];
    float* out = (float*)d_out;

    __half *WINh, *Yh, *Hb, *Wh;
    cudaGetSymbolAddress((void**)&WINh, g_hR);
    cudaGetSymbolAddress((void**)&Yh,   g_hA);
    cudaGetSymbolAddress((void**)&Hb,   g_hB);
    cudaGetSymbolAddress((void**)&Wh,   g_wh);

    __half* QKVh = Hb;
    __half* Oh   = Yh;
    __half* H    = WINh;
    __half* Y2h  = Hb;
    __half* Gh   = Hb + (size_t)TOKS * 384;

    cudaFuncSetAttribute((const void*)mma_gemm64<0,384>, cudaFuncAttributeMaxDynamicSharedMemorySize, GEMM_SMEM64);
    cudaFuncSetAttribute((const void*)mma_gemm64<1,384>, cudaFuncAttributeMaxDynamicSharedMemorySize, GEMM_SMEM64);
    cudaFuncSetAttribute((const void*)proj_ln_kernel,    cudaFuncAttributeMaxDynamicSharedMemorySize, PROJ_SMEM);
    cudaFuncSetAttribute((const void*)mma_gemm_sc<768>,  cudaFuncAttributeMaxDynamicSharedMemorySize, GEMM_SMEM_SC);

    // 0. convert all weights to fp16
    cvt_all_kernel<<<4608, 256>>>(in_w, out_w, w1, w2, Wh);
    // 1. gather + LN1
    ln1_gather_kernel<<<2048 * 4, 256>>>(x, n1_w, n1_b, Yh, WINh);
    // 2. QKV projection (64x128, BK=64)
    mma_gemm64<0,384><<<dim3(1152 / 128, TOKS / 64), 256, GEMM_SMEM64>>>(Yh, Wh + WQKV_OFF, in_b, nullptr, QKVh, 1152);
    // 3. tensor-core attention
    attn_kernel<<<dim3(4, 2048), 256>>>(QKVh, Oh);
    // 4. fused: out projection + residual -> H, LayerNorm2 -> Y2
    proj_ln_kernel<<<TOKS / 32, 256, PROJ_SMEM>>>(Oh, Wh + WO_OFF, out_b, WINh, n2_w, n2_b, H, Y2h);
    // 5. MLP fc1 + gelu
    mma_gemm64<1,384><<<dim3(768 / 128, TOKS / 64), 256, GEMM_SMEM64>>>(Y2h, Wh + W1_OFF, b1, nullptr, Gh, 768);
    // 6. MLP fc2 + residual + window-reverse scatter (BK=64)
    mma_gemm_sc<768><<<dim3(384 / 128, TOKS / 128), 256, GEMM_SMEM_SC>>>(Gh, Wh + W2_OFF, b2, H, out, 384);
}

// round 16
// speedup vs baseline: 1.1396x; 1.0289x over previous
#include <cuda_runtime.h>
#include <cuda_fp16.h>
#include <math.h>
#include <stdint.h>

#define TOKS 131072          // 2048 windows * 64 tokens

// fp16 scratch
__device__ __half g_hR[(size_t)TOKS * 384];      // WIN, later H (residual, fp16)
__device__ __half g_hA[(size_t)TOKS * 384];      // Y (post-LN1), later O (attn out)
__device__ __half g_hB[(size_t)TOKS * 1152];     // QKV, later Y2 (384) + G (768)
__device__ __half g_wh[1179648];                 // weights converted to half

#define WQKV_OFF 0
#define WO_OFF   442368
#define W1_OFF   589824
#define W2_OFF   884736

#define GEMM_SMEM64 73728     // 64x128 BK=64 kernel: 3 stages x 24KB
#define GEMM_SMEM_SC 98304    // 128x128 BK=64 scatter kernel: 3 stages x 32KB
#define PROJ_SMEM   79872     // proj+LN kernel: 3 stages x 26KB

// ===========================================================================
// helpers
// ===========================================================================
__device__ __forceinline__ void cp16(uint32_t dst, const void* src) {
    asm volatile("cp.async.cg.shared.global [%0], [%1], 16;"
        :: "r"(dst), "l"(src));
}
__device__ __forceinline__ void mma16(float* d, uint32_t a0, uint32_t a1,
                                      uint32_t a2, uint32_t a3,
                                      uint32_t b0, uint32_t b1) {
    asm volatile(
        "mma.sync.aligned.m16n8k16.row.col.f32.f16.f16.f32 "
        "{%0,%1,%2,%3}, {%4,%5,%6,%7}, {%8,%9}, {%0,%1,%2,%3};"
        : "+f"(d[0]), "+f"(d[1]), "+f"(d[2]), "+f"(d[3])
        : "r"(a0), "r"(a1), "r"(a2), "r"(a3), "r"(b0), "r"(b1));
}
__device__ __forceinline__ void ldsm4(uint32_t* r, uint32_t addr) {
    asm volatile("ldmatrix.sync.aligned.m8n8.x4.shared.b16 {%0,%1,%2,%3}, [%4];"
        : "=r"(r[0]), "=r"(r[1]), "=r"(r[2]), "=r"(r[3]) : "r"(addr));
}
__device__ __forceinline__ void ldsm4t(uint32_t* r, uint32_t addr) {
    asm volatile("ldmatrix.sync.aligned.m8n8.x4.trans.shared.b16 {%0,%1,%2,%3}, [%4];"
        : "=r"(r[0]), "=r"(r[1]), "=r"(r[2]), "=r"(r[3]) : "r"(addr));
}
__device__ __forceinline__ uint32_t pack2(float a, float b) {
    __half2 h = __floats2half2_rn(a, b);
    return *(uint32_t*)&h;
}
__device__ __forceinline__ float2 unpack2(uint32_t u) {
    return __half22float2(*(__half2*)&u);
}

// ===========================================================================
// Kernel 0: all weights fp32 -> fp16 in one launch
// ===========================================================================
__global__ void __launch_bounds__(256) cvt_all_kernel(
    const float* __restrict__ a, const float* __restrict__ b,
    const float* __restrict__ c, const float* __restrict__ d,
    __half* __restrict__ o)
{
    int i = blockIdx.x * 256 + threadIdx.x;
    if (i < 442368)       o[i] = __float2half(a[i]);
    else if (i < 589824)  o[i] = __float2half(b[i - 442368]);
    else if (i < 884736)  o[i] = __float2half(c[i - 589824]);
    else if (i < 1179648) o[i] = __float2half(d[i - 884736]);
}

// ===========================================================================
// Kernel 1: window gather + LayerNorm1. WIN fp16, Y fp16.
// Vectorized: x gathered via float4 (4 consecutive w), outputs via half2.
// ===========================================================================
__global__ void __launch_bounds__(256) ln1_gather_kernel(
    const float* __restrict__ x,
    const float* __restrict__ gw, const float* __restrict__ gb,
    __half* __restrict__ Y, __half* __restrict__ WIN)
{
    __shared__ float tile[384][17];
    __shared__ float s_mu[16], s_rs[16];

    int blk  = blockIdx.x;
    int win  = blk >> 2;
    int part = blk & 3;
    int b  = win >> 8;
    int wh = (win >> 4) & 15;
    int ww = win & 15;

    int tid = threadIdx.x;

    // gather: 1536 float4 chunks = 384 ch x 2 rows x 2 half-rows; 6/thread
    {
        long xrow = (long)b * 384 * 16384 + (long)(wh * 8 + part * 2) * 128 + ww * 8;
        #pragma unroll
        for (int j = 0; j < 6; j++) {
            int i  = tid + j * 256;
            int c  = i >> 2;
            int q  = i & 3;
            int r2 = q >> 1;        // row within 2-row strip
            int hf = q & 1;         // which 4-w half
            float4 v = *(const float4*)&x[xrow + (long)c * 16384 + r2 * 128 + hf * 4];
            int sl0 = r2 * 8 + hf * 4;
            tile[c][sl0 + 0] = v.x;
            tile[c][sl0 + 1] = v.y;
            tile[c][sl0 + 2] = v.z;
            tile[c][sl0 + 3] = v.w;
        }
    }
    __syncthreads();

    int lane = tid & 31, wd = tid >> 5;
    for (int t = wd * 2; t < wd * 2 + 2; t++) {
        float sum = 0.f, sq = 0.f;
        for (int c = lane; c < 384; c += 32) {
            float v = tile[c][t];
            sum += v; sq += v * v;
        }
        #pragma unroll
        for (int o = 16; o; o >>= 1) {
            sum += __shfl_xor_sync(~0u, sum, o);
            sq  += __shfl_xor_sync(~0u, sq,  o);
        }
        if (lane == 0) {
            float m = sum * (1.f / 384.f);
            float var = sq * (1.f / 384.f) - m * m;
            s_mu[t] = m;
            s_rs[t] = rsqrtf(var + 1e-5f);
        }
    }
    __syncthreads();

    long tok0 = (long)win * 64 + part * 16;
    // write phase: half2 pairs; 16 tokens x 192 pairs = 3072; 12/thread
    #pragma unroll
    for (int j = 0; j < 12; j++) {
        int i  = tid + j * 256;
        int c2 = i % 192;
        int t  = i / 192;
        int c  = c2 * 2;
        float v0 = tile[c][t],     v1 = tile[c + 1][t];
        float2 w2 = *(const float2*)(gw + c);
        float2 g2 = *(const float2*)(gb + c);
        long o = (tok0 + t) * 384 + c;
        *(uint32_t*)(WIN + o) = pack2(v0, v1);
        *(uint32_t*)(Y + o) = pack2(
            (v0 - s_mu[t]) * s_rs[t] * w2.x + g2.x,
            (v1 - s_mu[t]) * s_rs[t] * w2.y + g2.y);
    }
}

// ===========================================================================
// FP16 tensor-core GEMM, BM=64, BN=128, BK=64 (modes 0-1). 256 threads,
// 3-stage cp.async (24KB/stage), 3 CTAs/SM. (proven R14 kernel)
//  MODE 0: + bias, fp16 out             (QKV)
//  MODE 1: + bias, exact gelu, fp16 out (MLP1 -> G)
// ===========================================================================
template<int MODE, int K>
__global__ void __launch_bounds__(256, 3) mma_gemm64(
    const __half* __restrict__ A, const __half* __restrict__ W,
    const float* __restrict__ bias, const __half* __restrict__ res,
    void* __restrict__ outp, int N)
{
    extern __shared__ uint32_t sm[];

    const int tid  = threadIdx.x;
    const int lane = tid & 31, wid = tid >> 5;
    const int wm = wid & 1;
    const int wn = wid >> 1;
    const int gr = lane >> 2;
    const int cg = lane & 3;

    const long m0 = (long)blockIdx.y * 64;
    const int  n0 = blockIdx.x * 128;

    const uint32_t sb = (uint32_t)__cvta_generic_to_shared(sm);
    const __half* Ag = A + m0 * K;
    const __half* Wg = W + (long)n0 * K;

    float acc[2][4][4];
    #pragma unroll
    for (int i = 0; i < 2; i++)
        #pragma unroll
        for (int j = 0; j < 4; j++)
            #pragma unroll
            for (int k = 0; k < 4; k++) acc[i][j][k] = 0.f;

    constexpr int NS = K >> 6;

    auto issue = [&](int s, int p) {
        #pragma unroll
        for (int i = 0; i < 2; i++) {
            int idx = tid + i * 256;
            int row = idx >> 3, c = idx & 7;
            uint32_t u = (uint32_t)(c ^ (row & 7));
            cp16(sb + p * 24576u + row * 128u + u * 16u,
                 Ag + (long)row * K + s * 64 + c * 8);
        }
        #pragma unroll
        for (int i = 0; i < 4; i++) {
            int idx = tid + i * 256;
            int row = idx >> 3, c = idx & 7;
            uint32_t u = (uint32_t)(c ^ (row & 7));
            cp16(sb + p * 24576u + 8192u + row * 128u + u * 16u,
                 Wg + (long)row * K + s * 64 + c * 8);
        }
        asm volatile("cp.async.commit_group;");
    };

    const int lrow = (lane & 7) + ((lane >> 3) & 1) * 8;
    const int lk   = lane >> 4;

    issue(0, 0);
    issue(1, 1);
    #pragma unroll
    for (int s = 0; s < NS; s++) {
        const int p = s - (s / 3) * 3;
        if (s + 1 < NS) asm volatile("cp.async.wait_group 1;");
        else            asm volatile("cp.async.wait_group 0;");
        __syncthreads();
        if (s + 2 < NS) {
            int s2 = s + 2;
            issue(s2, s2 - (s2 / 3) * 3);
        }

        const uint32_t abase = sb + p * 24576u;
        const uint32_t bbase = abase + 8192u;

        #pragma unroll
        for (int kc = 0; kc < 4; kc++) {
            int c = kc * 2 + lk;
            uint32_t af[2][4], bq[2][4];
            #pragma unroll
            for (int mt = 0; mt < 2; mt++) {
                int row = wm * 32 + mt * 16 + lrow;
                uint32_t u = (uint32_t)(c ^ (row & 7));
                ldsm4(af[mt], abase + row * 128u + u * 16u);
            }
            #pragma unroll
            for (int pr = 0; pr < 2; pr++) {
                int row = wn * 32 + pr * 16 + lrow;
                uint32_t u = (uint32_t)(c ^ (row & 7));
                ldsm4(bq[pr], bbase + row * 128u + u * 16u);
            }
            #pragma unroll
            for (int mt = 0; mt < 2; mt++)
                #pragma unroll
                for (int nt = 0; nt < 4; nt++) {
                    int pr = nt >> 1, hi = nt & 1;
                    mma16(acc[mt][nt], af[mt][0], af[mt][1], af[mt][2], af[mt][3],
                          bq[pr][hi], bq[pr][hi + 2]);
                }
        }
    }

    #pragma unroll
    for (int mt = 0; mt < 2; mt++) {
        #pragma unroll
        for (int nt = 0; nt < 4; nt++) {
            int n = n0 + wn * 32 + nt * 8 + cg * 2;
            float2 b2 = *(const float2*)(bias + n);
            #pragma unroll
            for (int h = 0; h < 2; h++) {
                long r = m0 + wm * 32 + mt * 16 + h * 8 + gr;
                float v0 = acc[mt][nt][h * 2 + 0] + b2.x;
                float v1 = acc[mt][nt][h * 2 + 1] + b2.y;
                if (MODE == 1) {
                    v0 = 0.5f * v0 * (1.f + erff(v0 * 0.70710678118654752f));
                    v1 = 0.5f * v1 * (1.f + erff(v1 * 0.70710678118654752f));
                }
                *(uint32_t*)((__half*)outp + r * N + n) = pack2(v0, v1);
            }
        }
    }
}

// ===========================================================================
// Fused attn-out projection + residual + LayerNorm2. (proven R15 kernel)
// BM=32, BN=384, BK=32, 256 threads, 3-stage cp.async, 2 CTAs/SM.
// ===========================================================================
__global__ void __launch_bounds__(256, 2) proj_ln_kernel(
    const __half* __restrict__ A, const __half* __restrict__ W,
    const float* __restrict__ bias, const __half* __restrict__ res,
    const float* __restrict__ gw, const float* __restrict__ gb,
    __half* __restrict__ H, __half* __restrict__ Y2)
{
    extern __shared__ uint32_t sm[];
    const int ST = 26624;

    const int tid  = threadIdx.x;
    const int lane = tid & 31, wid = tid >> 5;
    const int wm = wid & 1;
    const int wn = wid >> 1;
    const int gr = lane >> 2;
    const int cg = lane & 3;

    const long m0 = (long)blockIdx.x * 32;
    const uint32_t sb = (uint32_t)__cvta_generic_to_shared(sm);
    const __half* Ag = A + m0 * 384;

    float acc[12][4];
    #pragma unroll
    for (int j = 0; j < 12; j++)
        #pragma unroll
        for (int k = 0; k < 4; k++) acc[j][k] = 0.f;

    const int NS = 12;

    auto issue = [&](int s, int p) {
        if (tid < 128) {
            int row = tid >> 2, c = tid & 3;
            int line = row >> 1;
            uint32_t u = (uint32_t)((((row & 1) << 2) + c) ^ (line & 7));
            cp16(sb + p * ST + line * 128u + u * 16u,
                 Ag + (long)row * 384 + s * 32 + c * 8);
        }
        #pragma unroll
        for (int i = 0; i < 6; i++) {
            int idx = tid + i * 256;
            int row = idx >> 2, c = idx & 3;
            int line = row >> 1;
            uint32_t u = (uint32_t)((((row & 1) << 2) + c) ^ (line & 7));
            cp16(sb + p * ST + 2048u + line * 128u + u * 16u,
                 W + (long)row * 384 + s * 32 + c * 8);
        }
        asm volatile("cp.async.commit_group;");
    };

    const int lrow = (lane & 7) + ((lane >> 3) & 1) * 8;
    const int lk   = lane >> 4;

    issue(0, 0);
    issue(1, 1);
    #pragma unroll
    for (int s = 0; s < NS; s++) {
        const int p = s - (s / 3) * 3;
        if (s + 1 < NS) asm volatile("cp.async.wait_group 1;");
        else            asm volatile("cp.async.wait_group 0;");
        __syncthreads();
        if (s + 2 < NS) {
            int s2 = s + 2;
            issue(s2, s2 - (s2 / 3) * 3);
        }

        const uint32_t abase = sb + p * ST;
        const uint32_t bbase = abase + 2048u;

        #pragma unroll
        for (int kc = 0; kc < 2; kc++) {
            int c = kc * 2 + lk;
            uint32_t af[4], bq[6][4];
            {
                int row = wm * 16 + lrow;
                int line = row >> 1;
                uint32_t u = (uint32_t)((((row & 1) << 2) + c) ^ (line & 7));
                ldsm4(af, abase + line * 128u + u * 16u);
            }
            #pragma unroll
            for (int pr = 0; pr < 6; pr++) {
                int row = wn * 96 + pr * 16 + lrow;
                int line = row >> 1;
                uint32_t u = (uint32_t)((((row & 1) << 2) + c) ^ (line & 7));
                ldsm4(bq[pr], bbase + line * 128u + u * 16u);
            }
            #pragma unroll
            for (int nt = 0; nt < 12; nt++) {
                int pr = nt >> 1, hi = nt & 1;
                mma16(acc[nt], af[0], af[1], af[2], af[3],
                      bq[pr][hi], bq[pr][hi + 2]);
            }
        }
    }

    // ------ epilogue: H + LN2 ------
    __syncthreads();
    float* rsum = (float*)sm;
    float* rsq  = (float*)sm + 128;

    const int rl0 = wm * 16 + gr;
    const int rl1 = rl0 + 8;
    const long r0 = m0 + rl0, r1 = m0 + rl1;

    float s0 = 0.f, q0 = 0.f, s1 = 0.f, q1 = 0.f;
    #pragma unroll
    for (int nt = 0; nt < 12; nt++) {
        int n = wn * 96 + nt * 8 + cg * 2;
        float2 b2 = *(const float2*)(bias + n);
        float2 rr0 = unpack2(*(const uint32_t*)(res + r0 * 384 + n));
        float2 rr1 = unpack2(*(const uint32_t*)(res + r1 * 384 + n));
        float v00 = acc[nt][0] + b2.x + rr0.x;
        float v01 = acc[nt][1] + b2.y + rr0.y;
        float v10 = acc[nt][2] + b2.x + rr1.x;
        float v11 = acc[nt][3] + b2.y + rr1.y;
        acc[nt][0] = v00; acc[nt][1] = v01; acc[nt][2] = v10; acc[nt][3] = v11;
        *(uint32_t*)(H + r0 * 384 + n) = pack2(v00, v01);
        *(uint32_t*)(H + r1 * 384 + n) = pack2(v10, v11);
        s0 += v00 + v01; q0 += v00 * v00 + v01 * v01;
        s1 += v10 + v11; q1 += v10 * v10 + v11 * v11;
    }
    s0 += __shfl_xor_sync(~0u, s0, 1); s0 += __shfl_xor_sync(~0u, s0, 2);
    q0 += __shfl_xor_sync(~0u, q0, 1); q0 += __shfl_xor_sync(~0u, q0, 2);
    s1 += __shfl_xor_sync(~0u, s1, 1); s1 += __shfl_xor_sync(~0u, s1, 2);
    q1 += __shfl_xor_sync(~0u, q1, 1); q1 += __shfl_xor_sync(~0u, q1, 2);
    if (cg == 0) {
        rsum[rl0 * 4 + wn] = s0; rsq[rl0 * 4 + wn] = q0;
        rsum[rl1 * 4 + wn] = s1; rsq[rl1 * 4 + wn] = q1;
    }
    __syncthreads();
    float sum0 = rsum[rl0 * 4] + rsum[rl0 * 4 + 1] + rsum[rl0 * 4 + 2] + rsum[rl0 * 4 + 3];
    float sq0  = rsq[rl0 * 4]  + rsq[rl0 * 4 + 1]  + rsq[rl0 * 4 + 2]  + rsq[rl0 * 4 + 3];
    float sum1 = rsum[rl1 * 4] + rsum[rl1 * 4 + 1] + rsum[rl1 * 4 + 2] + rsum[rl1 * 4 + 3];
    float sq1  = rsq[rl1 * 4]  + rsq[rl1 * 4 + 1]  + rsq[rl1 * 4 + 2]  + rsq[rl1 * 4 + 3];
    float mu0 = sum0 * (1.f / 384.f);
    float ir0 = rsqrtf(sq0 * (1.f / 384.f) - mu0 * mu0 + 1e-5f);
    float mu1 = sum1 * (1.f / 384.f);
    float ir1 = rsqrtf(sq1 * (1.f / 384.f) - mu1 * mu1 + 1e-5f);

    #pragma unroll
    for (int nt = 0; nt < 12; nt++) {
        int n = wn * 96 + nt * 8 + cg * 2;
        float2 w2 = *(const float2*)(gw + n);
        float2 g2 = *(const float2*)(gb + n);
        *(uint32_t*)(Y2 + r0 * 384 + n) =
            pack2((acc[nt][0] - mu0) * ir0 * w2.x + g2.x,
                  (acc[nt][1] - mu0) * ir0 * w2.y + g2.y);
        *(uint32_t*)(Y2 + r1 * 384 + n) =
            pack2((acc[nt][2] - mu1) * ir1 * w2.x + g2.x,
                  (acc[nt][3] - mu1) * ir1 * w2.y + g2.y);
    }
}

// ===========================================================================
// FP16 tensor-core GEMM, BM=128, BN=128, BK=64 (MODE 3): + bias + res(fp16),
// fp32 window-reverse scatter to NCHW out. 3-stage cp.async (32KB/stage).
// ===========================================================================
template<int K>
__global__ void __launch_bounds__(256, 2) mma_gemm_sc(
    const __half* __restrict__ A, const __half* __restrict__ W,
    const float* __restrict__ bias, const __half* __restrict__ res,
    float* __restrict__ out, int N)
{
    extern __shared__ uint32_t sm[];

    const int tid  = threadIdx.x;
    const int lane = tid & 31, wid = tid >> 5;
    const int wm = wid & 1;
    const int wn = wid >> 1;
    const int gr = lane >> 2;
    const int cg = lane & 3;

    const long m0 = (long)blockIdx.y * 128;
    const int  n0 = blockIdx.x * 128;

    const uint32_t sb = (uint32_t)__cvta_generic_to_shared(sm);
    const __half* Ag = A + m0 * K;
    const __half* Wg = W + (long)n0 * K;

    float acc[4][4][4];
    #pragma unroll
    for (int i = 0; i < 4; i++)
        #pragma unroll
        for (int j = 0; j < 4; j++)
            #pragma unroll
            for (int k = 0; k < 4; k++) acc[i][j][k] = 0.f;

    constexpr int NS = K >> 6;

    auto issue = [&](int s, int p) {
        #pragma unroll
        for (int i = 0; i < 4; i++) {
            int idx = tid + i * 256;
            int row = idx >> 3, c = idx & 7;
            uint32_t u = (uint32_t)(c ^ (row & 7));
            cp16(sb + p * 32768u + row * 128u + u * 16u,
                 Ag + (long)row * K + s * 64 + c * 8);
            cp16(sb + p * 32768u + 16384u + row * 128u + u * 16u,
                 Wg + (long)row * K + s * 64 + c * 8);
        }
        asm volatile("cp.async.commit_group;");
    };

    const int lrow = (lane & 7) + ((lane >> 3) & 1) * 8;
    const int lk   = lane >> 4;

    issue(0, 0);
    issue(1, 1);
    #pragma unroll
    for (int s = 0; s < NS; s++) {
        const int p = s - (s / 3) * 3;
        if (s + 1 < NS) asm volatile("cp.async.wait_group 1;");
        else            asm volatile("cp.async.wait_group 0;");
        __syncthreads();
        if (s + 2 < NS) {
            int s2 = s + 2;
            issue(s2, s2 - (s2 / 3) * 3);
        }

        const uint32_t abase = sb + p * 32768u;
        const uint32_t bbase = abase + 16384u;

        #pragma unroll
        for (int kc = 0; kc < 4; kc++) {
            int c = kc * 2 + lk;
            uint32_t af[4][4], bq[2][4];
            #pragma unroll
            for (int mt = 0; mt < 4; mt++) {
                int row = wm * 64 + mt * 16 + lrow;
                uint32_t u = (uint32_t)(c ^ (row & 7));
                ldsm4(af[mt], abase + row * 128u + u * 16u);
            }
            #pragma unroll
            for (int pr = 0; pr < 2; pr++) {
                int row = wn * 32 + pr * 16 + lrow;
                uint32_t u = (uint32_t)(c ^ (row & 7));
                ldsm4(bq[pr], bbase + row * 128u + u * 16u);
            }
            #pragma unroll
            for (int mt = 0; mt < 4; mt++)
                #pragma unroll
                for (int nt = 0; nt < 4; nt++) {
                    int pr = nt >> 1, hi = nt & 1;
                    mma16(acc[mt][nt], af[mt][0], af[mt][1], af[mt][2], af[mt][3],
                          bq[pr][hi], bq[pr][hi + 2]);
                }
        }
    }

    __syncthreads();
    float* T = (float*)sm;    // [128][66] floats
    #pragma unroll
    for (int chunk = 0; chunk < 2; chunk++) {
        if ((wn >> 1) == chunk) {
            #pragma unroll
            for (int mt = 0; mt < 4; mt++) {
                #pragma unroll
                for (int nt = 0; nt < 4; nt++) {
                    int cl = (wn & 1) * 32 + nt * 8 + cg * 2;
                    int n  = n0 + chunk * 64 + cl;
                    float2 b2 = *(const float2*)(bias + n);
                    #pragma unroll
                    for (int h = 0; h < 2; h++) {
                        int rl = wm * 64 + mt * 16 + h * 8 + gr;
                        long r = m0 + rl;
                        float2 rr = unpack2(*(const uint32_t*)(res + r * 384 + n));
                        T[rl * 66 + cl]     = acc[mt][nt][h * 2 + 0] + b2.x + rr.x;
                        T[rl * 66 + cl + 1] = acc[mt][nt][h * 2 + 1] + b2.y + rr.y;
                    }
                }
            }
        }
        __syncthreads();
        int ch = tid & 63;
        for (int g = tid >> 6; g < 16; g += 4) {
            long m = m0 + g * 8;
            int winI = (int)(m >> 6), sI = (int)(m & 63);
            int bI = winI >> 8, whI = (winI >> 4) & 15, wwI = winI & 15;
            int n = n0 + chunk * 64 + ch;
            long base = ((long)(bI * 384 + n)) * 16384
                      + (long)(whI * 8 + (sI >> 3)) * 128 + wwI * 8;
            float v[8];
            #pragma unroll
            for (int i = 0; i < 8; i++) v[i] = T[(g * 8 + i) * 66 + ch];
            *(float4*)(out + base)     = make_float4(v[0], v[1], v[2], v[3]);
            *(float4*)(out + base + 4) = make_float4(v[4], v[5], v[6], v[7]);
        }
        __syncthreads();
    }
}

// ===========================================================================
// Kernel 3: tensor-core attention (unchanged from R15 best).
// ===========================================================================
__global__ void __launch_bounds__(256, 4) attn_kernel(
    const __half* __restrict__ QKV, __half* __restrict__ O)
{
    __shared__ __half qkv[64 * 296];
    const int STRB = 592;

    const int hp  = blockIdx.x;
    const int h0  = hp * 2;
    const long tok0 = (long)blockIdx.y * 64;
    const int tid = threadIdx.x;
    const int lane = tid & 31, wid = tid >> 5;

    {
        const __half* g = QKV + tok0 * 1152 + h0 * 48;
        int row = tid / 36, seg = tid % 36;
        #pragma unroll
        for (int i = 0; i < 9; i++) {
            int part = (seg >= 24) ? 2 : ((seg >= 12) ? 1 : 0);
            int sub  = seg - part * 12;
            *(uint4*)&qkv[row * 296 + seg * 8] =
                *(const uint4*)(g + (long)row * 1152 + part * 384 + sub * 8);
            seg += 4; row += 7;
            if (seg >= 36) { seg -= 36; row += 1; }
        }
    }
    __syncthreads();

    const uint32_t sb = (uint32_t)__cvta_generic_to_shared(qkv);
    const int hl = wid >> 2;
    const int m0 = (wid & 3) * 16;
    const int gr = lane >> 2, cg = lane & 3;

    const int qoffB = hl * 96;
    const int koffB = 192 + hl * 96;
    const int voffB = 384 + hl * 96;

    const int lrow = (lane & 7) + ((lane >> 3) & 1) * 8;
    const int lkA  = lane >> 4;
    const int krow = (lane & 7) + ((lane >> 4) & 1) * 8;
    const int kcolb= ((lane >> 3) & 1) * 16;
    const int vrow = (lane & 7) + ((lane >> 3) & 1) * 8;
    const int vsel = lane >> 4;

    float sacc[8][4];
    #pragma unroll
    for (int nt = 0; nt < 8; nt++)
        #pragma unroll
        for (int j = 0; j < 4; j++) sacc[nt][j] = 0.f;

    #pragma unroll
    for (int kc = 0; kc < 3; kc++) {
        uint32_t a[4];
        ldsm4(a, sb + (uint32_t)((m0 + lrow) * STRB + qoffB + kc * 32 + lkA * 16));
        #pragma unroll
        for (int j = 0; j < 4; j++) {
            uint32_t b[4];
            ldsm4(b, sb + (uint32_t)((j * 16 + krow) * STRB + koffB + kc * 32 + kcolb));
            mma16(sacc[2 * j],     a[0], a[1], a[2], a[3], b[0], b[1]);
            mma16(sacc[2 * j + 1], a[0], a[1], a[2], a[3], b[2], b[3]);
        }
    }

    const float scale = 0.14433756729740645f;
    float mx0 = -1e30f, mx1 = -1e30f;
    #pragma unroll
    for (int nt = 0; nt < 8; nt++) {
        mx0 = fmaxf(mx0, fmaxf(sacc[nt][0], sacc[nt][1]));
        mx1 = fmaxf(mx1, fmaxf(sacc[nt][2], sacc[nt][3]));
    }
    mx0 = fmaxf(mx0, __shfl_xor_sync(~0u, mx0, 1));
    mx0 = fmaxf(mx0, __shfl_xor_sync(~0u, mx0, 2));
    mx1 = fmaxf(mx1, __shfl_xor_sync(~0u, mx1, 1));
    mx1 = fmaxf(mx1, __shfl_xor_sync(~0u, mx1, 2));
    mx0 *= scale; mx1 *= scale;

    float e[8][4];
    float sum0 = 0.f, sum1 = 0.f;
    #pragma unroll
    for (int nt = 0; nt < 8; nt++) {
        e[nt][0] = __expf(sacc[nt][0] * scale - mx0);
        e[nt][1] = __expf(sacc[nt][1] * scale - mx0);
        e[nt][2] = __expf(sacc[nt][2] * scale - mx1);
        e[nt][3] = __expf(sacc[nt][3] * scale - mx1);
        sum0 += e[nt][0] + e[nt][1];
        sum1 += e[nt][2] + e[nt][3];
    }
    sum0 += __shfl_xor_sync(~0u, sum0, 1);
    sum0 += __shfl_xor_sync(~0u, sum0, 2);
    sum1 += __shfl_xor_sync(~0u, sum1, 1);
    sum1 += __shfl_xor_sync(~0u, sum1, 2);
    float inv0 = 1.f / sum0, inv1 = 1.f / sum1;

    uint32_t p0[8], p1[8];
    #pragma unroll
    for (int nt = 0; nt < 8; nt++) {
        p0[nt] = pack2(e[nt][0] * inv0, e[nt][1] * inv0);
        p1[nt] = pack2(e[nt][2] * inv1, e[nt][3] * inv1);
    }

    float oacc[6][4];
    #pragma unroll
    for (int nt = 0; nt < 6; nt++)
        #pragma unroll
        for (int j = 0; j < 4; j++) oacc[nt][j] = 0.f;

    #pragma unroll
    for (int kc = 0; kc < 4; kc++) {
        uint32_t a0 = p0[2 * kc],     a1 = p1[2 * kc];
        uint32_t a2 = p0[2 * kc + 1], a3 = p1[2 * kc + 1];
        #pragma unroll
        for (int j = 0; j < 3; j++) {
            uint32_t b[4];
            ldsm4t(b, sb + (uint32_t)((kc * 16 + vrow) * STRB
                                      + voffB + (2 * j + vsel) * 16));
            mma16(oacc[2 * j],     a0, a1, a2, a3, b[0], b[1]);
            mma16(oacc[2 * j + 1], a0, a1, a2, a3, b[2], b[3]);
        }
    }

    #pragma unroll
    for (int nt = 0; nt < 6; nt++) {
        long col = (h0 + hl) * 48 + nt * 8 + cg * 2;
        long r0 = tok0 + m0 + gr;
        *(uint32_t*)(O + r0 * 384 + col)       = pack2(oacc[nt][0], oacc[nt][1]);
        *(uint32_t*)(O + (r0 + 8) * 384 + col) = pack2(oacc[nt][2], oacc[nt][3]);
    }
}

// ===========================================================================
extern "C" void kernel_launch(void* const* d_in, const int* in_sizes, int n_in,
                              void* d_out, int out_size)
{
    const float* x     = (const float*)d_in[0];
    const float* n1_w  = (const float*)d_in[1];
    const float* n1_b  = (const float*)d_in[2];
    const float* in_w  = (const float*)d_in[3];
    const float* in_b  = (const float*)d_in[4];
    const float* out_w = (const float*)d_in[5];
    const float* out_b = (const float*)d_in[6];
    const float* n2_w  = (const float*)d_in[7];
    const float* n2_b  = (const float*)d_in[8];
    const float* w1    = (const float*)d_in[9];
    const float* b1    = (const float*)d_in[10];
    const float* w2    = (const float*)d_in[11];
    const float* b2    = (const float*)d_in[12];
    float* out = (float*)d_out;

    __half *WINh, *Yh, *Hb, *Wh;
    cudaGetSymbolAddress((void**)&WINh, g_hR);
    cudaGetSymbolAddress((void**)&Yh,   g_hA);
    cudaGetSymbolAddress((void**)&Hb,   g_hB);
    cudaGetSymbolAddress((void**)&Wh,   g_wh);

    __half* QKVh = Hb;
    __half* Oh   = Yh;
    __half* H    = WINh;
    __half* Y2h  = Hb;
    __half* Gh   = Hb + (size_t)TOKS * 384;

    cudaFuncSetAttribute((const void*)mma_gemm64<0,384>, cudaFuncAttributeMaxDynamicSharedMemorySize, GEMM_SMEM64);
    cudaFuncSetAttribute((const void*)mma_gemm64<1,384>, cudaFuncAttributeMaxDynamicSharedMemorySize, GEMM_SMEM64);
    cudaFuncSetAttribute((const void*)proj_ln_kernel,    cudaFuncAttributeMaxDynamicSharedMemorySize, PROJ_SMEM);
    cudaFuncSetAttribute((const void*)mma_gemm_sc<768>,  cudaFuncAttributeMaxDynamicSharedMemorySize, GEMM_SMEM_SC);

    // 0. convert all weights to fp16
    cvt_all_kernel<<<4608, 256>>>(in_w, out_w, w1, w2, Wh);
    // 1. gather + LN1 (vectorized)
    ln1_gather_kernel<<<2048 * 4, 256>>>(x, n1_w, n1_b, Yh, WINh);
    // 2. QKV projection (64x128, BK=64)
    mma_gemm64<0,384><<<dim3(1152 / 128, TOKS / 64), 256, GEMM_SMEM64>>>(Yh, Wh + WQKV_OFF, in_b, nullptr, QKVh, 1152);
    // 3. tensor-core attention
    attn_kernel<<<dim3(4, 2048), 256>>>(QKVh, Oh);
    // 4. fused: out projection + residual -> H, LayerNorm2 -> Y2
    proj_ln_kernel<<<TOKS / 32, 256, PROJ_SMEM>>>(Oh, Wh + WO_OFF, out_b, WINh, n2_w, n2_b, H, Y2h);
    // 5. MLP fc1 + gelu
    mma_gemm64<1,384><<<dim3(768 / 128, TOKS / 64), 256, GEMM_SMEM64>>>(Y2h, Wh + W1_OFF, b1, nullptr, Gh, 768);
    // 6. MLP fc2 + residual + window-reverse scatter (BK=64)
    mma_gemm_sc<768><<<dim3(384 / 128, TOKS / 128), 256, GEMM_SMEM_SC>>>(Gh, Wh + W2_OFF, b2, H, out, 384);
}

// round 17
// speedup vs baseline: 1.1538x; 1.0125x over previous
#include <cuda_runtime.h>
#include <cuda_fp16.h>
#include <math.h>
#include <stdint.h>

#define TOKS 131072          // 2048 windows * 64 tokens

// fp16 scratch
__device__ __half g_hR[(size_t)TOKS * 384];      // WIN, later H (residual, fp16)
__device__ __half g_hA[(size_t)TOKS * 384];      // Y (post-LN1), later O (attn out)
__device__ __half g_hB[(size_t)TOKS * 1152];     // QKV, later Y2 (384) + G (768)
__device__ __half g_wh[1179648];                 // weights converted to half

#define WQKV_OFF 0
#define WO_OFF   442368
#define W1_OFF   589824
#define W2_OFF   884736

#define GEMM_SMEM64 73728     // 64x128 BK=64 kernel: 3 stages x 24KB
#define GEMM_SMEM_SC 98304    // 128x128 BK=64 scatter kernel: 3 stages x 32KB
#define PROJ_SMEM   79872     // proj+LN kernel: 3 stages x 26KB

// ===========================================================================
// helpers
// ===========================================================================
__device__ __forceinline__ void cp16(uint32_t dst, const void* src) {
    asm volatile("cp.async.cg.shared.global [%0], [%1], 16;"
        :: "r"(dst), "l"(src));
}
__device__ __forceinline__ void mma16(float* d, uint32_t a0, uint32_t a1,
                                      uint32_t a2, uint32_t a3,
                                      uint32_t b0, uint32_t b1) {
    asm volatile(
        "mma.sync.aligned.m16n8k16.row.col.f32.f16.f16.f32 "
        "{%0,%1,%2,%3}, {%4,%5,%6,%7}, {%8,%9}, {%0,%1,%2,%3};"
        : "+f"(d[0]), "+f"(d[1]), "+f"(d[2]), "+f"(d[3])
        : "r"(a0), "r"(a1), "r"(a2), "r"(a3), "r"(b0), "r"(b1));
}
__device__ __forceinline__ void ldsm4(uint32_t* r, uint32_t addr) {
    asm volatile("ldmatrix.sync.aligned.m8n8.x4.shared.b16 {%0,%1,%2,%3}, [%4];"
        : "=r"(r[0]), "=r"(r[1]), "=r"(r[2]), "=r"(r[3]) : "r"(addr));
}
__device__ __forceinline__ void ldsm4t(uint32_t* r, uint32_t addr) {
    asm volatile("ldmatrix.sync.aligned.m8n8.x4.trans.shared.b16 {%0,%1,%2,%3}, [%4];"
        : "=r"(r[0]), "=r"(r[1]), "=r"(r[2]), "=r"(r[3]) : "r"(addr));
}
__device__ __forceinline__ uint32_t pack2(float a, float b) {
    __half2 h = __floats2half2_rn(a, b);
    return *(uint32_t*)&h;
}
__device__ __forceinline__ float2 unpack2(uint32_t u) {
    return __half22float2(*(__half2*)&u);
}
// exact-form gelu with A&S 7.1.26 erf approximation (|err| < 1.5e-7,
// far below fp16 output resolution -> numerically equivalent to erff path)
__device__ __forceinline__ float gelu_f(float x) {
    float z = fabsf(x) * 0.70710678118654752f;
    float t = __frcp_rn(1.f + 0.3275911f * z);
    float poly = t * (0.254829592f + t * (-0.284496736f +
                 t * (1.421413741f + t * (-1.453152027f + t * 1.061405429f))));
    float erfv = 1.f - poly * __expf(-z * z);
    erfv = copysignf(erfv, x);
    return 0.5f * x * (1.f + erfv);
}

// ===========================================================================
// Kernel 0: all weights fp32 -> fp16 in one launch
// ===========================================================================
__global__ void __launch_bounds__(256) cvt_all_kernel(
    const float* __restrict__ a, const float* __restrict__ b,
    const float* __restrict__ c, const float* __restrict__ d,
    __half* __restrict__ o)
{
    int i = blockIdx.x * 256 + threadIdx.x;
    if (i < 442368)       o[i] = __float2half(a[i]);
    else if (i < 589824)  o[i] = __float2half(b[i - 442368]);
    else if (i < 884736)  o[i] = __float2half(c[i - 589824]);
    else if (i < 1179648) o[i] = __float2half(d[i - 884736]);
}

// ===========================================================================
// Kernel 1: window gather + LayerNorm1 (vectorized, R16 proven).
// ===========================================================================
__global__ void __launch_bounds__(256) ln1_gather_kernel(
    const float* __restrict__ x,
    const float* __restrict__ gw, const float* __restrict__ gb,
    __half* __restrict__ Y, __half* __restrict__ WIN)
{
    __shared__ float tile[384][17];
    __shared__ float s_mu[16], s_rs[16];

    int blk  = blockIdx.x;
    int win  = blk >> 2;
    int part = blk & 3;
    int b  = win >> 8;
    int wh = (win >> 4) & 15;
    int ww = win & 15;

    int tid = threadIdx.x;

    {
        long xrow = (long)b * 384 * 16384 + (long)(wh * 8 + part * 2) * 128 + ww * 8;
        #pragma unroll
        for (int j = 0; j < 6; j++) {
            int i  = tid + j * 256;
            int c  = i >> 2;
            int q  = i & 3;
            int r2 = q >> 1;
            int hf = q & 1;
            float4 v = *(const float4*)&x[xrow + (long)c * 16384 + r2 * 128 + hf * 4];
            int sl0 = r2 * 8 + hf * 4;
            tile[c][sl0 + 0] = v.x;
            tile[c][sl0 + 1] = v.y;
            tile[c][sl0 + 2] = v.z;
            tile[c][sl0 + 3] = v.w;
        }
    }
    __syncthreads();

    int lane = tid & 31, wd = tid >> 5;
    for (int t = wd * 2; t < wd * 2 + 2; t++) {
        float sum = 0.f, sq = 0.f;
        for (int c = lane; c < 384; c += 32) {
            float v = tile[c][t];
            sum += v; sq += v * v;
        }
        #pragma unroll
        for (int o = 16; o; o >>= 1) {
            sum += __shfl_xor_sync(~0u, sum, o);
            sq  += __shfl_xor_sync(~0u, sq,  o);
        }
        if (lane == 0) {
            float m = sum * (1.f / 384.f);
            float var = sq * (1.f / 384.f) - m * m;
            s_mu[t] = m;
            s_rs[t] = rsqrtf(var + 1e-5f);
        }
    }
    __syncthreads();

    long tok0 = (long)win * 64 + part * 16;
    #pragma unroll
    for (int j = 0; j < 12; j++) {
        int i  = tid + j * 256;
        int c2 = i % 192;
        int t  = i / 192;
        int c  = c2 * 2;
        float v0 = tile[c][t],     v1 = tile[c + 1][t];
        float2 w2 = *(const float2*)(gw + c);
        float2 g2 = *(const float2*)(gb + c);
        long o = (tok0 + t) * 384 + c;
        *(uint32_t*)(WIN + o) = pack2(v0, v1);
        *(uint32_t*)(Y + o) = pack2(
            (v0 - s_mu[t]) * s_rs[t] * w2.x + g2.x,
            (v1 - s_mu[t]) * s_rs[t] * w2.y + g2.y);
    }
}

// ===========================================================================
// FP16 tensor-core GEMM, BM=64, BN=128, BK=64 (modes 0-1). 256 threads,
// 3-stage cp.async (24KB/stage), 3 CTAs/SM. (proven R14 kernel)
//  MODE 0: + bias, fp16 out             (QKV)
//  MODE 1: + bias, fast exact gelu, fp16 out (MLP1 -> G)
// ===========================================================================
template<int MODE, int K>
__global__ void __launch_bounds__(256, 3) mma_gemm64(
    const __half* __restrict__ A, const __half* __restrict__ W,
    const float* __restrict__ bias, const __half* __restrict__ res,
    void* __restrict__ outp, int N)
{
    extern __shared__ uint32_t sm[];

    const int tid  = threadIdx.x;
    const int lane = tid & 31, wid = tid >> 5;
    const int wm = wid & 1;
    const int wn = wid >> 1;
    const int gr = lane >> 2;
    const int cg = lane & 3;

    const long m0 = (long)blockIdx.y * 64;
    const int  n0 = blockIdx.x * 128;

    const uint32_t sb = (uint32_t)__cvta_generic_to_shared(sm);
    const __half* Ag = A + m0 * K;
    const __half* Wg = W + (long)n0 * K;

    float acc[2][4][4];
    #pragma unroll
    for (int i = 0; i < 2; i++)
        #pragma unroll
        for (int j = 0; j < 4; j++)
            #pragma unroll
            for (int k = 0; k < 4; k++) acc[i][j][k] = 0.f;

    constexpr int NS = K >> 6;

    auto issue = [&](int s, int p) {
        #pragma unroll
        for (int i = 0; i < 2; i++) {
            int idx = tid + i * 256;
            int row = idx >> 3, c = idx & 7;
            uint32_t u = (uint32_t)(c ^ (row & 7));
            cp16(sb + p * 24576u + row * 128u + u * 16u,
                 Ag + (long)row * K + s * 64 + c * 8);
        }
        #pragma unroll
        for (int i = 0; i < 4; i++) {
            int idx = tid + i * 256;
            int row = idx >> 3, c = idx & 7;
            uint32_t u = (uint32_t)(c ^ (row & 7));
            cp16(sb + p * 24576u + 8192u + row * 128u + u * 16u,
                 Wg + (long)row * K + s * 64 + c * 8);
        }
        asm volatile("cp.async.commit_group;");
    };

    const int lrow = (lane & 7) + ((lane >> 3) & 1) * 8;
    const int lk   = lane >> 4;

    issue(0, 0);
    issue(1, 1);
    #pragma unroll
    for (int s = 0; s < NS; s++) {
        const int p = s - (s / 3) * 3;
        if (s + 1 < NS) asm volatile("cp.async.wait_group 1;");
        else            asm volatile("cp.async.wait_group 0;");
        __syncthreads();
        if (s + 2 < NS) {
            int s2 = s + 2;
            issue(s2, s2 - (s2 / 3) * 3);
        }

        const uint32_t abase = sb + p * 24576u;
        const uint32_t bbase = abase + 8192u;

        #pragma unroll
        for (int kc = 0; kc < 4; kc++) {
            int c = kc * 2 + lk;
            uint32_t af[2][4], bq[2][4];
            #pragma unroll
            for (int mt = 0; mt < 2; mt++) {
                int row = wm * 32 + mt * 16 + lrow;
                uint32_t u = (uint32_t)(c ^ (row & 7));
                ldsm4(af[mt], abase + row * 128u + u * 16u);
            }
            #pragma unroll
            for (int pr = 0; pr < 2; pr++) {
                int row = wn * 32 + pr * 16 + lrow;
                uint32_t u = (uint32_t)(c ^ (row & 7));
                ldsm4(bq[pr], bbase + row * 128u + u * 16u);
            }
            #pragma unroll
            for (int mt = 0; mt < 2; mt++)
                #pragma unroll
                for (int nt = 0; nt < 4; nt++) {
                    int pr = nt >> 1, hi = nt & 1;
                    mma16(acc[mt][nt], af[mt][0], af[mt][1], af[mt][2], af[mt][3],
                          bq[pr][hi], bq[pr][hi + 2]);
                }
        }
    }

    #pragma unroll
    for (int mt = 0; mt < 2; mt++) {
        #pragma unroll
        for (int nt = 0; nt < 4; nt++) {
            int n = n0 + wn * 32 + nt * 8 + cg * 2;
            float2 b2 = *(const float2*)(bias + n);
            #pragma unroll
            for (int h = 0; h < 2; h++) {
                long r = m0 + wm * 32 + mt * 16 + h * 8 + gr;
                float v0 = acc[mt][nt][h * 2 + 0] + b2.x;
                float v1 = acc[mt][nt][h * 2 + 1] + b2.y;
                if (MODE == 1) {
                    v0 = gelu_f(v0);
                    v1 = gelu_f(v1);
                }
                *(uint32_t*)((__half*)outp + r * N + n) = pack2(v0, v1);
            }
        }
    }
}

// ===========================================================================
// Fused attn-out projection + residual + LayerNorm2. (proven R15 kernel)
// ===========================================================================
__global__ void __launch_bounds__(256, 2) proj_ln_kernel(
    const __half* __restrict__ A, const __half* __restrict__ W,
    const float* __restrict__ bias, const __half* __restrict__ res,
    const float* __restrict__ gw, const float* __restrict__ gb,
    __half* __restrict__ H, __half* __restrict__ Y2)
{
    extern __shared__ uint32_t sm[];
    const int ST = 26624;

    const int tid  = threadIdx.x;
    const int lane = tid & 31, wid = tid >> 5;
    const int wm = wid & 1;
    const int wn = wid >> 1;
    const int gr = lane >> 2;
    const int cg = lane & 3;

    const long m0 = (long)blockIdx.x * 32;
    const uint32_t sb = (uint32_t)__cvta_generic_to_shared(sm);
    const __half* Ag = A + m0 * 384;

    float acc[12][4];
    #pragma unroll
    for (int j = 0; j < 12; j++)
        #pragma unroll
        for (int k = 0; k < 4; k++) acc[j][k] = 0.f;

    const int NS = 12;

    auto issue = [&](int s, int p) {
        if (tid < 128) {
            int row = tid >> 2, c = tid & 3;
            int line = row >> 1;
            uint32_t u = (uint32_t)((((row & 1) << 2) + c) ^ (line & 7));
            cp16(sb + p * ST + line * 128u + u * 16u,
                 Ag + (long)row * 384 + s * 32 + c * 8);
        }
        #pragma unroll
        for (int i = 0; i < 6; i++) {
            int idx = tid + i * 256;
            int row = idx >> 2, c = idx & 3;
            int line = row >> 1;
            uint32_t u = (uint32_t)((((row & 1) << 2) + c) ^ (line & 7));
            cp16(sb + p * ST + 2048u + line * 128u + u * 16u,
                 W + (long)row * 384 + s * 32 + c * 8);
        }
        asm volatile("cp.async.commit_group;");
    };

    const int lrow = (lane & 7) + ((lane >> 3) & 1) * 8;
    const int lk   = lane >> 4;

    issue(0, 0);
    issue(1, 1);
    #pragma unroll
    for (int s = 0; s < NS; s++) {
        const int p = s - (s / 3) * 3;
        if (s + 1 < NS) asm volatile("cp.async.wait_group 1;");
        else            asm volatile("cp.async.wait_group 0;");
        __syncthreads();
        if (s + 2 < NS) {
            int s2 = s + 2;
            issue(s2, s2 - (s2 / 3) * 3);
        }

        const uint32_t abase = sb + p * ST;
        const uint32_t bbase = abase + 2048u;

        #pragma unroll
        for (int kc = 0; kc < 2; kc++) {
            int c = kc * 2 + lk;
            uint32_t af[4], bq[6][4];
            {
                int row = wm * 16 + lrow;
                int line = row >> 1;
                uint32_t u = (uint32_t)((((row & 1) << 2) + c) ^ (line & 7));
                ldsm4(af, abase + line * 128u + u * 16u);
            }
            #pragma unroll
            for (int pr = 0; pr < 6; pr++) {
                int row = wn * 96 + pr * 16 + lrow;
                int line = row >> 1;
                uint32_t u = (uint32_t)((((row & 1) << 2) + c) ^ (line & 7));
                ldsm4(bq[pr], bbase + line * 128u + u * 16u);
            }
            #pragma unroll
            for (int nt = 0; nt < 12; nt++) {
                int pr = nt >> 1, hi = nt & 1;
                mma16(acc[nt], af[0], af[1], af[2], af[3],
                      bq[pr][hi], bq[pr][hi + 2]);
            }
        }
    }

    // ------ epilogue: H + LN2 ------
    __syncthreads();
    float* rsum = (float*)sm;
    float* rsq  = (float*)sm + 128;

    const int rl0 = wm * 16 + gr;
    const int rl1 = rl0 + 8;
    const long r0 = m0 + rl0, r1 = m0 + rl1;

    float s0 = 0.f, q0 = 0.f, s1 = 0.f, q1 = 0.f;
    #pragma unroll
    for (int nt = 0; nt < 12; nt++) {
        int n = wn * 96 + nt * 8 + cg * 2;
        float2 b2 = *(const float2*)(bias + n);
        float2 rr0 = unpack2(*(const uint32_t*)(res + r0 * 384 + n));
        float2 rr1 = unpack2(*(const uint32_t*)(res + r1 * 384 + n));
        float v00 = acc[nt][0] + b2.x + rr0.x;
        float v01 = acc[nt][1] + b2.y + rr0.y;
        float v10 = acc[nt][2] + b2.x + rr1.x;
        float v11 = acc[nt][3] + b2.y + rr1.y;
        acc[nt][0] = v00; acc[nt][1] = v01; acc[nt][2] = v10; acc[nt][3] = v11;
        *(uint32_t*)(H + r0 * 384 + n) = pack2(v00, v01);
        *(uint32_t*)(H + r1 * 384 + n) = pack2(v10, v11);
        s0 += v00 + v01; q0 += v00 * v00 + v01 * v01;
        s1 += v10 + v11; q1 += v10 * v10 + v11 * v11;
    }
    s0 += __shfl_xor_sync(~0u, s0, 1); s0 += __shfl_xor_sync(~0u, s0, 2);
    q0 += __shfl_xor_sync(~0u, q0, 1); q0 += __shfl_xor_sync(~0u, q0, 2);
    s1 += __shfl_xor_sync(~0u, s1, 1); s1 += __shfl_xor_sync(~0u, s1, 2);
    q1 += __shfl_xor_sync(~0u, q1, 1); q1 += __shfl_xor_sync(~0u, q1, 2);
    if (cg == 0) {
        rsum[rl0 * 4 + wn] = s0; rsq[rl0 * 4 + wn] = q0;
        rsum[rl1 * 4 + wn] = s1; rsq[rl1 * 4 + wn] = q1;
    }
    __syncthreads();
    float sum0 = rsum[rl0 * 4] + rsum[rl0 * 4 + 1] + rsum[rl0 * 4 + 2] + rsum[rl0 * 4 + 3];
    float sq0  = rsq[rl0 * 4]  + rsq[rl0 * 4 + 1]  + rsq[rl0 * 4 + 2]  + rsq[rl0 * 4 + 3];
    float sum1 = rsum[rl1 * 4] + rsum[rl1 * 4 + 1] + rsum[rl1 * 4 + 2] + rsum[rl1 * 4 + 3];
    float sq1  = rsq[rl1 * 4]  + rsq[rl1 * 4 + 1]  + rsq[rl1 * 4 + 2]  + rsq[rl1 * 4 + 3];
    float mu0 = sum0 * (1.f / 384.f);
    float ir0 = rsqrtf(sq0 * (1.f / 384.f) - mu0 * mu0 + 1e-5f);
    float mu1 = sum1 * (1.f / 384.f);
    float ir1 = rsqrtf(sq1 * (1.f / 384.f) - mu1 * mu1 + 1e-5f);

    #pragma unroll
    for (int nt = 0; nt < 12; nt++) {
        int n = wn * 96 + nt * 8 + cg * 2;
        float2 w2 = *(const float2*)(gw + n);
        float2 g2 = *(const float2*)(gb + n);
        *(uint32_t*)(Y2 + r0 * 384 + n) =
            pack2((acc[nt][0] - mu0) * ir0 * w2.x + g2.x,
                  (acc[nt][1] - mu0) * ir0 * w2.y + g2.y);
        *(uint32_t*)(Y2 + r1 * 384 + n) =
            pack2((acc[nt][2] - mu1) * ir1 * w2.x + g2.x,
                  (acc[nt][3] - mu1) * ir1 * w2.y + g2.y);
    }
}

// ===========================================================================
// FP16 tensor-core GEMM, BM=128, BN=128, BK=64 (MODE 3): + bias + res(fp16),
// fp32 window-reverse scatter to NCHW out. (proven R15/R16 kernel)
// ===========================================================================
template<int K>
__global__ void __launch_bounds__(256, 2) mma_gemm_sc(
    const __half* __restrict__ A, const __half* __restrict__ W,
    const float* __restrict__ bias, const __half* __restrict__ res,
    float* __restrict__ out, int N)
{
    extern __shared__ uint32_t sm[];

    const int tid  = threadIdx.x;
    const int lane = tid & 31, wid = tid >> 5;
    const int wm = wid & 1;
    const int wn = wid >> 1;
    const int gr = lane >> 2;
    const int cg = lane & 3;

    const long m0 = (long)blockIdx.y * 128;
    const int  n0 = blockIdx.x * 128;

    const uint32_t sb = (uint32_t)__cvta_generic_to_shared(sm);
    const __half* Ag = A + m0 * K;
    const __half* Wg = W + (long)n0 * K;

    float acc[4][4][4];
    #pragma unroll
    for (int i = 0; i < 4; i++)
        #pragma unroll
        for (int j = 0; j < 4; j++)
            #pragma unroll
            for (int k = 0; k < 4; k++) acc[i][j][k] = 0.f;

    constexpr int NS = K >> 6;

    auto issue = [&](int s, int p) {
        #pragma unroll
        for (int i = 0; i < 4; i++) {
            int idx = tid + i * 256;
            int row = idx >> 3, c = idx & 7;
            uint32_t u = (uint32_t)(c ^ (row & 7));
            cp16(sb + p * 32768u + row * 128u + u * 16u,
                 Ag + (long)row * K + s * 64 + c * 8);
            cp16(sb + p * 32768u + 16384u + row * 128u + u * 16u,
                 Wg + (long)row * K + s * 64 + c * 8);
        }
        asm volatile("cp.async.commit_group;");
    };

    const int lrow = (lane & 7) + ((lane >> 3) & 1) * 8;
    const int lk   = lane >> 4;

    issue(0, 0);
    issue(1, 1);
    #pragma unroll
    for (int s = 0; s < NS; s++) {
        const int p = s - (s / 3) * 3;
        if (s + 1 < NS) asm volatile("cp.async.wait_group 1;");
        else            asm volatile("cp.async.wait_group 0;");
        __syncthreads();
        if (s + 2 < NS) {
            int s2 = s + 2;
            issue(s2, s2 - (s2 / 3) * 3);
        }

        const uint32_t abase = sb + p * 32768u;
        const uint32_t bbase = abase + 16384u;

        #pragma unroll
        for (int kc = 0; kc < 4; kc++) {
            int c = kc * 2 + lk;
            uint32_t af[4][4], bq[2][4];
            #pragma unroll
            for (int mt = 0; mt < 4; mt++) {
                int row = wm * 64 + mt * 16 + lrow;
                uint32_t u = (uint32_t)(c ^ (row & 7));
                ldsm4(af[mt], abase + row * 128u + u * 16u);
            }
            #pragma unroll
            for (int pr = 0; pr < 2; pr++) {
                int row = wn * 32 + pr * 16 + lrow;
                uint32_t u = (uint32_t)(c ^ (row & 7));
                ldsm4(bq[pr], bbase + row * 128u + u * 16u);
            }
            #pragma unroll
            for (int mt = 0; mt < 4; mt++)
                #pragma unroll
                for (int nt = 0; nt < 4; nt++) {
                    int pr = nt >> 1, hi = nt & 1;
                    mma16(acc[mt][nt], af[mt][0], af[mt][1], af[mt][2], af[mt][3],
                          bq[pr][hi], bq[pr][hi + 2]);
                }
        }
    }

    __syncthreads();
    float* T = (float*)sm;    // [128][66] floats
    #pragma unroll
    for (int chunk = 0; chunk < 2; chunk++) {
        if ((wn >> 1) == chunk) {
            #pragma unroll
            for (int mt = 0; mt < 4; mt++) {
                #pragma unroll
                for (int nt = 0; nt < 4; nt++) {
                    int cl = (wn & 1) * 32 + nt * 8 + cg * 2;
                    int n  = n0 + chunk * 64 + cl;
                    float2 b2 = *(const float2*)(bias + n);
                    #pragma unroll
                    for (int h = 0; h < 2; h++) {
                        int rl = wm * 64 + mt * 16 + h * 8 + gr;
                        long r = m0 + rl;
                        float2 rr = unpack2(*(const uint32_t*)(res + r * 384 + n));
                        T[rl * 66 + cl]     = acc[mt][nt][h * 2 + 0] + b2.x + rr.x;
                        T[rl * 66 + cl + 1] = acc[mt][nt][h * 2 + 1] + b2.y + rr.y;
                    }
                }
            }
        }
        __syncthreads();
        int ch = tid & 63;
        for (int g = tid >> 6; g < 16; g += 4) {
            long m = m0 + g * 8;
            int winI = (int)(m >> 6), sI = (int)(m & 63);
            int bI = winI >> 8, whI = (winI >> 4) & 15, wwI = winI & 15;
            int n = n0 + chunk * 64 + ch;
            long base = ((long)(bI * 384 + n)) * 16384
                      + (long)(whI * 8 + (sI >> 3)) * 128 + wwI * 8;
            float v[8];
            #pragma unroll
            for (int i = 0; i < 8; i++) v[i] = T[(g * 8 + i) * 66 + ch];
            *(float4*)(out + base)     = make_float4(v[0], v[1], v[2], v[3]);
            *(float4*)(out + base + 4) = make_float4(v[4], v[5], v[6], v[7]);
        }
        __syncthreads();
    }
}

// ===========================================================================
// Kernel 3: tensor-core attention; staging now via cp.async.
// ===========================================================================
__global__ void __launch_bounds__(256, 4) attn_kernel(
    const __half* __restrict__ QKV, __half* __restrict__ O)
{
    __shared__ __half qkv[64 * 296];
    const int STRB = 592;

    const int hp  = blockIdx.x;
    const int h0  = hp * 2;
    const long tok0 = (long)blockIdx.y * 64;
    const int tid = threadIdx.x;
    const int lane = tid & 31, wid = tid >> 5;
    const uint32_t sb = (uint32_t)__cvta_generic_to_shared(qkv);

    {
        const __half* g = QKV + tok0 * 1152 + h0 * 48;
        int row = tid / 36, seg = tid % 36;
        #pragma unroll
        for (int i = 0; i < 9; i++) {
            int part = (seg >= 24) ? 2 : ((seg >= 12) ? 1 : 0);
            int sub  = seg - part * 12;
            cp16(sb + (uint32_t)(row * STRB + seg * 16),
                 g + (long)row * 1152 + part * 384 + sub * 8);
            seg += 4; row += 7;
            if (seg >= 36) { seg -= 36; row += 1; }
        }
        asm volatile("cp.async.commit_group;");
        asm volatile("cp.async.wait_group 0;");
    }
    __syncthreads();

    const int hl = wid >> 2;
    const int m0 = (wid & 3) * 16;
    const int gr = lane >> 2, cg = lane & 3;

    const int qoffB = hl * 96;
    const int koffB = 192 + hl * 96;
    const int voffB = 384 + hl * 96;

    const int lrow = (lane & 7) + ((lane >> 3) & 1) * 8;
    const int lkA  = lane >> 4;
    const int krow = (lane & 7) + ((lane >> 4) & 1) * 8;
    const int kcolb= ((lane >> 3) & 1) * 16;
    const int vrow = (lane & 7) + ((lane >> 3) & 1) * 8;
    const int vsel = lane >> 4;

    float sacc[8][4];
    #pragma unroll
    for (int nt = 0; nt < 8; nt++)
        #pragma unroll
        for (int j = 0; j < 4; j++) sacc[nt][j] = 0.f;

    #pragma unroll
    for (int kc = 0; kc < 3; kc++) {
        uint32_t a[4];
        ldsm4(a, sb + (uint32_t)((m0 + lrow) * STRB + qoffB + kc * 32 + lkA * 16));
        #pragma unroll
        for (int j = 0; j < 4; j++) {
            uint32_t b[4];
            ldsm4(b, sb + (uint32_t)((j * 16 + krow) * STRB + koffB + kc * 32 + kcolb));
            mma16(sacc[2 * j],     a[0], a[1], a[2], a[3], b[0], b[1]);
            mma16(sacc[2 * j + 1], a[0], a[1], a[2], a[3], b[2], b[3]);
        }
    }

    const float scale = 0.14433756729740645f;
    float mx0 = -1e30f, mx1 = -1e30f;
    #pragma unroll
    for (int nt = 0; nt < 8; nt++) {
        mx0 = fmaxf(mx0, fmaxf(sacc[nt][0], sacc[nt][1]));
        mx1 = fmaxf(mx1, fmaxf(sacc[nt][2], sacc[nt][3]));
    }
    mx0 = fmaxf(mx0, __shfl_xor_sync(~0u, mx0, 1));
    mx0 = fmaxf(mx0, __shfl_xor_sync(~0u, mx0, 2));
    mx1 = fmaxf(mx1, __shfl_xor_sync(~0u, mx1, 1));
    mx1 = fmaxf(mx1, __shfl_xor_sync(~0u, mx1, 2));
    mx0 *= scale; mx1 *= scale;

    float e[8][4];
    float sum0 = 0.f, sum1 = 0.f;
    #pragma unroll
    for (int nt = 0; nt < 8; nt++) {
        e[nt][0] = __expf(sacc[nt][0] * scale - mx0);
        e[nt][1] = __expf(sacc[nt][1] * scale - mx0);
        e[nt][2] = __expf(sacc[nt][2] * scale - mx1);
        e[nt][3] = __expf(sacc[nt][3] * scale - mx1);
        sum0 += e[nt][0] + e[nt][1];
        sum1 += e[nt][2] + e[nt][3];
    }
    sum0 += __shfl_xor_sync(~0u, sum0, 1);
    sum0 += __shfl_xor_sync(~0u, sum0, 2);
    sum1 += __shfl_xor_sync(~0u, sum1, 1);
    sum1 += __shfl_xor_sync(~0u, sum1, 2);
    float inv0 = 1.f / sum0, inv1 = 1.f / sum1;

    uint32_t p0[8], p1[8];
    #pragma unroll
    for (int nt = 0; nt < 8; nt++) {
        p0[nt] = pack2(e[nt][0] * inv0, e[nt][1] * inv0);
        p1[nt] = pack2(e[nt][2] * inv1, e[nt][3] * inv1);
    }

    float oacc[6][4];
    #pragma unroll
    for (int nt = 0; nt < 6; nt++)
        #pragma unroll
        for (int j = 0; j < 4; j++) oacc[nt][j] = 0.f;

    #pragma unroll
    for (int kc = 0; kc < 4; kc++) {
        uint32_t a0 = p0[2 * kc],     a1 = p1[2 * kc];
        uint32_t a2 = p0[2 * kc + 1], a3 = p1[2 * kc + 1];
        #pragma unroll
        for (int j = 0; j < 3; j++) {
            uint32_t b[4];
            ldsm4t(b, sb + (uint32_t)((kc * 16 + vrow) * STRB
                                      + voffB + (2 * j + vsel) * 16));
            mma16(oacc[2 * j],     a0, a1, a2, a3, b[0], b[1]);
            mma16(oacc[2 * j + 1], a0, a1, a2, a3, b[2], b[3]);
        }
    }

    #pragma unroll
    for (int nt = 0; nt < 6; nt++) {
        long col = (h0 + hl) * 48 + nt * 8 + cg * 2;
        long r0 = tok0 + m0 + gr;
        *(uint32_t*)(O + r0 * 384 + col)       = pack2(oacc[nt][0], oacc[nt][1]);
        *(uint32_t*)(O + (r0 + 8) * 384 + col) = pack2(oacc[nt][2], oacc[nt][3]);
    }
}

// ===========================================================================
extern "C" void kernel_launch(void* const* d_in, const int* in_sizes, int n_in,
                              void* d_out, int out_size)
{
    const float* x     = (const float*)d_in[0];
    const float* n1_w  = (const float*)d_in[1];
    const float* n1_b  = (const float*)d_in[2];
    const float* in_w  = (const float*)d_in[3];
    const float* in_b  = (const float*)d_in[4];
    const float* out_w = (const float*)d_in[5];
    const float* out_b = (const float*)d_in[6];
    const float* n2_w  = (const float*)d_in[7];
    const float* n2_b  = (const float*)d_in[8];
    const float* w1    = (const float*)d_in[9];
    const float* b1    = (const float*)d_in[10];
    const float* w2    = (const float*)d_in[11];
    const float* b2    = (const float*)d_in[12];
    float* out = (float*)d_out;

    __half *WINh, *Yh, *Hb, *Wh;
    cudaGetSymbolAddress((void**)&WINh, g_hR);
    cudaGetSymbolAddress((void**)&Yh,   g_hA);
    cudaGetSymbolAddress((void**)&Hb,   g_hB);
    cudaGetSymbolAddress((void**)&Wh,   g_wh);

    __half* QKVh = Hb;
    __half* Oh   = Yh;
    __half* H    = WINh;
    __half* Y2h  = Hb;
    __half* Gh   = Hb + (size_t)TOKS * 384;

    cudaFuncSetAttribute((const void*)mma_gemm64<0,384>, cudaFuncAttributeMaxDynamicSharedMemorySize, GEMM_SMEM64);
    cudaFuncSetAttribute((const void*)mma_gemm64<1,384>, cudaFuncAttributeMaxDynamicSharedMemorySize, GEMM_SMEM64);
    cudaFuncSetAttribute((const void*)proj_ln_kernel,    cudaFuncAttributeMaxDynamicSharedMemorySize, PROJ_SMEM);
    cudaFuncSetAttribute((const void*)mma_gemm_sc<768>,  cudaFuncAttributeMaxDynamicSharedMemorySize, GEMM_SMEM_SC);

    // 0. convert all weights to fp16
    cvt_all_kernel<<<4608, 256>>>(in_w, out_w, w1, w2, Wh);
    // 1. gather + LN1 (vectorized)
    ln1_gather_kernel<<<2048 * 4, 256>>>(x, n1_w, n1_b, Yh, WINh);
    // 2. QKV projection (64x128, BK=64)
    mma_gemm64<0,384><<<dim3(1152 / 128, TOKS / 64), 256, GEMM_SMEM64>>>(Yh, Wh + WQKV_OFF, in_b, nullptr, QKVh, 1152);
    // 3. tensor-core attention (cp.async staging)
    attn_kernel<<<dim3(4, 2048), 256>>>(QKVh, Oh);
    // 4. fused: out projection + residual -> H, LayerNorm2 -> Y2
    proj_ln_kernel<<<TOKS / 32, 256, PROJ_SMEM>>>(Oh, Wh + WO_OFF, out_b, WINh, n2_w, n2_b, H, Y2h);
    // 5. MLP fc1 + fast gelu
    mma_gemm64<1,384><<<dim3(768 / 128, TOKS / 64), 256, GEMM_SMEM64>>>(Y2h, Wh + W1_OFF, b1, nullptr, Gh, 768);
    // 6. MLP fc2 + residual + window-reverse scatter (BK=64)
    mma_gemm_sc<768><<<dim3(384 / 128, TOKS / 128), 256, GEMM_SMEM_SC>>>(Gh, Wh + W2_OFF, b2, H, out, 384);
}